// round 8
// baseline (speedup 1.0000x reference)
#include <cuda_runtime.h>
#include <cuda_fp16.h>
#include <cstdint>
#include <math.h>

#define GG 8
#define MM 1024
#define NN 8192
#define HH 256
#define NHEADS 8
#define HDIM 32
#define FFND 1024
#define QKVD 768

// ---------------- scratch ----------------
__device__ float    g_dinv[NN];
__device__ float    g_xw  [NN * HH];
__device__ float    g_xl  [NN * HH];
__device__ uint32_t g_adj [GG * MM * 32];
__device__ unsigned char g_dist[(size_t)GG * MM * MM];
__device__ float    g_qkv [(size_t)NN * QKVD];
__device__ float    g_tmp [NN * HH];
__device__ float    g_h1  [NN * HH];
__device__ float    g_h2  [NN * HH];
__device__ float    g_y   [NN * HH];
__device__ int      g_cnt [NN];
__device__ int      g_base[NN];
__device__ int      g_fillp[NN];
__device__ int      g_esrc[262144];

#define AL16 __align__(16)
__device__ AL16 __half g_x_h [NN * HH];
__device__ AL16 __half g_at_h[NN * HH];
__device__ AL16 __half g_h1_h[NN * HH];
__device__ AL16 __half g_y_h [NN * HH];
__device__ AL16 __half g_mid_h[(size_t)NN * FFND];
__device__ AL16 __half g_q_h [NN * HH];
__device__ AL16 __half g_k_h [NN * HH], g_k_l [NN * HH];
__device__ AL16 __half g_vt_h[GG * NHEADS * HDIM * MM], g_vt_l[GG * NHEADS * HDIM * MM];
__device__ AL16 __half g_whi[1376256], g_wlo[1376256];
#define OFF_GCN   0
#define OFF_QKV   65536
#define OFF_PROJ  262144
#define OFF_FFN1  327680
#define OFF_FFN2  589824
#define OFF_OFFN1 851968
#define OFF_OFFN2 1114112

// ---------------- helpers ----------------
__device__ __forceinline__ uint32_t packh(float a, float b) {
    uint32_t r;
    asm("cvt.rn.f16x2.f32 %0, %1, %2;" : "=r"(r) : "f"(b), "f"(a));
    return r;
}
__device__ __forceinline__ float ex2f(float x) {
    float y; asm("ex2.approx.f32 %0, %1;" : "=f"(y) : "f"(x)); return y;
}
__device__ __forceinline__ void split2(float a, float b, uint32_t& hi, uint32_t& lo) {
    uint32_t h = packh(a, b);
    __half2 h2 = *reinterpret_cast<__half2*>(&h);
    float2 f2 = __half22float2(h2);
    hi = h;
    lo = packh(a - f2.x, b - f2.y);
}
#define CP16(dst, src) asm volatile("cp.async.cg.shared.global [%0], [%1], 16;\n" :: "r"(dst), "l"(src))
#define MMAH(d, a0, a1, a2, a3, b0, b1) \
    asm volatile("mma.sync.aligned.m16n8k16.row.col.f32.f16.f16.f32 " \
                 "{%0,%1,%2,%3}, {%4,%5,%6,%7}, {%8,%9}, {%0,%1,%2,%3};" \
                 : "+f"(d[0]), "+f"(d[1]), "+f"(d[2]), "+f"(d[3]) \
                 : "r"(a0), "r"(a1), "r"(a2), "r"(a3), "r"(b0), "r"(b1))
#define LDSM4(r0, r1, r2, r3, addr) \
    asm volatile("ldmatrix.sync.aligned.m8n8.x4.shared.b16 {%0,%1,%2,%3}, [%4];" \
                 : "=r"(r0), "=r"(r1), "=r"(r2), "=r"(r3) : "r"(addr))

// ---------------- splits ----------------
__global__ void splitx(const float4* __restrict__ in, __half* __restrict__ hi, int n4) {
    int i = blockIdx.x * blockDim.x + threadIdx.x;
    if (i >= n4) return;
    float4 v = in[i];
    *(uint2*)(hi + i * 4) = make_uint2(packh(v.x, v.y), packh(v.z, v.w));
}
__global__ void splitw(const float4* w0, const float4* w1, const float4* w2, const float4* w3,
                       const float4* w4, const float4* w5, const float4* w6,
                       __half* __restrict__ hi, __half* __restrict__ lo) {
    int i = blockIdx.x * blockDim.x + threadIdx.x;
    if (i >= 344064) return;
    const float4* src; int base;
    if      (i < 16384)  { src = w0; base = 0; }
    else if (i < 65536)  { src = w1; base = 16384; }
    else if (i < 81920)  { src = w2; base = 65536; }
    else if (i < 147456) { src = w3; base = 81920; }
    else if (i < 212992) { src = w4; base = 147456; }
    else if (i < 278528) { src = w5; base = 212992; }
    else                 { src = w6; base = 278528; }
    float4 v = src[i - base];
    uint32_t h0, l0, h1, l1;
    split2(v.x, v.y, h0, l0);
    split2(v.z, v.w, h1, l1);
    *(uint2*)(hi + (size_t)i * 4) = make_uint2(h0, h1);
    *(uint2*)(lo + (size_t)i * 4) = make_uint2(l0, l1);
}

// ---------------- graph prep ----------------
__global__ void zero_prep(int* __restrict__ cnt, uint32_t* __restrict__ adj) {
    int i = blockIdx.x * blockDim.x + threadIdx.x;
    if (i < GG * MM * 32) adj[i] = 0u;
    if (i < NN) cnt[i] = 0;
}
__global__ void edge_prep(const int* __restrict__ ei, int E, int* __restrict__ cnt,
                          uint32_t* __restrict__ adj) {
    int e = blockIdx.x * blockDim.x + threadIdx.x;
    if (e >= E) return;
    int s = ei[e], d = ei[E + e];
    atomicAdd(&cnt[d], 1);
    if (s == d || (s >> 10) != (d >> 10)) return;
    int g = s >> 10, ls = s & 1023, ld = d & 1023;
    atomicOr(&adj[((size_t)g * MM + ls) * 32 + (ld >> 5)], 1u << (ld & 31));
    atomicOr(&adj[((size_t)g * MM + ld) * 32 + (ls >> 5)], 1u << (ls & 31));
}
__global__ void scan_kernel(const int* __restrict__ cnt, int* __restrict__ base,
                            int* __restrict__ fillp, float* __restrict__ dinv) {
    __shared__ int wsum[32];
    int t = threadIdx.x;
    int v[8]; int s = 0;
#pragma unroll
    for (int k = 0; k < 8; ++k) { v[k] = s; s += cnt[t * 8 + k]; }
    int lane = t & 31, w = t >> 5;
    int tot = s, sc = s;
#pragma unroll
    for (int o = 1; o < 32; o <<= 1) {
        int n = __shfl_up_sync(0xFFFFFFFFu, sc, o);
        if (lane >= o) sc += n;
    }
    if (lane == 31) wsum[w] = sc;
    __syncthreads();
    if (w == 0) {
        int x = wsum[lane];
#pragma unroll
        for (int o = 1; o < 32; o <<= 1) {
            int n = __shfl_up_sync(0xFFFFFFFFu, x, o);
            if (lane >= o) x += n;
        }
        wsum[lane] = x;
    }
    __syncthreads();
    int excl = sc - tot + (w > 0 ? wsum[w - 1] : 0);
#pragma unroll
    for (int k = 0; k < 8; ++k) {
        int idx = t * 8 + k;
        int b = excl + v[k];
        base[idx] = b;
        fillp[idx] = b;
        dinv[idx] = rsqrtf((float)cnt[idx] + 1.0f);
    }
}
__global__ void fill_edges(const int* __restrict__ ei, int E, int* __restrict__ fillp,
                           int* __restrict__ esrc) {
    int e = blockIdx.x * blockDim.x + threadIdx.x;
    if (e >= E) return;
    int s = ei[e], d = ei[E + e];
    int pos = atomicAdd(&fillp[d], 1);
    esrc[pos] = s;
}
// GCN aggregation: gather per destination node, 4-way batched loads for MLP
__launch_bounds__(256)
__global__ void gcn_gather(const float* __restrict__ xw, const float* __restrict__ dinv,
                           const int* __restrict__ base, const int* __restrict__ cnt,
                           const int* __restrict__ esrc, const float* __restrict__ gcn_b,
                           float* __restrict__ xl) {
    int node = blockIdx.x * 4 + (threadIdx.x >> 6);
    int c4 = (threadIdx.x & 63) * 4;
    float dd = dinv[node];
    float4 v0 = *(const float4*)&xw[(size_t)node * HH + c4];
    float ax = dd * v0.x, ay = dd * v0.y, az = dd * v0.z, aw = dd * v0.w;
    int b0 = __ldg(&base[node]);
    int n  = __ldg(&cnt[node]);
    int k = 0;
    for (; k + 4 <= n; k += 4) {
        int s0 = __ldg(&esrc[b0 + k]);
        int s1 = __ldg(&esrc[b0 + k + 1]);
        int s2 = __ldg(&esrc[b0 + k + 2]);
        int s3 = __ldg(&esrc[b0 + k + 3]);
        float w0 = __ldg(&dinv[s0]), w1 = __ldg(&dinv[s1]);
        float w2 = __ldg(&dinv[s2]), w3 = __ldg(&dinv[s3]);
        float4 a = *(const float4*)&xw[(size_t)s0 * HH + c4];
        float4 b = *(const float4*)&xw[(size_t)s1 * HH + c4];
        float4 c = *(const float4*)&xw[(size_t)s2 * HH + c4];
        float4 d = *(const float4*)&xw[(size_t)s3 * HH + c4];
        ax += w0 * a.x + w1 * b.x + w2 * c.x + w3 * d.x;
        ay += w0 * a.y + w1 * b.y + w2 * c.y + w3 * d.y;
        az += w0 * a.z + w1 * b.z + w2 * c.z + w3 * d.z;
        aw += w0 * a.w + w1 * b.w + w2 * c.w + w3 * d.w;
    }
    for (; k < n; ++k) {
        int s = __ldg(&esrc[b0 + k]);
        float ws = __ldg(&dinv[s]);
        float4 v = *(const float4*)&xw[(size_t)s * HH + c4];
        ax += ws * v.x; ay += ws * v.y; az += ws * v.z; aw += ws * v.w;
    }
    float4 bia = *(const float4*)&gcn_b[c4];
    float4 o;
    o.x = dd * ax + bia.x; o.y = dd * ay + bia.y;
    o.z = dd * az + bia.z; o.w = dd * aw + bia.w;
    *(float4*)&xl[(size_t)node * HH + c4] = o;
}

// ---------------- SPD bitset BFS: 16 CTAs/graph x 64 threads ----------------
__launch_bounds__(64)
__global__ void spd_kernel(const uint32_t* __restrict__ adj, unsigned char* __restrict__ dist) {
    extern __shared__ uint32_t adj_sh[];   // [1024][33]
    int g = blockIdx.x >> 4;
    const uint32_t* ga = adj + (size_t)g * MM * 32;
    for (int idx = threadIdx.x; idx < MM * 32; idx += blockDim.x) {
        int r = idx >> 5, w = idx & 31;
        adj_sh[r * 33 + w] = ga[idx];
    }
    __syncthreads();

    int i = (blockIdx.x & 15) * 64 + threadIdx.x;
    unsigned char* drow = dist + ((size_t)g * MM + i) * MM;

    uint32_t reach[32], frontier[32];
#pragma unroll
    for (int w = 0; w < 32; ++w) {
        uint32_t a = adj_sh[i * 33 + w];
        reach[w] = a; frontier[w] = a;
    }
#pragma unroll
    for (int w = 0; w < 32; ++w) {
        uint32_t f = frontier[w];
        uint32_t* dp = (uint32_t*)(drow + w * 32);
#pragma unroll
        for (int q = 0; q < 8; ++q) {
            uint32_t nib = (f >> (q * 4)) & 0xF;
            uint32_t word = 0x06060606u;
            if (nib & 1) word = (word & 0xFFFFFF00u) | 0x01u;
            if (nib & 2) word = (word & 0xFFFF00FFu) | 0x0100u;
            if (nib & 4) word = (word & 0xFF00FFFFu) | 0x010000u;
            if (nib & 8) word = (word & 0x00FFFFFFu) | 0x01000000u;
            dp[q] = word;
        }
    }
    drow[i] = 0;
    reach[i >> 5] |= 1u << (i & 31);

    for (int d = 2; d <= 5; ++d) {
        uint32_t nw[32];
#pragma unroll
        for (int w = 0; w < 32; ++w) nw[w] = 0u;
        for (int w = 0; w < 32; ++w) {
            uint32_t f = frontier[w];
            while (f) {
                int b = __ffs((int)f) - 1;
                f &= f - 1;
                const uint32_t* aj = &adj_sh[(w * 32 + b) * 33];
#pragma unroll
                for (int ww = 0; ww < 32; ++ww) nw[ww] |= aj[ww];
            }
        }
        uint32_t any = 0;
        uint32_t rep = (uint32_t)d * 0x01010101u;
#pragma unroll
        for (int w = 0; w < 32; ++w) {
            uint32_t newly = nw[w] & ~reach[w];
            frontier[w] = newly;
            reach[w] |= newly;
            any |= newly;
            if (newly) {
                uint32_t* dp = (uint32_t*)(drow + w * 32);
#pragma unroll
                for (int q = 0; q < 8; ++q) {
                    uint32_t nib = (newly >> (q * 4)) & 0xF;
                    if (nib) {
                        uint32_t m = ((nib & 1) ? 0xFFu : 0u) | ((nib & 2) ? 0xFF00u : 0u)
                                   | ((nib & 4) ? 0xFF0000u : 0u) | ((nib & 8) ? 0xFF000000u : 0u);
                        dp[q] = (dp[q] & ~m) | (rep & m);
                    }
                }
            }
        }
        if (!any) break;
    }
}

// ---------------- fp16 GEMM 128x128 (ldmatrix) for wide-F layers ----------------
template <int GELU, int RES, int OUTF16>
__launch_bounds__(256, 2)
__global__ void gemm_f16(const __half* __restrict__ Ag, const __half* __restrict__ Whg,
                         const __half* __restrict__ Wlg,
                         const float* __restrict__ bias, const float* __restrict__ res,
                         float* __restrict__ C, __half* __restrict__ Ch, int K, int F) {
    extern __shared__ unsigned char smp[];
    const int STG = 30720;
    int m0 = blockIdx.x * 128, f0 = blockIdx.y * 128;
    int tid = threadIdx.x, lane = tid & 31, warp = tid >> 5;
    int g = lane >> 2, tg = lane & 3;
    int wm = (warp >> 2) * 64, wn = (warp & 3) * 32;
    uint32_t smem_base = (uint32_t)__cvta_generic_to_shared(smp);

    uint32_t aOff = (uint32_t)(wm + (lane & 15)) * 80 + (uint32_t)(lane >> 4) * 16;
    uint32_t bOff = (uint32_t)(wn + ((lane >> 4) << 3) + (lane & 7)) * 80
                  + (uint32_t)((lane >> 3) & 1) * 16;

    float acc[4][4][4];
#pragma unroll
    for (int a = 0; a < 4; ++a)
#pragma unroll
        for (int b = 0; b < 4; ++b)
#pragma unroll
            for (int c = 0; c < 4; ++c) acc[a][b][c] = 0.f;

    auto load_stage = [&](int s, int k0) {
        uint32_t db = smem_base + s * STG;
        const __half* srcs[3] = {
            Ag + (size_t)m0 * K + k0, Whg + (size_t)f0 * K + k0, Wlg + (size_t)f0 * K + k0 };
#pragma unroll
        for (int arr = 0; arr < 3; ++arr) {
            const __half* bp = srcs[arr];
            uint32_t ab = db + arr * 10240;
#pragma unroll
            for (int c = 0; c < 2; ++c) {
                int t = tid + c * 256;
                int row = t >> 2, ch = t & 3;
                CP16(ab + row * 80 + ch * 16, bp + (size_t)row * K + ch * 8);
            }
        }
        asm volatile("cp.async.commit_group;\n" ::);
    };

    int nk = K >> 5;
    load_stage(0, 0);
    for (int kc = 0; kc < nk; ++kc) {
        if (kc + 1 < nk) {
            load_stage((kc + 1) & 1, (kc + 1) << 5);
            asm volatile("cp.async.wait_group 1;\n" ::);
        } else {
            asm volatile("cp.async.wait_group 0;\n" ::);
        }
        __syncthreads();

        uint32_t stg = smem_base + (kc & 1) * STG;
        uint32_t aB  = stg + aOff;
        uint32_t whB = stg + 10240 + bOff;
        uint32_t wlB = stg + 20480 + bOff;
#pragma unroll
        for (int ks = 0; ks < 2; ++ks) {
            uint32_t bh[4][2], bl[4][2];
            LDSM4(bh[0][0], bh[0][1], bh[1][0], bh[1][1], whB + ks * 32);
            LDSM4(bh[2][0], bh[2][1], bh[3][0], bh[3][1], whB + 1280 + ks * 32);
            LDSM4(bl[0][0], bl[0][1], bl[1][0], bl[1][1], wlB + ks * 32);
            LDSM4(bl[2][0], bl[2][1], bl[3][0], bl[3][1], wlB + 1280 + ks * 32);
#pragma unroll
            for (int mt = 0; mt < 4; ++mt) {
                uint32_t a0, a1, a2, a3;
                LDSM4(a0, a1, a2, a3, aB + mt * 1280 + ks * 32);
#pragma unroll
                for (int nt = 0; nt < 4; ++nt) {
                    MMAH(acc[mt][nt], a0, a1, a2, a3, bh[nt][0], bh[nt][1]);
                    MMAH(acc[mt][nt], a0, a1, a2, a3, bl[nt][0], bl[nt][1]);
                }
            }
        }
        __syncthreads();
    }

#pragma unroll
    for (int mt = 0; mt < 4; ++mt) {
#pragma unroll
        for (int half = 0; half < 2; ++half) {
            int row = m0 + wm + mt * 16 + g + half * 8;
#pragma unroll
            for (int nt = 0; nt < 4; ++nt) {
                int col = f0 + wn + nt * 8 + tg * 2;
                float v0 = acc[mt][nt][half * 2 + 0];
                float v1 = acc[mt][nt][half * 2 + 1];
                if (bias) { v0 += bias[col]; v1 += bias[col + 1]; }
                if (GELU) { v0 = v0 * normcdff(v0); v1 = v1 * normcdff(v1); }
                if (RES)  { v0 += res[(size_t)row * F + col]; v1 += res[(size_t)row * F + col + 1]; }
                if (OUTF16) {
                    *(uint32_t*)(Ch + (size_t)row * F + col) = packh(v0, v1);
                } else {
                    float2 o; o.x = v0; o.y = v1;
                    *(float2*)(C + (size_t)row * F + col) = o;
                }
            }
        }
    }
}

// ---------------- fp16 GEMM 64x64 (ldmatrix, 4 warps, 4 CTAs/SM) for F=256 layers ----------------
template <int GELU, int RES, int OUTF16>
__launch_bounds__(128, 4)
__global__ void gemm_s(const __half* __restrict__ Ag, const __half* __restrict__ Whg,
                       const __half* __restrict__ Wlg,
                       const float* __restrict__ bias, const float* __restrict__ res,
                       float* __restrict__ C, __half* __restrict__ Ch, int K, int F) {
    extern __shared__ unsigned char smp[];
    const int STG = 15360;      // 3 arrays x 64 rows x 80B
    int m0 = blockIdx.x * 64, f0 = blockIdx.y * 64;
    int tid = threadIdx.x, lane = tid & 31, warp = tid >> 5;
    int g = lane >> 2, tg = lane & 3;
    int wm = (warp >> 1) * 32, wn = (warp & 1) * 32;
    uint32_t smem_base = (uint32_t)__cvta_generic_to_shared(smp);

    uint32_t aOff = (uint32_t)(wm + (lane & 15)) * 80 + (uint32_t)(lane >> 4) * 16;
    uint32_t bOff = (uint32_t)(wn + ((lane >> 4) << 3) + (lane & 7)) * 80
                  + (uint32_t)((lane >> 3) & 1) * 16;

    float acc[2][4][4];
#pragma unroll
    for (int a = 0; a < 2; ++a)
#pragma unroll
        for (int b = 0; b < 4; ++b)
#pragma unroll
            for (int c = 0; c < 4; ++c) acc[a][b][c] = 0.f;

    auto load_stage = [&](int s, int k0) {
        uint32_t db = smem_base + s * STG;
        const __half* srcs[3] = {
            Ag + (size_t)m0 * K + k0, Whg + (size_t)f0 * K + k0, Wlg + (size_t)f0 * K + k0 };
#pragma unroll
        for (int arr = 0; arr < 3; ++arr) {
            const __half* bp = srcs[arr];
            uint32_t ab = db + arr * 5120;
#pragma unroll
            for (int c = 0; c < 2; ++c) {
                int t = tid + c * 128;
                int row = t >> 2, ch = t & 3;
                CP16(ab + row * 80 + ch * 16, bp + (size_t)row * K + ch * 8);
            }
        }
        asm volatile("cp.async.commit_group;\n" ::);
    };

    int nk = K >> 5;
    load_stage(0, 0);
    for (int kc = 0; kc < nk; ++kc) {
        if (kc + 1 < nk) {
            load_stage((kc + 1) & 1, (kc + 1) << 5);
            asm volatile("cp.async.wait_group 1;\n" ::);
        } else {
            asm volatile("cp.async.wait_group 0;\n" ::);
        }
        __syncthreads();

        uint32_t stg = smem_base + (kc & 1) * STG;
        uint32_t aB  = stg + aOff;
        uint32_t whB = stg + 5120 + bOff;
        uint32_t wlB = stg + 10240 + bOff;
#pragma unroll
        for (int ks = 0; ks < 2; ++ks) {
            uint32_t bh[4][2], bl[4][2];
            LDSM4(bh[0][0], bh[0][1], bh[1][0], bh[1][1], whB + ks * 32);
            LDSM4(bh[2][0], bh[2][1], bh[3][0], bh[3][1], whB + 1280 + ks * 32);
            LDSM4(bl[0][0], bl[0][1], bl[1][0], bl[1][1], wlB + ks * 32);
            LDSM4(bl[2][0], bl[2][1], bl[3][0], bl[3][1], wlB + 1280 + ks * 32);
#pragma unroll
            for (int mt = 0; mt < 2; ++mt) {
                uint32_t a0, a1, a2, a3;
                LDSM4(a0, a1, a2, a3, aB + mt * 1280 + ks * 32);
#pragma unroll
                for (int nt = 0; nt < 4; ++nt) {
                    MMAH(acc[mt][nt], a0, a1, a2, a3, bh[nt][0], bh[nt][1]);
                    MMAH(acc[mt][nt], a0, a1, a2, a3, bl[nt][0], bl[nt][1]);
                }
            }
        }
        __syncthreads();
    }

#pragma unroll
    for (int mt = 0; mt < 2; ++mt) {
#pragma unroll
        for (int half = 0; half < 2; ++half) {
            int row = m0 + wm + mt * 16 + g + half * 8;
#pragma unroll
            for (int nt = 0; nt < 4; ++nt) {
                int col = f0 + wn + nt * 8 + tg * 2;
                float v0 = acc[mt][nt][half * 2 + 0];
                float v1 = acc[mt][nt][half * 2 + 1];
                if (bias) { v0 += bias[col]; v1 += bias[col + 1]; }
                if (GELU) { v0 = v0 * normcdff(v0); v1 = v1 * normcdff(v1); }
                if (RES)  { v0 += res[(size_t)row * F + col]; v1 += res[(size_t)row * F + col + 1]; }
                if (OUTF16) {
                    *(uint32_t*)(Ch + (size_t)row * F + col) = packh(v0, v1);
                } else {
                    float2 o; o.x = v0; o.y = v1;
                    *(float2*)(C + (size_t)row * F + col) = o;
                }
            }
        }
    }
}

// ---------------- qkv prepass ----------------
__launch_bounds__(256)
__global__ void qkv_prep(const float* __restrict__ qkv,
                         __half* __restrict__ qh,
                         __half* __restrict__ kh, __half* __restrict__ kl,
                         __half* __restrict__ vth, __half* __restrict__ vtl) {
    __shared__ float vsm[64][33];
    int nb = blockIdx.x * 64;
    int g = nb >> 10;
    int jb = nb & 1023;
    int tid = threadIdx.x;
    const float scale = 0.17677669529663687f;

#pragma unroll
    for (int it = 0; it < 32; ++it) {
        int flat = tid + it * 256;
        int row = flat >> 7, c4 = flat & 127;
        int node = nb + row;
        float4 v = *(const float4*)&qkv[(size_t)node * QKVD + c4 * 4];
        int c = c4 * 4;
        if (c < 256) {
            *(uint2*)(qh + (size_t)node * HH + c) =
                make_uint2(packh(v.x * scale, v.y * scale), packh(v.z * scale, v.w * scale));
        } else {
            uint32_t h0, l0, h1, l1;
            split2(v.x, v.y, h0, l0);
            split2(v.z, v.w, h1, l1);
            *(uint2*)(kh + (size_t)node * HH + c - 256) = make_uint2(h0, h1);
            *(uint2*)(kl + (size_t)node * HH + c - 256) = make_uint2(l0, l1);
        }
    }

    for (int h = 0; h < NHEADS; ++h) {
        __syncthreads();
#pragma unroll
        for (int it = 0; it < 2; ++it) {
            int flat = tid + it * 256;
            int row = flat >> 3, c4 = flat & 7;
            float4 v = *(const float4*)&qkv[(size_t)(nb + row) * QKVD + 512 + h * 32 + c4 * 4];
            vsm[row][c4 * 4 + 0] = v.x;
            vsm[row][c4 * 4 + 1] = v.y;
            vsm[row][c4 * 4 + 2] = v.z;
            vsm[row][c4 * 4 + 3] = v.w;
        }
        __syncthreads();
        int d = tid >> 3, j0 = (tid & 7) * 8;
        uint32_t hw[4], lw[4];
#pragma unroll
        for (int p = 0; p < 4; ++p) {
            float a = vsm[j0 + p * 2 + 0][d];
            float b = vsm[j0 + p * 2 + 1][d];
            split2(a, b, hw[p], lw[p]);
        }
        size_t off = ((size_t)(g * NHEADS + h) * HDIM + d) * MM + jb + j0;
        *(uint4*)(vth + off) = make_uint4(hw[0], hw[1], hw[2], hw[3]);
        *(uint4*)(vtl + off) = make_uint4(lw[0], lw[1], lw[2], lw[3]);
    }
}

// ---------------- flash attention (fp16 A-single / B-dual) ----------------
__launch_bounds__(256)
__global__ void attn_mma(const __half* __restrict__ qh,
                         const __half* __restrict__ kh, const __half* __restrict__ kl,
                         const __half* __restrict__ vth, const __half* __restrict__ vtl,
                         const unsigned char* __restrict__ dist, const float* __restrict__ bias_emb,
                         __half* __restrict__ oh) {
    extern __shared__ unsigned char smp[];
    const int STG = 37888;
    __shared__ float btab[8];
    int gh = blockIdx.x;
    int g = gh >> 3, h = gh & 7;
    int i0 = blockIdx.y * 128;
    int tid = threadIdx.x, lane = tid & 31, warp = tid >> 5;
    int r = lane >> 2, tg = lane & 3;
    if (tid < 7) btab[tid] = bias_emb[tid];
    uint32_t sb = (uint32_t)__cvta_generic_to_shared(smp);
    const float L2E = 1.44269504f;

    int rowA = i0 + warp * 16 + r;
    int rowB = rowA + 8;
    uint32_t qf[2][4];
#pragma unroll
    for (int kc = 0; kc < 2; ++kc) {
        size_t baseA = (size_t)(g * MM + rowA) * HH + h * HDIM + kc * 16 + tg * 2;
        size_t baseB = (size_t)(g * MM + rowB) * HH + h * HDIM + kc * 16 + tg * 2;
        qf[kc][0] = *(const uint32_t*)(qh + baseA);
        qf[kc][1] = *(const uint32_t*)(qh + baseB);
        qf[kc][2] = *(const uint32_t*)(qh + baseA + 8);
        qf[kc][3] = *(const uint32_t*)(qh + baseB + 8);
    }

    float acc_o[4][4];
#pragma unroll
    for (int a = 0; a < 4; ++a)
#pragma unroll
        for (int b = 0; b < 4; ++b) acc_o[a][b] = 0.f;
    float mA = -1e30f, mB = -1e30f, lA = 0.f, lB = 0.f;

    const unsigned char* drowA = dist + ((size_t)(g * MM + rowA)) * MM;
    const unsigned char* drowB = dist + ((size_t)(g * MM + rowB)) * MM;

    auto load_stage = [&](int s, int j0) {
        uint32_t db = sb + s * STG;
#pragma unroll
        for (int c = 0; c < 2; ++c) {
            int t = tid + c * 256;
            int row = t >> 2, ch = t & 3;
            const __half* src = kh + (size_t)(g * MM + j0 + row) * HH + h * HDIM + ch * 8;
            CP16(db + row * 80 + ch * 16, src);
            const __half* srcl = kl + (size_t)(g * MM + j0 + row) * HH + h * HDIM + ch * 8;
            CP16(db + 10240 + row * 80 + ch * 16, srcl);
        }
#pragma unroll
        for (int c = 0; c < 2; ++c) {
            int t = tid + c * 256;
            int row = t >> 4, ch = t & 15;
            size_t off = ((size_t)(gh) * HDIM + row) * MM + j0 + ch * 8;
            CP16(db + 20480 + row * 272 + ch * 16, vth + off);
            CP16(db + 29184 + row * 272 + ch * 16, vtl + off);
        }
        asm volatile("cp.async.commit_group;\n" ::);
    };

    load_stage(0, 0);
    for (int ch = 0; ch < 8; ++ch) {
        int j0 = ch * 128;
        if (ch < 7) {
            load_stage((ch + 1) & 1, j0 + 128);
            asm volatile("cp.async.wait_group 1;\n" ::);
        } else {
            asm volatile("cp.async.wait_group 0;\n" ::);
        }
        __syncthreads();

        const uint32_t* KH = (const uint32_t*)(smp + (ch & 1) * STG);
        const uint32_t* KL = KH + 2560;
        const uint32_t* VH = KH + 5120;
        const uint32_t* VL = VH + 2176;

        float acc_s[16][4];
#pragma unroll
        for (int nt = 0; nt < 16; ++nt)
#pragma unroll
            for (int c = 0; c < 4; ++c) acc_s[nt][c] = 0.f;
#pragma unroll
        for (int kc = 0; kc < 2; ++kc) {
#pragma unroll
            for (int nt = 0; nt < 16; ++nt) {
                int idx = (nt * 8 + r) * 20 + kc * 8 + tg;
                uint32_t b0h = KH[idx], b1h = KH[idx + 4];
                uint32_t b0l = KL[idx], b1l = KL[idx + 4];
                MMAH(acc_s[nt], qf[kc][0], qf[kc][1], qf[kc][2], qf[kc][3], b0h, b1h);
                MMAH(acc_s[nt], qf[kc][0], qf[kc][1], qf[kc][2], qf[kc][3], b0l, b1l);
            }
        }

        float cmA = -1e30f, cmB = -1e30f;
#pragma unroll
        for (int nt = 0; nt < 16; ++nt) {
            uchar2 dA = *(const uchar2*)(drowA + j0 + nt * 8 + tg * 2);
            uchar2 dB = *(const uchar2*)(drowB + j0 + nt * 8 + tg * 2);
            acc_s[nt][0] += btab[dA.x];
            acc_s[nt][1] += btab[dA.y];
            acc_s[nt][2] += btab[dB.x];
            acc_s[nt][3] += btab[dB.y];
            cmA = fmaxf(cmA, fmaxf(acc_s[nt][0], acc_s[nt][1]));
            cmB = fmaxf(cmB, fmaxf(acc_s[nt][2], acc_s[nt][3]));
        }
        cmA = fmaxf(cmA, __shfl_xor_sync(0xFFFFFFFFu, cmA, 1));
        cmA = fmaxf(cmA, __shfl_xor_sync(0xFFFFFFFFu, cmA, 2));
        cmB = fmaxf(cmB, __shfl_xor_sync(0xFFFFFFFFu, cmB, 1));
        cmB = fmaxf(cmB, __shfl_xor_sync(0xFFFFFFFFu, cmB, 2));

        float mAn = fmaxf(mA, cmA), mBn = fmaxf(mB, cmB);
        float corrA = ex2f((mA - mAn) * L2E);
        float corrB = ex2f((mB - mBn) * L2E);
        mA = mAn; mB = mBn;

        uint32_t ph0[16], ph1[16];
        float lsA = 0.f, lsB = 0.f;
#pragma unroll
        for (int nt = 0; nt < 16; ++nt) {
            float p0 = ex2f((acc_s[nt][0] - mA) * L2E);
            float p1 = ex2f((acc_s[nt][1] - mA) * L2E);
            float p2 = ex2f((acc_s[nt][2] - mB) * L2E);
            float p3 = ex2f((acc_s[nt][3] - mB) * L2E);
            lsA += p0 + p1; lsB += p2 + p3;
            ph0[nt] = packh(p0, p1);
            ph1[nt] = packh(p2, p3);
        }
        lsA += __shfl_xor_sync(0xFFFFFFFFu, lsA, 1);
        lsA += __shfl_xor_sync(0xFFFFFFFFu, lsA, 2);
        lsB += __shfl_xor_sync(0xFFFFFFFFu, lsB, 1);
        lsB += __shfl_xor_sync(0xFFFFFFFFu, lsB, 2);
        lA = lA * corrA + lsA;
        lB = lB * corrB + lsB;

#pragma unroll
        for (int nto = 0; nto < 4; ++nto) {
            acc_o[nto][0] *= corrA; acc_o[nto][1] *= corrA;
            acc_o[nto][2] *= corrB; acc_o[nto][3] *= corrB;
        }

#pragma unroll
        for (int kc = 0; kc < 8; ++kc) {
            uint32_t a0 = ph0[2 * kc], a1 = ph1[2 * kc], a2 = ph0[2 * kc + 1], a3 = ph1[2 * kc + 1];
#pragma unroll
            for (int nto = 0; nto < 4; ++nto) {
                int idx = (nto * 8 + r) * 68 + kc * 8 + tg;
                uint32_t b0h = VH[idx], b1h = VH[idx + 4];
                uint32_t b0l = VL[idx], b1l = VL[idx + 4];
                MMAH(acc_o[nto], a0, a1, a2, a3, b0h, b1h);
                MMAH(acc_o[nto], a0, a1, a2, a3, b0l, b1l);
            }
        }
        __syncthreads();
    }

    float invA = 1.f / lA, invB = 1.f / lB;
#pragma unroll
    for (int nto = 0; nto < 4; ++nto) {
        int col = h * HDIM + nto * 8 + tg * 2;
        *(uint32_t*)(oh + (size_t)(g * MM + rowA) * HH + col) =
            packh(acc_o[nto][0] * invA, acc_o[nto][1] * invA);
        *(uint32_t*)(oh + (size_t)(g * MM + rowB) * HH + col) =
            packh(acc_o[nto][2] * invB, acc_o[nto][3] * invB);
    }
}

// ---------------- LayerNorm ----------------
__launch_bounds__(256)
__global__ void ln_kernel(const float* __restrict__ a, const float* __restrict__ b,
                          const float* __restrict__ c, const float* __restrict__ gam,
                          const float* __restrict__ bet, float* __restrict__ out,
                          __half* __restrict__ oh) {
    int row = blockIdx.x, t = threadIdx.x;
    size_t idx = (size_t)row * HH + t;
    float v = a[idx];
    if (b) v += b[idx];
    if (c) v += c[idx];
    float s = v, s2 = v * v;
#pragma unroll
    for (int o = 16; o; o >>= 1) {
        s  += __shfl_xor_sync(0xFFFFFFFFu, s, o);
        s2 += __shfl_xor_sync(0xFFFFFFFFu, s2, o);
    }
    __shared__ float sh1[8], sh2[8];
    int w = t >> 5, ln = t & 31;
    if (ln == 0) { sh1[w] = s; sh2[w] = s2; }
    __syncthreads();
    if (w == 0) {
        s  = (ln < 8) ? sh1[ln] : 0.f;
        s2 = (ln < 8) ? sh2[ln] : 0.f;
#pragma unroll
        for (int o = 4; o; o >>= 1) {
            s  += __shfl_xor_sync(0xFFFFFFFFu, s, o);
            s2 += __shfl_xor_sync(0xFFFFFFFFu, s2, o);
        }
        if (ln == 0) { sh1[0] = s; sh2[0] = s2; }
    }
    __syncthreads();
    float mean = sh1[0] * (1.f / HH);
    float var  = sh2[0] * (1.f / HH) - mean * mean;
    float rr = (v - mean) * rsqrtf(var + 1e-5f) * gam[t] + bet[t];
    out[idx] = rr;
    if (oh) oh[idx] = __float2half(rr);
}

// ---------------- host ----------------
static void* sym(const void* s) { void* p = nullptr; cudaGetSymbolAddress(&p, s); return p; }

extern "C" void kernel_launch(void* const* d_in, const int* in_sizes, int n_in,
                              void* d_out, int out_size) {
    const float* x      = (const float*)d_in[0];
    const float* gcn_w  = (const float*)d_in[1];
    const float* gcn_b  = (const float*)d_in[2];
    const float* qkv_w  = (const float*)d_in[3];
    const float* qkv_b  = (const float*)d_in[4];
    const float* proj_w = (const float*)d_in[5];
    const float* proj_b = (const float*)d_in[6];
    const float* ln1_g  = (const float*)d_in[7];
    const float* ln1_b  = (const float*)d_in[8];
    const float* ln2_g  = (const float*)d_in[9];
    const float* ln2_b  = (const float*)d_in[10];
    const float* ffn1_w = (const float*)d_in[11];
    const float* ffn1_b = (const float*)d_in[12];
    const float* ffn2_w = (const float*)d_in[13];
    const float* ffn2_b = (const float*)d_in[14];
    const float* bias_e = (const float*)d_in[15];
    const float* oln1_g = (const float*)d_in[16];
    const float* oln1_b = (const float*)d_in[17];
    const float* oln2_g = (const float*)d_in[18];
    const float* oln2_b = (const float*)d_in[19];
    const float* offn1_w= (const float*)d_in[20];
    const float* offn1_b= (const float*)d_in[21];
    const float* offn2_w= (const float*)d_in[22];
    const float* offn2_b= (const float*)d_in[23];
    const int*   ei     = (const int*)d_in[24];
    int E = in_sizes[24] / 2;

    float*    p_dinv = (float*)sym(g_dinv);
    float*    p_xw   = (float*)sym(g_xw);
    float*    p_xl   = (float*)sym(g_xl);
    uint32_t* p_adj  = (uint32_t*)sym(g_adj);
    unsigned char* p_dist = (unsigned char*)sym(g_dist);
    float*    p_qkv  = (float*)sym(g_qkv);
    float*    p_tmp  = (float*)sym(g_tmp);
    float*    p_h1   = (float*)sym(g_h1);
    float*    p_h2   = (float*)sym(g_h2);
    float*    p_y    = (float*)sym(g_y);
    int*      p_cnt  = (int*)sym(g_cnt);
    int*      p_base = (int*)sym(g_base);
    int*      p_fill = (int*)sym(g_fillp);
    int*      p_esrc = (int*)sym(g_esrc);
    __half* x_h   = (__half*)sym(g_x_h);
    __half* at_h  = (__half*)sym(g_at_h);
    __half* h1_h  = (__half*)sym(g_h1_h);
    __half* y_h   = (__half*)sym(g_y_h);
    __half* mid_h = (__half*)sym(g_mid_h);
    __half* q_h   = (__half*)sym(g_q_h);
    __half* k_h   = (__half*)sym(g_k_h);
    __half* k_l   = (__half*)sym(g_k_l);
    __half* vt_h  = (__half*)sym(g_vt_h);
    __half* vt_l  = (__half*)sym(g_vt_l);
    __half* whi   = (__half*)sym(g_whi);
    __half* wlo   = (__half*)sym(g_wlo);
    float* out = (float*)d_out;

    const int SMEM  = 61440;
    const int SSMEM = 30720;
    const int ASMEM = 75776;
    cudaFuncSetAttribute(gemm_f16<0,0,0>, cudaFuncAttributeMaxDynamicSharedMemorySize, SMEM);
    cudaFuncSetAttribute(gemm_f16<1,0,1>, cudaFuncAttributeMaxDynamicSharedMemorySize, SMEM);
    cudaFuncSetAttribute(gemm_s<0,0,0>, cudaFuncAttributeMaxDynamicSharedMemorySize, SSMEM);
    cudaFuncSetAttribute(gemm_s<0,1,0>, cudaFuncAttributeMaxDynamicSharedMemorySize, SSMEM);
    cudaFuncSetAttribute(attn_mma, cudaFuncAttributeMaxDynamicSharedMemorySize, ASMEM);
    cudaFuncSetAttribute(spd_kernel, cudaFuncAttributeMaxDynamicSharedMemorySize, MM * 33 * 4);

    // launches 1-3 prep; launch 4 = spd_kernel (profiler slot)
    zero_prep<<<(GG * MM * 32 + 255) / 256, 256>>>(p_cnt, p_adj);
    splitw<<<(344064 + 255) / 256, 256>>>((const float4*)gcn_w, (const float4*)qkv_w,
        (const float4*)proj_w, (const float4*)ffn1_w, (const float4*)ffn2_w,
        (const float4*)offn1_w, (const float4*)offn2_w, whi, wlo);
    edge_prep<<<(E + 255) / 256, 256>>>(ei, E, p_cnt, p_adj);
    spd_kernel<<<GG * 16, 64, MM * 33 * 4>>>(p_adj, p_dist);

    // --- remaining prep ---
    splitx<<<(NN * HH / 4 + 255) / 256, 256>>>((const float4*)x, x_h, NN * HH / 4);
    scan_kernel<<<1, 1024>>>(p_cnt, p_base, p_fill, p_dinv);
    fill_edges<<<(E + 255) / 256, 256>>>(ei, E, p_fill, p_esrc);

    // --- GCN branch ---
    gemm_s<0,0,0><<<dim3(NN/64, HH/64), 128, SSMEM>>>(x_h, whi + OFF_GCN, wlo + OFF_GCN,
        nullptr, nullptr, p_xw, nullptr, HH, HH);
    gcn_gather<<<NN / 4, 256>>>(p_xw, p_dinv, p_base, p_cnt, p_esrc, gcn_b, p_xl);

    // --- Graphormer layer ---
    gemm_f16<0,0,0><<<dim3(NN/128, QKVD/128), 256, SMEM>>>(x_h, whi + OFF_QKV, wlo + OFF_QKV,
        qkv_b, nullptr, p_qkv, nullptr, HH, QKVD);
    qkv_prep<<<NN / 64, 256>>>(p_qkv, q_h, k_h, k_l, vt_h, vt_l);
    attn_mma<<<dim3(GG * NHEADS, MM / 128), 256, ASMEM>>>(q_h, k_h, k_l, vt_h, vt_l,
        p_dist, bias_e, at_h);
    gemm_s<0,1,0><<<dim3(NN/64, HH/64), 128, SSMEM>>>(at_h, whi + OFF_PROJ, wlo + OFF_PROJ,
        proj_b, x, p_tmp, nullptr, HH, HH);
    ln_kernel<<<NN, 256>>>(p_tmp, nullptr, nullptr, ln1_g, ln1_b, p_h1, h1_h);
    gemm_f16<1,0,1><<<dim3(NN/128, FFND/128), 256, SMEM>>>(h1_h, whi + OFF_FFN1, wlo + OFF_FFN1,
        ffn1_b, nullptr, nullptr, mid_h, HH, FFND);
    gemm_s<0,1,0><<<dim3(NN/64, HH/64), 128, SSMEM>>>(mid_h, whi + OFF_FFN2, wlo + OFF_FFN2,
        ffn2_b, p_h1, p_tmp, nullptr, FFND, HH);
    ln_kernel<<<NN, 256>>>(p_tmp, nullptr, nullptr, ln2_g, ln2_b, p_h2, nullptr);

    // --- GPS combine + outer FFN ---
    ln_kernel<<<NN, 256>>>(x, p_xl, p_h2, oln1_g, oln1_b, p_y, y_h);
    gemm_f16<1,0,1><<<dim3(NN/128, FFND/128), 256, SMEM>>>(y_h, whi + OFF_OFFN1, wlo + OFF_OFFN1,
        offn1_b, nullptr, nullptr, mid_h, HH, FFND);
    gemm_s<0,1,0><<<dim3(NN/64, HH/64), 128, SSMEM>>>(mid_h, whi + OFF_OFFN2, wlo + OFF_OFFN2,
        offn2_b, p_y, p_tmp, nullptr, FFND, HH);
    ln_kernel<<<NN, 256>>>(p_tmp, nullptr, nullptr, oln2_g, oln2_b, out, nullptr);
}

// round 9
// speedup vs baseline: 1.3169x; 1.3169x over previous
#include <cuda_runtime.h>
#include <cuda_fp16.h>
#include <cstdint>
#include <math.h>

#define GG 8
#define MM 1024
#define NN 8192
#define HH 256
#define NHEADS 8
#define HDIM 32
#define FFND 1024
#define QKVD 768

// ---------------- scratch ----------------
__device__ float    g_dinv[NN];
__device__ float    g_xw  [NN * HH];
__device__ float    g_xl  [NN * HH];
__device__ uint32_t g_adj [GG * MM * 32];
__device__ unsigned char g_dist[(size_t)GG * MM * MM];
__device__ float    g_qkv [(size_t)NN * QKVD];
__device__ float    g_tmp [NN * HH];
__device__ float    g_h1  [NN * HH];
__device__ float    g_h2  [NN * HH];
__device__ float    g_y   [NN * HH];
__device__ int      g_cnt [NN];
__device__ int      g_base[NN];
__device__ int      g_fillp[NN];
__device__ int      g_esrc[262144];

#define AL16 __align__(16)
__device__ AL16 __half g_x_h [NN * HH];
__device__ AL16 __half g_at_h[NN * HH];
__device__ AL16 __half g_h1_h[NN * HH];
__device__ AL16 __half g_y_h [NN * HH];
__device__ AL16 __half g_mid_h[(size_t)NN * FFND];
__device__ AL16 __half g_q_h [NN * HH];
__device__ AL16 __half g_k_h [NN * HH], g_k_l [NN * HH];
__device__ AL16 __half g_vt_h[GG * NHEADS * HDIM * MM], g_vt_l[GG * NHEADS * HDIM * MM];
__device__ AL16 __half g_whi[1376256], g_wlo[1376256];
#define OFF_GCN   0
#define OFF_QKV   65536
#define OFF_PROJ  262144
#define OFF_FFN1  327680
#define OFF_FFN2  589824
#define OFF_OFFN1 851968
#define OFF_OFFN2 1114112

// ---------------- helpers ----------------
__device__ __forceinline__ uint32_t packh(float a, float b) {
    uint32_t r;
    asm("cvt.rn.f16x2.f32 %0, %1, %2;" : "=r"(r) : "f"(b), "f"(a));
    return r;
}
__device__ __forceinline__ float ex2f(float x) {
    float y; asm("ex2.approx.f32 %0, %1;" : "=f"(y) : "f"(x)); return y;
}
__device__ __forceinline__ void split2(float a, float b, uint32_t& hi, uint32_t& lo) {
    uint32_t h = packh(a, b);
    __half2 h2 = *reinterpret_cast<__half2*>(&h);
    float2 f2 = __half22float2(h2);
    hi = h;
    lo = packh(a - f2.x, b - f2.y);
}
#define CP16(dst, src) asm volatile("cp.async.cg.shared.global [%0], [%1], 16;\n" :: "r"(dst), "l"(src))
#define MMAH(d, a0, a1, a2, a3, b0, b1) \
    asm volatile("mma.sync.aligned.m16n8k16.row.col.f32.f16.f16.f32 " \
                 "{%0,%1,%2,%3}, {%4,%5,%6,%7}, {%8,%9}, {%0,%1,%2,%3};" \
                 : "+f"(d[0]), "+f"(d[1]), "+f"(d[2]), "+f"(d[3]) \
                 : "r"(a0), "r"(a1), "r"(a2), "r"(a3), "r"(b0), "r"(b1))
#define LDSM4(r0, r1, r2, r3, addr) \
    asm volatile("ldmatrix.sync.aligned.m8n8.x4.shared.b16 {%0,%1,%2,%3}, [%4];" \
                 : "=r"(r0), "=r"(r1), "=r"(r2), "=r"(r3) : "r"(addr))

// ---------------- splits ----------------
__global__ void splitx(const float4* __restrict__ in, __half* __restrict__ hi, int n4) {
    int i = blockIdx.x * blockDim.x + threadIdx.x;
    if (i >= n4) return;
    float4 v = in[i];
    *(uint2*)(hi + i * 4) = make_uint2(packh(v.x, v.y), packh(v.z, v.w));
}
__global__ void splitw(const float4* w0, const float4* w1, const float4* w2, const float4* w3,
                       const float4* w4, const float4* w5, const float4* w6,
                       __half* __restrict__ hi, __half* __restrict__ lo) {
    int i = blockIdx.x * blockDim.x + threadIdx.x;
    if (i >= 344064) return;
    const float4* src; int base;
    if      (i < 16384)  { src = w0; base = 0; }
    else if (i < 65536)  { src = w1; base = 16384; }
    else if (i < 81920)  { src = w2; base = 65536; }
    else if (i < 147456) { src = w3; base = 81920; }
    else if (i < 212992) { src = w4; base = 147456; }
    else if (i < 278528) { src = w5; base = 212992; }
    else                 { src = w6; base = 278528; }
    float4 v = src[i - base];
    uint32_t h0, l0, h1, l1;
    split2(v.x, v.y, h0, l0);
    split2(v.z, v.w, h1, l1);
    *(uint2*)(hi + (size_t)i * 4) = make_uint2(h0, h1);
    *(uint2*)(lo + (size_t)i * 4) = make_uint2(l0, l1);
}

// ---------------- graph prep ----------------
__global__ void zero_prep(int* __restrict__ cnt, uint32_t* __restrict__ adj) {
    int i = blockIdx.x * blockDim.x + threadIdx.x;
    if (i < GG * MM * 32) adj[i] = 0u;
    if (i < NN) cnt[i] = 0;
}
__global__ void edge_prep(const int* __restrict__ ei, int E, int* __restrict__ cnt,
                          uint32_t* __restrict__ adj) {
    int e = blockIdx.x * blockDim.x + threadIdx.x;
    if (e >= E) return;
    int s = ei[e], d = ei[E + e];
    atomicAdd(&cnt[d], 1);
    if (s == d || (s >> 10) != (d >> 10)) return;
    int g = s >> 10, ls = s & 1023, ld = d & 1023;
    atomicOr(&adj[((size_t)g * MM + ls) * 32 + (ld >> 5)], 1u << (ld & 31));
    atomicOr(&adj[((size_t)g * MM + ld) * 32 + (ls >> 5)], 1u << (ls & 31));
}
__global__ void scan_kernel(const int* __restrict__ cnt, int* __restrict__ base,
                            int* __restrict__ fillp, float* __restrict__ dinv) {
    __shared__ int wsum[32];
    int t = threadIdx.x;
    int v[8]; int s = 0;
#pragma unroll
    for (int k = 0; k < 8; ++k) { v[k] = s; s += cnt[t * 8 + k]; }
    int lane = t & 31, w = t >> 5;
    int tot = s, sc = s;
#pragma unroll
    for (int o = 1; o < 32; o <<= 1) {
        int n = __shfl_up_sync(0xFFFFFFFFu, sc, o);
        if (lane >= o) sc += n;
    }
    if (lane == 31) wsum[w] = sc;
    __syncthreads();
    if (w == 0) {
        int x = wsum[lane];
#pragma unroll
        for (int o = 1; o < 32; o <<= 1) {
            int n = __shfl_up_sync(0xFFFFFFFFu, x, o);
            if (lane >= o) x += n;
        }
        wsum[lane] = x;
    }
    __syncthreads();
    int excl = sc - tot + (w > 0 ? wsum[w - 1] : 0);
#pragma unroll
    for (int k = 0; k < 8; ++k) {
        int idx = t * 8 + k;
        int b = excl + v[k];
        base[idx] = b;
        fillp[idx] = b;
        dinv[idx] = rsqrtf((float)cnt[idx] + 1.0f);
    }
}
__global__ void fill_edges(const int* __restrict__ ei, int E, int* __restrict__ fillp,
                           int* __restrict__ esrc) {
    int e = blockIdx.x * blockDim.x + threadIdx.x;
    if (e >= E) return;
    int s = ei[e], d = ei[E + e];
    int pos = atomicAdd(&fillp[d], 1);
    esrc[pos] = s;
}
// GCN aggregation: gather per destination node, 4-way batched loads
__launch_bounds__(256)
__global__ void gcn_gather(const float* __restrict__ xw, const float* __restrict__ dinv,
                           const int* __restrict__ base, const int* __restrict__ cnt,
                           const int* __restrict__ esrc, const float* __restrict__ gcn_b,
                           float* __restrict__ xl) {
    int node = blockIdx.x * 4 + (threadIdx.x >> 6);
    int c4 = (threadIdx.x & 63) * 4;
    float dd = dinv[node];
    float4 v0 = *(const float4*)&xw[(size_t)node * HH + c4];
    float ax = dd * v0.x, ay = dd * v0.y, az = dd * v0.z, aw = dd * v0.w;
    int b0 = __ldg(&base[node]);
    int n  = __ldg(&cnt[node]);
    int k = 0;
    for (; k + 4 <= n; k += 4) {
        int s0 = __ldg(&esrc[b0 + k]);
        int s1 = __ldg(&esrc[b0 + k + 1]);
        int s2 = __ldg(&esrc[b0 + k + 2]);
        int s3 = __ldg(&esrc[b0 + k + 3]);
        float w0 = __ldg(&dinv[s0]), w1 = __ldg(&dinv[s1]);
        float w2 = __ldg(&dinv[s2]), w3 = __ldg(&dinv[s3]);
        float4 a = *(const float4*)&xw[(size_t)s0 * HH + c4];
        float4 b = *(const float4*)&xw[(size_t)s1 * HH + c4];
        float4 c = *(const float4*)&xw[(size_t)s2 * HH + c4];
        float4 d = *(const float4*)&xw[(size_t)s3 * HH + c4];
        ax += w0 * a.x + w1 * b.x + w2 * c.x + w3 * d.x;
        ay += w0 * a.y + w1 * b.y + w2 * c.y + w3 * d.y;
        az += w0 * a.z + w1 * b.z + w2 * c.z + w3 * d.z;
        aw += w0 * a.w + w1 * b.w + w2 * c.w + w3 * d.w;
    }
    for (; k < n; ++k) {
        int s = __ldg(&esrc[b0 + k]);
        float ws = __ldg(&dinv[s]);
        float4 v = *(const float4*)&xw[(size_t)s * HH + c4];
        ax += ws * v.x; ay += ws * v.y; az += ws * v.z; aw += ws * v.w;
    }
    float4 bia = *(const float4*)&gcn_b[c4];
    float4 o;
    o.x = dd * ax + bia.x; o.y = dd * ay + bia.y;
    o.z = dd * az + bia.z; o.w = dd * aw + bia.w;
    *(float4*)&xl[(size_t)node * HH + c4] = o;
}

// ---------------- SPD bitset BFS: warp-per-source ----------------
// 128 CTAs (16/graph) x 512 threads (16 warps). Each warp does 4 sources.
// Lane t owns bitset word t; frontier enumeration is warp-uniform.
__launch_bounds__(512)
__global__ void spd_kernel(const uint32_t* __restrict__ adj, unsigned char* __restrict__ dist) {
    extern __shared__ uint32_t adj_sh[];   // [1024][33]
    int g = blockIdx.x >> 4;
    const uint32_t* ga = adj + (size_t)g * MM * 32;
    for (int idx = threadIdx.x; idx < MM * 32; idx += 512) {
        int r = idx >> 5, w = idx & 31;
        adj_sh[r * 33 + w] = ga[idx];
    }
    __syncthreads();

    int warp = threadIdx.x >> 5, lane = threadIdx.x & 31;
#pragma unroll
    for (int sub = 0; sub < 4; ++sub) {
        int i = (blockIdx.x & 15) * 64 + sub * 16 + warp;
        unsigned char* drow = dist + ((size_t)g * MM + i) * MM;

        uint32_t reach = adj_sh[i * 33 + lane];
        uint32_t frontier = reach;

        // write d=1 / default-6 for this lane's 32 bytes
        {
            uint32_t f = frontier;
            uint32_t* dp = (uint32_t*)(drow + lane * 32);
#pragma unroll
            for (int q = 0; q < 8; ++q) {
                uint32_t nib = (f >> (q * 4)) & 0xF;
                uint32_t word = 0x06060606u;
                if (nib & 1) word = (word & 0xFFFFFF00u) | 0x01u;
                if (nib & 2) word = (word & 0xFFFF00FFu) | 0x0100u;
                if (nib & 4) word = (word & 0xFF00FFFFu) | 0x010000u;
                if (nib & 8) word = (word & 0x00FFFFFFu) | 0x01000000u;
                dp[q] = word;
            }
        }
        if (lane == (i >> 5)) {
            drow[i] = 0;                    // diagonal (same lane wrote this word above)
            reach |= 1u << (i & 31);
        }

        for (int d = 2; d <= 5; ++d) {
            uint32_t nw = 0;
            for (int w = 0; w < 32; ++w) {
                uint32_t f = __shfl_sync(0xFFFFFFFFu, frontier, w);
                while (f) {
                    int b = __ffs((int)f) - 1;
                    f &= f - 1;
                    nw |= adj_sh[(w * 32 + b) * 33 + lane];
                }
            }
            uint32_t newly = nw & ~reach;
            frontier = newly;
            reach |= newly;
            uint32_t any = __ballot_sync(0xFFFFFFFFu, newly != 0u);
            if (newly) {
                uint32_t rep = (uint32_t)d * 0x01010101u;
                uint32_t* dp = (uint32_t*)(drow + lane * 32);
#pragma unroll
                for (int q = 0; q < 8; ++q) {
                    uint32_t nib = (newly >> (q * 4)) & 0xF;
                    if (nib) {
                        uint32_t m = ((nib & 1) ? 0xFFu : 0u) | ((nib & 2) ? 0xFF00u : 0u)
                                   | ((nib & 4) ? 0xFF0000u : 0u) | ((nib & 8) ? 0xFF000000u : 0u);
                        dp[q] = (dp[q] & ~m) | (rep & m);
                    }
                }
            }
            if (!any) break;
        }
    }
}

// ---------------- fp16 GEMM 128x128 (ldmatrix) ----------------
template <int GELU, int RES, int OUTF16>
__launch_bounds__(256, 2)
__global__ void gemm_f16(const __half* __restrict__ Ag, const __half* __restrict__ Whg,
                         const __half* __restrict__ Wlg,
                         const float* __restrict__ bias, const float* __restrict__ res,
                         float* __restrict__ C, __half* __restrict__ Ch, int K, int F) {
    extern __shared__ unsigned char smp[];
    const int STG = 30720;
    int m0 = blockIdx.x * 128, f0 = blockIdx.y * 128;
    int tid = threadIdx.x, lane = tid & 31, warp = tid >> 5;
    int g = lane >> 2, tg = lane & 3;
    int wm = (warp >> 2) * 64, wn = (warp & 3) * 32;
    uint32_t smem_base = (uint32_t)__cvta_generic_to_shared(smp);

    uint32_t aOff = (uint32_t)(wm + (lane & 15)) * 80 + (uint32_t)(lane >> 4) * 16;
    uint32_t bOff = (uint32_t)(wn + ((lane >> 4) << 3) + (lane & 7)) * 80
                  + (uint32_t)((lane >> 3) & 1) * 16;

    float acc[4][4][4];
#pragma unroll
    for (int a = 0; a < 4; ++a)
#pragma unroll
        for (int b = 0; b < 4; ++b)
#pragma unroll
            for (int c = 0; c < 4; ++c) acc[a][b][c] = 0.f;

    auto load_stage = [&](int s, int k0) {
        uint32_t db = smem_base + s * STG;
        const __half* srcs[3] = {
            Ag + (size_t)m0 * K + k0, Whg + (size_t)f0 * K + k0, Wlg + (size_t)f0 * K + k0 };
#pragma unroll
        for (int arr = 0; arr < 3; ++arr) {
            const __half* bp = srcs[arr];
            uint32_t ab = db + arr * 10240;
#pragma unroll
            for (int c = 0; c < 2; ++c) {
                int t = tid + c * 256;
                int row = t >> 2, ch = t & 3;
                CP16(ab + row * 80 + ch * 16, bp + (size_t)row * K + ch * 8);
            }
        }
        asm volatile("cp.async.commit_group;\n" ::);
    };

    int nk = K >> 5;
    load_stage(0, 0);
    for (int kc = 0; kc < nk; ++kc) {
        if (kc + 1 < nk) {
            load_stage((kc + 1) & 1, (kc + 1) << 5);
            asm volatile("cp.async.wait_group 1;\n" ::);
        } else {
            asm volatile("cp.async.wait_group 0;\n" ::);
        }
        __syncthreads();

        uint32_t stg = smem_base + (kc & 1) * STG;
        uint32_t aB  = stg + aOff;
        uint32_t whB = stg + 10240 + bOff;
        uint32_t wlB = stg + 20480 + bOff;
#pragma unroll
        for (int ks = 0; ks < 2; ++ks) {
            uint32_t bh[4][2], bl[4][2];
            LDSM4(bh[0][0], bh[0][1], bh[1][0], bh[1][1], whB + ks * 32);
            LDSM4(bh[2][0], bh[2][1], bh[3][0], bh[3][1], whB + 1280 + ks * 32);
            LDSM4(bl[0][0], bl[0][1], bl[1][0], bl[1][1], wlB + ks * 32);
            LDSM4(bl[2][0], bl[2][1], bl[3][0], bl[3][1], wlB + 1280 + ks * 32);
#pragma unroll
            for (int mt = 0; mt < 4; ++mt) {
                uint32_t a0, a1, a2, a3;
                LDSM4(a0, a1, a2, a3, aB + mt * 1280 + ks * 32);
#pragma unroll
                for (int nt = 0; nt < 4; ++nt) {
                    MMAH(acc[mt][nt], a0, a1, a2, a3, bh[nt][0], bh[nt][1]);
                    MMAH(acc[mt][nt], a0, a1, a2, a3, bl[nt][0], bl[nt][1]);
                }
            }
        }
        __syncthreads();
    }

#pragma unroll
    for (int mt = 0; mt < 4; ++mt) {
#pragma unroll
        for (int half = 0; half < 2; ++half) {
            int row = m0 + wm + mt * 16 + g + half * 8;
#pragma unroll
            for (int nt = 0; nt < 4; ++nt) {
                int col = f0 + wn + nt * 8 + tg * 2;
                float v0 = acc[mt][nt][half * 2 + 0];
                float v1 = acc[mt][nt][half * 2 + 1];
                if (bias) { v0 += bias[col]; v1 += bias[col + 1]; }
                if (GELU) { v0 = v0 * normcdff(v0); v1 = v1 * normcdff(v1); }
                if (RES)  { v0 += res[(size_t)row * F + col]; v1 += res[(size_t)row * F + col + 1]; }
                if (OUTF16) {
                    *(uint32_t*)(Ch + (size_t)row * F + col) = packh(v0, v1);
                } else {
                    float2 o; o.x = v0; o.y = v1;
                    *(float2*)(C + (size_t)row * F + col) = o;
                }
            }
        }
    }
}

// ---------------- qkv prepass ----------------
__launch_bounds__(256)
__global__ void qkv_prep(const float* __restrict__ qkv,
                         __half* __restrict__ qh,
                         __half* __restrict__ kh, __half* __restrict__ kl,
                         __half* __restrict__ vth, __half* __restrict__ vtl) {
    __shared__ float vsm[64][33];
    int nb = blockIdx.x * 64;
    int g = nb >> 10;
    int jb = nb & 1023;
    int tid = threadIdx.x;
    const float scale = 0.17677669529663687f;

#pragma unroll
    for (int it = 0; it < 32; ++it) {
        int flat = tid + it * 256;
        int row = flat >> 7, c4 = flat & 127;
        int node = nb + row;
        float4 v = *(const float4*)&qkv[(size_t)node * QKVD + c4 * 4];
        int c = c4 * 4;
        if (c < 256) {
            *(uint2*)(qh + (size_t)node * HH + c) =
                make_uint2(packh(v.x * scale, v.y * scale), packh(v.z * scale, v.w * scale));
        } else {
            uint32_t h0, l0, h1, l1;
            split2(v.x, v.y, h0, l0);
            split2(v.z, v.w, h1, l1);
            *(uint2*)(kh + (size_t)node * HH + c - 256) = make_uint2(h0, h1);
            *(uint2*)(kl + (size_t)node * HH + c - 256) = make_uint2(l0, l1);
        }
    }

    for (int h = 0; h < NHEADS; ++h) {
        __syncthreads();
#pragma unroll
        for (int it = 0; it < 2; ++it) {
            int flat = tid + it * 256;
            int row = flat >> 3, c4 = flat & 7;
            float4 v = *(const float4*)&qkv[(size_t)(nb + row) * QKVD + 512 + h * 32 + c4 * 4];
            vsm[row][c4 * 4 + 0] = v.x;
            vsm[row][c4 * 4 + 1] = v.y;
            vsm[row][c4 * 4 + 2] = v.z;
            vsm[row][c4 * 4 + 3] = v.w;
        }
        __syncthreads();
        int d = tid >> 3, j0 = (tid & 7) * 8;
        uint32_t hw[4], lw[4];
#pragma unroll
        for (int p = 0; p < 4; ++p) {
            float a = vsm[j0 + p * 2 + 0][d];
            float b = vsm[j0 + p * 2 + 1][d];
            split2(a, b, hw[p], lw[p]);
        }
        size_t off = ((size_t)(g * NHEADS + h) * HDIM + d) * MM + jb + j0;
        *(uint4*)(vth + off) = make_uint4(hw[0], hw[1], hw[2], hw[3]);
        *(uint4*)(vtl + off) = make_uint4(lw[0], lw[1], lw[2], lw[3]);
    }
}

// ---------------- flash attention (fp16 A-single / B-dual) ----------------
__launch_bounds__(256)
__global__ void attn_mma(const __half* __restrict__ qh,
                         const __half* __restrict__ kh, const __half* __restrict__ kl,
                         const __half* __restrict__ vth, const __half* __restrict__ vtl,
                         const unsigned char* __restrict__ dist, const float* __restrict__ bias_emb,
                         __half* __restrict__ oh) {
    extern __shared__ unsigned char smp[];
    const int STG = 37888;
    __shared__ float btab[8];
    int gh = blockIdx.x;
    int g = gh >> 3, h = gh & 7;
    int i0 = blockIdx.y * 128;
    int tid = threadIdx.x, lane = tid & 31, warp = tid >> 5;
    int r = lane >> 2, tg = lane & 3;
    if (tid < 7) btab[tid] = bias_emb[tid];
    uint32_t sb = (uint32_t)__cvta_generic_to_shared(smp);
    const float L2E = 1.44269504f;

    int rowA = i0 + warp * 16 + r;
    int rowB = rowA + 8;
    uint32_t qf[2][4];
#pragma unroll
    for (int kc = 0; kc < 2; ++kc) {
        size_t baseA = (size_t)(g * MM + rowA) * HH + h * HDIM + kc * 16 + tg * 2;
        size_t baseB = (size_t)(g * MM + rowB) * HH + h * HDIM + kc * 16 + tg * 2;
        qf[kc][0] = *(const uint32_t*)(qh + baseA);
        qf[kc][1] = *(const uint32_t*)(qh + baseB);
        qf[kc][2] = *(const uint32_t*)(qh + baseA + 8);
        qf[kc][3] = *(const uint32_t*)(qh + baseB + 8);
    }

    float acc_o[4][4];
#pragma unroll
    for (int a = 0; a < 4; ++a)
#pragma unroll
        for (int b = 0; b < 4; ++b) acc_o[a][b] = 0.f;
    float mA = -1e30f, mB = -1e30f, lA = 0.f, lB = 0.f;

    const unsigned char* drowA = dist + ((size_t)(g * MM + rowA)) * MM;
    const unsigned char* drowB = dist + ((size_t)(g * MM + rowB)) * MM;

    auto load_stage = [&](int s, int j0) {
        uint32_t db = sb + s * STG;
#pragma unroll
        for (int c = 0; c < 2; ++c) {
            int t = tid + c * 256;
            int row = t >> 2, ch = t & 3;
            const __half* src = kh + (size_t)(g * MM + j0 + row) * HH + h * HDIM + ch * 8;
            CP16(db + row * 80 + ch * 16, src);
            const __half* srcl = kl + (size_t)(g * MM + j0 + row) * HH + h * HDIM + ch * 8;
            CP16(db + 10240 + row * 80 + ch * 16, srcl);
        }
#pragma unroll
        for (int c = 0; c < 2; ++c) {
            int t = tid + c * 256;
            int row = t >> 4, ch = t & 15;
            size_t off = ((size_t)(gh) * HDIM + row) * MM + j0 + ch * 8;
            CP16(db + 20480 + row * 272 + ch * 16, vth + off);
            CP16(db + 29184 + row * 272 + ch * 16, vtl + off);
        }
        asm volatile("cp.async.commit_group;\n" ::);
    };

    load_stage(0, 0);
    for (int ch = 0; ch < 8; ++ch) {
        int j0 = ch * 128;
        if (ch < 7) {
            load_stage((ch + 1) & 1, j0 + 128);
            asm volatile("cp.async.wait_group 1;\n" ::);
        } else {
            asm volatile("cp.async.wait_group 0;\n" ::);
        }
        __syncthreads();

        const uint32_t* KH = (const uint32_t*)(smp + (ch & 1) * STG);
        const uint32_t* KL = KH + 2560;
        const uint32_t* VH = KH + 5120;
        const uint32_t* VL = VH + 2176;

        float acc_s[16][4];
#pragma unroll
        for (int nt = 0; nt < 16; ++nt)
#pragma unroll
            for (int c = 0; c < 4; ++c) acc_s[nt][c] = 0.f;
#pragma unroll
        for (int kc = 0; kc < 2; ++kc) {
#pragma unroll
            for (int nt = 0; nt < 16; ++nt) {
                int idx = (nt * 8 + r) * 20 + kc * 8 + tg;
                uint32_t b0h = KH[idx], b1h = KH[idx + 4];
                uint32_t b0l = KL[idx], b1l = KL[idx + 4];
                MMAH(acc_s[nt], qf[kc][0], qf[kc][1], qf[kc][2], qf[kc][3], b0h, b1h);
                MMAH(acc_s[nt], qf[kc][0], qf[kc][1], qf[kc][2], qf[kc][3], b0l, b1l);
            }
        }

        float cmA = -1e30f, cmB = -1e30f;
#pragma unroll
        for (int nt = 0; nt < 16; ++nt) {
            uchar2 dA = *(const uchar2*)(drowA + j0 + nt * 8 + tg * 2);
            uchar2 dB = *(const uchar2*)(drowB + j0 + nt * 8 + tg * 2);
            acc_s[nt][0] += btab[dA.x];
            acc_s[nt][1] += btab[dA.y];
            acc_s[nt][2] += btab[dB.x];
            acc_s[nt][3] += btab[dB.y];
            cmA = fmaxf(cmA, fmaxf(acc_s[nt][0], acc_s[nt][1]));
            cmB = fmaxf(cmB, fmaxf(acc_s[nt][2], acc_s[nt][3]));
        }
        cmA = fmaxf(cmA, __shfl_xor_sync(0xFFFFFFFFu, cmA, 1));
        cmA = fmaxf(cmA, __shfl_xor_sync(0xFFFFFFFFu, cmA, 2));
        cmB = fmaxf(cmB, __shfl_xor_sync(0xFFFFFFFFu, cmB, 1));
        cmB = fmaxf(cmB, __shfl_xor_sync(0xFFFFFFFFu, cmB, 2));

        float mAn = fmaxf(mA, cmA), mBn = fmaxf(mB, cmB);
        float corrA = ex2f((mA - mAn) * L2E);
        float corrB = ex2f((mB - mBn) * L2E);
        mA = mAn; mB = mBn;

        uint32_t ph0[16], ph1[16];
        float lsA = 0.f, lsB = 0.f;
#pragma unroll
        for (int nt = 0; nt < 16; ++nt) {
            float p0 = ex2f((acc_s[nt][0] - mA) * L2E);
            float p1 = ex2f((acc_s[nt][1] - mA) * L2E);
            float p2 = ex2f((acc_s[nt][2] - mB) * L2E);
            float p3 = ex2f((acc_s[nt][3] - mB) * L2E);
            lsA += p0 + p1; lsB += p2 + p3;
            ph0[nt] = packh(p0, p1);
            ph1[nt] = packh(p2, p3);
        }
        lsA += __shfl_xor_sync(0xFFFFFFFFu, lsA, 1);
        lsA += __shfl_xor_sync(0xFFFFFFFFu, lsA, 2);
        lsB += __shfl_xor_sync(0xFFFFFFFFu, lsB, 1);
        lsB += __shfl_xor_sync(0xFFFFFFFFu, lsB, 2);
        lA = lA * corrA + lsA;
        lB = lB * corrB + lsB;

#pragma unroll
        for (int nto = 0; nto < 4; ++nto) {
            acc_o[nto][0] *= corrA; acc_o[nto][1] *= corrA;
            acc_o[nto][2] *= corrB; acc_o[nto][3] *= corrB;
        }

#pragma unroll
        for (int kc = 0; kc < 8; ++kc) {
            uint32_t a0 = ph0[2 * kc], a1 = ph1[2 * kc], a2 = ph0[2 * kc + 1], a3 = ph1[2 * kc + 1];
#pragma unroll
            for (int nto = 0; nto < 4; ++nto) {
                int idx = (nto * 8 + r) * 68 + kc * 8 + tg;
                uint32_t b0h = VH[idx], b1h = VH[idx + 4];
                uint32_t b0l = VL[idx], b1l = VL[idx + 4];
                MMAH(acc_o[nto], a0, a1, a2, a3, b0h, b1h);
                MMAH(acc_o[nto], a0, a1, a2, a3, b0l, b1l);
            }
        }
        __syncthreads();
    }

    float invA = 1.f / lA, invB = 1.f / lB;
#pragma unroll
    for (int nto = 0; nto < 4; ++nto) {
        int col = h * HDIM + nto * 8 + tg * 2;
        *(uint32_t*)(oh + (size_t)(g * MM + rowA) * HH + col) =
            packh(acc_o[nto][0] * invA, acc_o[nto][1] * invA);
        *(uint32_t*)(oh + (size_t)(g * MM + rowB) * HH + col) =
            packh(acc_o[nto][2] * invB, acc_o[nto][3] * invB);
    }
}

// ---------------- LayerNorm ----------------
__launch_bounds__(256)
__global__ void ln_kernel(const float* __restrict__ a, const float* __restrict__ b,
                          const float* __restrict__ c, const float* __restrict__ gam,
                          const float* __restrict__ bet, float* __restrict__ out,
                          __half* __restrict__ oh) {
    int row = blockIdx.x, t = threadIdx.x;
    size_t idx = (size_t)row * HH + t;
    float v = a[idx];
    if (b) v += b[idx];
    if (c) v += c[idx];
    float s = v, s2 = v * v;
#pragma unroll
    for (int o = 16; o; o >>= 1) {
        s  += __shfl_xor_sync(0xFFFFFFFFu, s, o);
        s2 += __shfl_xor_sync(0xFFFFFFFFu, s2, o);
    }
    __shared__ float sh1[8], sh2[8];
    int w = t >> 5, ln = t & 31;
    if (ln == 0) { sh1[w] = s; sh2[w] = s2; }
    __syncthreads();
    if (w == 0) {
        s  = (ln < 8) ? sh1[ln] : 0.f;
        s2 = (ln < 8) ? sh2[ln] : 0.f;
#pragma unroll
        for (int o = 4; o; o >>= 1) {
            s  += __shfl_xor_sync(0xFFFFFFFFu, s, o);
            s2 += __shfl_xor_sync(0xFFFFFFFFu, s2, o);
        }
        if (ln == 0) { sh1[0] = s; sh2[0] = s2; }
    }
    __syncthreads();
    float mean = sh1[0] * (1.f / HH);
    float var  = sh2[0] * (1.f / HH) - mean * mean;
    float rr = (v - mean) * rsqrtf(var + 1e-5f) * gam[t] + bet[t];
    out[idx] = rr;
    if (oh) oh[idx] = __float2half(rr);
}

// ---------------- host ----------------
static void* sym(const void* s) { void* p = nullptr; cudaGetSymbolAddress(&p, s); return p; }

extern "C" void kernel_launch(void* const* d_in, const int* in_sizes, int n_in,
                              void* d_out, int out_size) {
    const float* x      = (const float*)d_in[0];
    const float* gcn_w  = (const float*)d_in[1];
    const float* gcn_b  = (const float*)d_in[2];
    const float* qkv_w  = (const float*)d_in[3];
    const float* qkv_b  = (const float*)d_in[4];
    const float* proj_w = (const float*)d_in[5];
    const float* proj_b = (const float*)d_in[6];
    const float* ln1_g  = (const float*)d_in[7];
    const float* ln1_b  = (const float*)d_in[8];
    const float* ln2_g  = (const float*)d_in[9];
    const float* ln2_b  = (const float*)d_in[10];
    const float* ffn1_w = (const float*)d_in[11];
    const float* ffn1_b = (const float*)d_in[12];
    const float* ffn2_w = (const float*)d_in[13];
    const float* ffn2_b = (const float*)d_in[14];
    const float* bias_e = (const float*)d_in[15];
    const float* oln1_g = (const float*)d_in[16];
    const float* oln1_b = (const float*)d_in[17];
    const float* oln2_g = (const float*)d_in[18];
    const float* oln2_b = (const float*)d_in[19];
    const float* offn1_w= (const float*)d_in[20];
    const float* offn1_b= (const float*)d_in[21];
    const float* offn2_w= (const float*)d_in[22];
    const float* offn2_b= (const float*)d_in[23];
    const int*   ei     = (const int*)d_in[24];
    int E = in_sizes[24] / 2;

    float*    p_dinv = (float*)sym(g_dinv);
    float*    p_xw   = (float*)sym(g_xw);
    float*    p_xl   = (float*)sym(g_xl);
    uint32_t* p_adj  = (uint32_t*)sym(g_adj);
    unsigned char* p_dist = (unsigned char*)sym(g_dist);
    float*    p_qkv  = (float*)sym(g_qkv);
    float*    p_tmp  = (float*)sym(g_tmp);
    float*    p_h1   = (float*)sym(g_h1);
    float*    p_h2   = (float*)sym(g_h2);
    float*    p_y    = (float*)sym(g_y);
    int*      p_cnt  = (int*)sym(g_cnt);
    int*      p_base = (int*)sym(g_base);
    int*      p_fill = (int*)sym(g_fillp);
    int*      p_esrc = (int*)sym(g_esrc);
    __half* x_h   = (__half*)sym(g_x_h);
    __half* at_h  = (__half*)sym(g_at_h);
    __half* h1_h  = (__half*)sym(g_h1_h);
    __half* y_h   = (__half*)sym(g_y_h);
    __half* mid_h = (__half*)sym(g_mid_h);
    __half* q_h   = (__half*)sym(g_q_h);
    __half* k_h   = (__half*)sym(g_k_h);
    __half* k_l   = (__half*)sym(g_k_l);
    __half* vt_h  = (__half*)sym(g_vt_h);
    __half* vt_l  = (__half*)sym(g_vt_l);
    __half* whi   = (__half*)sym(g_whi);
    __half* wlo   = (__half*)sym(g_wlo);
    float* out = (float*)d_out;

    const int SMEM  = 61440;
    const int ASMEM = 75776;
    cudaFuncSetAttribute(gemm_f16<0,0,0>, cudaFuncAttributeMaxDynamicSharedMemorySize, SMEM);
    cudaFuncSetAttribute(gemm_f16<0,1,0>, cudaFuncAttributeMaxDynamicSharedMemorySize, SMEM);
    cudaFuncSetAttribute(gemm_f16<1,0,1>, cudaFuncAttributeMaxDynamicSharedMemorySize, SMEM);
    cudaFuncSetAttribute(attn_mma, cudaFuncAttributeMaxDynamicSharedMemorySize, ASMEM);
    cudaFuncSetAttribute(spd_kernel, cudaFuncAttributeMaxDynamicSharedMemorySize, MM * 33 * 4);

    // launches 1-3 prep; launch 4 = spd_kernel (profiler slot)
    zero_prep<<<(GG * MM * 32 + 255) / 256, 256>>>(p_cnt, p_adj);
    splitw<<<(344064 + 255) / 256, 256>>>((const float4*)gcn_w, (const float4*)qkv_w,
        (const float4*)proj_w, (const float4*)ffn1_w, (const float4*)ffn2_w,
        (const float4*)offn1_w, (const float4*)offn2_w, whi, wlo);
    edge_prep<<<(E + 255) / 256, 256>>>(ei, E, p_cnt, p_adj);
    spd_kernel<<<GG * 16, 512, MM * 33 * 4>>>(p_adj, p_dist);

    // --- remaining prep ---
    splitx<<<(NN * HH / 4 + 255) / 256, 256>>>((const float4*)x, x_h, NN * HH / 4);
    scan_kernel<<<1, 1024>>>(p_cnt, p_base, p_fill, p_dinv);
    fill_edges<<<(E + 255) / 256, 256>>>(ei, E, p_fill, p_esrc);

    // --- GCN branch ---
    gemm_f16<0,0,0><<<dim3(NN/128, HH/128), 256, SMEM>>>(x_h, whi + OFF_GCN, wlo + OFF_GCN,
        nullptr, nullptr, p_xw, nullptr, HH, HH);
    gcn_gather<<<NN / 4, 256>>>(p_xw, p_dinv, p_base, p_cnt, p_esrc, gcn_b, p_xl);

    // --- Graphormer layer ---
    gemm_f16<0,0,0><<<dim3(NN/128, QKVD/128), 256, SMEM>>>(x_h, whi + OFF_QKV, wlo + OFF_QKV,
        qkv_b, nullptr, p_qkv, nullptr, HH, QKVD);
    qkv_prep<<<NN / 64, 256>>>(p_qkv, q_h, k_h, k_l, vt_h, vt_l);
    attn_mma<<<dim3(GG * NHEADS, MM / 128), 256, ASMEM>>>(q_h, k_h, k_l, vt_h, vt_l,
        p_dist, bias_e, at_h);
    gemm_f16<0,1,0><<<dim3(NN/128, HH/128), 256, SMEM>>>(at_h, whi + OFF_PROJ, wlo + OFF_PROJ,
        proj_b, x, p_tmp, nullptr, HH, HH);
    ln_kernel<<<NN, 256>>>(p_tmp, nullptr, nullptr, ln1_g, ln1_b, p_h1, h1_h);
    gemm_f16<1,0,1><<<dim3(NN/128, FFND/128), 256, SMEM>>>(h1_h, whi + OFF_FFN1, wlo + OFF_FFN1,
        ffn1_b, nullptr, nullptr, mid_h, HH, FFND);
    gemm_f16<0,1,0><<<dim3(NN/128, HH/128), 256, SMEM>>>(mid_h, whi + OFF_FFN2, wlo + OFF_FFN2,
        ffn2_b, p_h1, p_tmp, nullptr, FFND, HH);
    ln_kernel<<<NN, 256>>>(p_tmp, nullptr, nullptr, ln2_g, ln2_b, p_h2, nullptr);

    // --- GPS combine + outer FFN ---
    ln_kernel<<<NN, 256>>>(x, p_xl, p_h2, oln1_g, oln1_b, p_y, y_h);
    gemm_f16<1,0,1><<<dim3(NN/128, FFND/128), 256, SMEM>>>(y_h, whi + OFF_OFFN1, wlo + OFF_OFFN1,
        offn1_b, nullptr, nullptr, mid_h, HH, FFND);
    gemm_f16<0,1,0><<<dim3(NN/128, HH/128), 256, SMEM>>>(mid_h, whi + OFF_OFFN2, wlo + OFF_OFFN2,
        offn2_b, p_y, p_tmp, nullptr, FFND, HH);
    ln_kernel<<<NN, 256>>>(p_tmp, nullptr, nullptr, oln2_g, oln2_b, out, nullptr);
}

// round 10
// speedup vs baseline: 1.7266x; 1.3111x over previous
#include <cuda_runtime.h>
#include <cuda_fp16.h>
#include <cstdint>
#include <math.h>

#define GG 8
#define MM 1024
#define NN 8192
#define HH 256
#define NHEADS 8
#define HDIM 32
#define FFND 1024
#define QKVD 768

// ---------------- scratch ----------------
__device__ float    g_dinv[NN];
__device__ float    g_xw  [NN * HH];
__device__ float    g_xl  [NN * HH];
__device__ uint32_t g_adj [GG * MM * 32];
__device__ uint32_t g_R2  [GG * MM * 32];
__device__ uint32_t g_R3  [GG * MM * 32];
__device__ uint32_t g_R4  [GG * MM * 32];
__device__ uint32_t g_R5  [GG * MM * 32];
__device__ unsigned char g_dist[(size_t)GG * MM * MM];
__device__ float    g_qkv [(size_t)NN * QKVD];
__device__ float    g_tmp [NN * HH];
__device__ float    g_h1  [NN * HH];
__device__ float    g_h2  [NN * HH];
__device__ float    g_y   [NN * HH];
__device__ int      g_cnt [NN];
__device__ int      g_base[NN];
__device__ int      g_fillp[NN];
__device__ int      g_esrc[262144];

#define AL16 __align__(16)
__device__ AL16 __half g_x_h [NN * HH];
__device__ AL16 __half g_at_h[NN * HH];
__device__ AL16 __half g_h1_h[NN * HH];
__device__ AL16 __half g_y_h [NN * HH];
__device__ AL16 __half g_mid_h[(size_t)NN * FFND];
__device__ AL16 __half g_q_h [NN * HH];
__device__ AL16 __half g_k_h [NN * HH], g_k_l [NN * HH];
__device__ AL16 __half g_vt_h[GG * NHEADS * HDIM * MM], g_vt_l[GG * NHEADS * HDIM * MM];
__device__ AL16 __half g_whi[1376256], g_wlo[1376256];
#define OFF_GCN   0
#define OFF_QKV   65536
#define OFF_PROJ  262144
#define OFF_FFN1  327680
#define OFF_FFN2  589824
#define OFF_OFFN1 851968
#define OFF_OFFN2 1114112

// ---------------- helpers ----------------
__device__ __forceinline__ uint32_t packh(float a, float b) {
    uint32_t r;
    asm("cvt.rn.f16x2.f32 %0, %1, %2;" : "=r"(r) : "f"(b), "f"(a));
    return r;
}
__device__ __forceinline__ float ex2f(float x) {
    float y; asm("ex2.approx.f32 %0, %1;" : "=f"(y) : "f"(x)); return y;
}
__device__ __forceinline__ void split2(float a, float b, uint32_t& hi, uint32_t& lo) {
    uint32_t h = packh(a, b);
    __half2 h2 = *reinterpret_cast<__half2*>(&h);
    float2 f2 = __half22float2(h2);
    hi = h;
    lo = packh(a - f2.x, b - f2.y);
}
#define CP16(dst, src) asm volatile("cp.async.cg.shared.global [%0], [%1], 16;\n" :: "r"(dst), "l"(src))
#define MMAH(d, a0, a1, a2, a3, b0, b1) \
    asm volatile("mma.sync.aligned.m16n8k16.row.col.f32.f16.f16.f32 " \
                 "{%0,%1,%2,%3}, {%4,%5,%6,%7}, {%8,%9}, {%0,%1,%2,%3};" \
                 : "+f"(d[0]), "+f"(d[1]), "+f"(d[2]), "+f"(d[3]) \
                 : "r"(a0), "r"(a1), "r"(a2), "r"(a3), "r"(b0), "r"(b1))
#define LDSM4(r0, r1, r2, r3, addr) \
    asm volatile("ldmatrix.sync.aligned.m8n8.x4.shared.b16 {%0,%1,%2,%3}, [%4];" \
                 : "=r"(r0), "=r"(r1), "=r"(r2), "=r"(r3) : "r"(addr))

// ---------------- splits ----------------
__global__ void splitx(const float4* __restrict__ in, __half* __restrict__ hi, int n4) {
    int i = blockIdx.x * blockDim.x + threadIdx.x;
    if (i >= n4) return;
    float4 v = in[i];
    *(uint2*)(hi + i * 4) = make_uint2(packh(v.x, v.y), packh(v.z, v.w));
}
__global__ void splitw(const float4* w0, const float4* w1, const float4* w2, const float4* w3,
                       const float4* w4, const float4* w5, const float4* w6,
                       __half* __restrict__ hi, __half* __restrict__ lo) {
    int i = blockIdx.x * blockDim.x + threadIdx.x;
    if (i >= 344064) return;
    const float4* src; int base;
    if      (i < 16384)  { src = w0; base = 0; }
    else if (i < 65536)  { src = w1; base = 16384; }
    else if (i < 81920)  { src = w2; base = 65536; }
    else if (i < 147456) { src = w3; base = 81920; }
    else if (i < 212992) { src = w4; base = 147456; }
    else if (i < 278528) { src = w5; base = 212992; }
    else                 { src = w6; base = 278528; }
    float4 v = src[i - base];
    uint32_t h0, l0, h1, l1;
    split2(v.x, v.y, h0, l0);
    split2(v.z, v.w, h1, l1);
    *(uint2*)(hi + (size_t)i * 4) = make_uint2(h0, h1);
    *(uint2*)(lo + (size_t)i * 4) = make_uint2(l0, l1);
}

// ---------------- graph prep ----------------
__global__ void zero_prep(int* __restrict__ cnt, uint32_t* __restrict__ adj) {
    int i = blockIdx.x * blockDim.x + threadIdx.x;
    if (i < GG * MM * 32) adj[i] = 0u;
    if (i < NN) cnt[i] = 0;
}
__global__ void edge_prep(const int* __restrict__ ei, int E, int* __restrict__ cnt,
                          uint32_t* __restrict__ adj) {
    int e = blockIdx.x * blockDim.x + threadIdx.x;
    if (e >= E) return;
    int s = ei[e], d = ei[E + e];
    atomicAdd(&cnt[d], 1);
    if (s == d || (s >> 10) != (d >> 10)) return;
    int g = s >> 10, ls = s & 1023, ld = d & 1023;
    atomicOr(&adj[((size_t)g * MM + ls) * 32 + (ld >> 5)], 1u << (ld & 31));
    atomicOr(&adj[((size_t)g * MM + ld) * 32 + (ls >> 5)], 1u << (ls & 31));
}
__global__ void scan_kernel(const int* __restrict__ cnt, int* __restrict__ base,
                            int* __restrict__ fillp, float* __restrict__ dinv) {
    __shared__ int wsum[32];
    int t = threadIdx.x;
    int v[8]; int s = 0;
#pragma unroll
    for (int k = 0; k < 8; ++k) { v[k] = s; s += cnt[t * 8 + k]; }
    int lane = t & 31, w = t >> 5;
    int tot = s, sc = s;
#pragma unroll
    for (int o = 1; o < 32; o <<= 1) {
        int n = __shfl_up_sync(0xFFFFFFFFu, sc, o);
        if (lane >= o) sc += n;
    }
    if (lane == 31) wsum[w] = sc;
    __syncthreads();
    if (w == 0) {
        int x = wsum[lane];
#pragma unroll
        for (int o = 1; o < 32; o <<= 1) {
            int n = __shfl_up_sync(0xFFFFFFFFu, x, o);
            if (lane >= o) x += n;
        }
        wsum[lane] = x;
    }
    __syncthreads();
    int excl = sc - tot + (w > 0 ? wsum[w - 1] : 0);
#pragma unroll
    for (int k = 0; k < 8; ++k) {
        int idx = t * 8 + k;
        int b = excl + v[k];
        base[idx] = b;
        fillp[idx] = b;
        dinv[idx] = rsqrtf((float)cnt[idx] + 1.0f);
    }
}
__global__ void fill_edges(const int* __restrict__ ei, int E, int* __restrict__ fillp,
                           int* __restrict__ esrc) {
    int e = blockIdx.x * blockDim.x + threadIdx.x;
    if (e >= E) return;
    int s = ei[e], d = ei[E + e];
    int pos = atomicAdd(&fillp[d], 1);
    esrc[pos] = s;
}
// GCN aggregation: gather per destination node, 4-way batched loads
__launch_bounds__(256)
__global__ void gcn_gather(const float* __restrict__ xw, const float* __restrict__ dinv,
                           const int* __restrict__ base, const int* __restrict__ cnt,
                           const int* __restrict__ esrc, const float* __restrict__ gcn_b,
                           float* __restrict__ xl) {
    int node = blockIdx.x * 4 + (threadIdx.x >> 6);
    int c4 = (threadIdx.x & 63) * 4;
    float dd = dinv[node];
    float4 v0 = *(const float4*)&xw[(size_t)node * HH + c4];
    float ax = dd * v0.x, ay = dd * v0.y, az = dd * v0.z, aw = dd * v0.w;
    int b0 = __ldg(&base[node]);
    int n  = __ldg(&cnt[node]);
    int k = 0;
    for (; k + 4 <= n; k += 4) {
        int s0 = __ldg(&esrc[b0 + k]);
        int s1 = __ldg(&esrc[b0 + k + 1]);
        int s2 = __ldg(&esrc[b0 + k + 2]);
        int s3 = __ldg(&esrc[b0 + k + 3]);
        float w0 = __ldg(&dinv[s0]), w1 = __ldg(&dinv[s1]);
        float w2 = __ldg(&dinv[s2]), w3 = __ldg(&dinv[s3]);
        float4 a = *(const float4*)&xw[(size_t)s0 * HH + c4];
        float4 b = *(const float4*)&xw[(size_t)s1 * HH + c4];
        float4 c = *(const float4*)&xw[(size_t)s2 * HH + c4];
        float4 d = *(const float4*)&xw[(size_t)s3 * HH + c4];
        ax += w0 * a.x + w1 * b.x + w2 * c.x + w3 * d.x;
        ay += w0 * a.y + w1 * b.y + w2 * c.y + w3 * d.y;
        az += w0 * a.z + w1 * b.z + w2 * c.z + w3 * d.z;
        aw += w0 * a.w + w1 * b.w + w2 * c.w + w3 * d.w;
    }
    for (; k < n; ++k) {
        int s = __ldg(&esrc[b0 + k]);
        float ws = __ldg(&dinv[s]);
        float4 v = *(const float4*)&xw[(size_t)s * HH + c4];
        ax += ws * v.x; ay += ws * v.y; az += ws * v.z; aw += ws * v.w;
    }
    float4 bia = *(const float4*)&gcn_b[c4];
    float4 o;
    o.x = dd * ax + bia.x; o.y = dd * ay + bia.y;
    o.z = dd * az + bia.z; o.w = dd * aw + bia.w;
    *(float4*)&xl[(size_t)node * HH + c4] = o;
}

// ---------------- SPD: boolean matrix powers, warp-per-row ----------------
// R_d[i] = R_{d-1}[i] | OR_{j in nbr(i)} R_{d-1}[j].  Lane = bitset word.
__launch_bounds__(256)
__global__ void spd_round(const uint32_t* __restrict__ adj, const uint32_t* __restrict__ Rp,
                          uint32_t* __restrict__ Rn) {
    int gw = (blockIdx.x * 256 + threadIdx.x) >> 5;   // global row 0..8191
    int lane = threadIdx.x & 31;
    int g = gw >> 10, i = gw & 1023;
    const uint32_t* Rg = Rp + (size_t)g * MM * 32;
    uint32_t a = adj[((size_t)g * MM + i) * 32 + lane];
    uint32_t nw = Rg[i * 32 + lane];
    for (int w = 0; w < 32; ++w) {
        uint32_t f = __shfl_sync(0xFFFFFFFFu, a, w);
        while (f) {
            int b = __ffs((int)f) - 1;
            f &= f - 1;
            nw |= Rg[(w * 32 + b) * 32 + lane];
        }
    }
    Rn[((size_t)g * MM + i) * 32 + lane] = nw;
}
// dist byte = 6 - #{d : bit in R_d}  (R monotone); diag forced 0.
__device__ __forceinline__ uint32_t nibspread(uint32_t r, int q) {
    return (((r >> (q * 4)) & 0xFu) * 0x00204081u) & 0x01010101u;
}
__launch_bounds__(256)
__global__ void spd_final(const uint32_t* __restrict__ R1, const uint32_t* __restrict__ R2,
                          const uint32_t* __restrict__ R3, const uint32_t* __restrict__ R4,
                          const uint32_t* __restrict__ R5, unsigned char* __restrict__ dist) {
    int idx = blockIdx.x * 256 + threadIdx.x;   // 0..262143 = row*32 + w
    int row = idx >> 5, w = idx & 31;
    uint32_t r1 = R1[idx], r2 = R2[idx], r3 = R3[idx], r4 = R4[idx], r5 = R5[idx];
    unsigned char* drow = dist + (size_t)row * MM;
    uint4* dp = (uint4*)(drow + w * 32);
    uint32_t o[8];
#pragma unroll
    for (int q = 0; q < 8; ++q) {
        uint32_t s = nibspread(r1, q) + nibspread(r2, q) + nibspread(r3, q)
                   + nibspread(r4, q) + nibspread(r5, q);
        o[q] = 0x06060606u - s;
    }
    dp[0] = make_uint4(o[0], o[1], o[2], o[3]);
    dp[1] = make_uint4(o[4], o[5], o[6], o[7]);
    int i = row & 1023;
    if ((i >> 5) == w) drow[i] = 0;   // diagonal
}

// ---------------- fp16 GEMM 128x128 (ldmatrix) ----------------
template <int GELU, int RES, int OUTF16>
__launch_bounds__(256, 2)
__global__ void gemm_f16(const __half* __restrict__ Ag, const __half* __restrict__ Whg,
                         const __half* __restrict__ Wlg,
                         const float* __restrict__ bias, const float* __restrict__ res,
                         float* __restrict__ C, __half* __restrict__ Ch, int K, int F) {
    extern __shared__ unsigned char smp[];
    const int STG = 30720;
    int m0 = blockIdx.x * 128, f0 = blockIdx.y * 128;
    int tid = threadIdx.x, lane = tid & 31, warp = tid >> 5;
    int g = lane >> 2, tg = lane & 3;
    int wm = (warp >> 2) * 64, wn = (warp & 3) * 32;
    uint32_t smem_base = (uint32_t)__cvta_generic_to_shared(smp);

    uint32_t aOff = (uint32_t)(wm + (lane & 15)) * 80 + (uint32_t)(lane >> 4) * 16;
    uint32_t bOff = (uint32_t)(wn + ((lane >> 4) << 3) + (lane & 7)) * 80
                  + (uint32_t)((lane >> 3) & 1) * 16;

    float acc[4][4][4];
#pragma unroll
    for (int a = 0; a < 4; ++a)
#pragma unroll
        for (int b = 0; b < 4; ++b)
#pragma unroll
            for (int c = 0; c < 4; ++c) acc[a][b][c] = 0.f;

    auto load_stage = [&](int s, int k0) {
        uint32_t db = smem_base + s * STG;
        const __half* srcs[3] = {
            Ag + (size_t)m0 * K + k0, Whg + (size_t)f0 * K + k0, Wlg + (size_t)f0 * K + k0 };
#pragma unroll
        for (int arr = 0; arr < 3; ++arr) {
            const __half* bp = srcs[arr];
            uint32_t ab = db + arr * 10240;
#pragma unroll
            for (int c = 0; c < 2; ++c) {
                int t = tid + c * 256;
                int row = t >> 2, ch = t & 3;
                CP16(ab + row * 80 + ch * 16, bp + (size_t)row * K + ch * 8);
            }
        }
        asm volatile("cp.async.commit_group;\n" ::);
    };

    int nk = K >> 5;
    load_stage(0, 0);
    for (int kc = 0; kc < nk; ++kc) {
        if (kc + 1 < nk) {
            load_stage((kc + 1) & 1, (kc + 1) << 5);
            asm volatile("cp.async.wait_group 1;\n" ::);
        } else {
            asm volatile("cp.async.wait_group 0;\n" ::);
        }
        __syncthreads();

        uint32_t stg = smem_base + (kc & 1) * STG;
        uint32_t aB  = stg + aOff;
        uint32_t whB = stg + 10240 + bOff;
        uint32_t wlB = stg + 20480 + bOff;
#pragma unroll
        for (int ks = 0; ks < 2; ++ks) {
            uint32_t bh[4][2], bl[4][2];
            LDSM4(bh[0][0], bh[0][1], bh[1][0], bh[1][1], whB + ks * 32);
            LDSM4(bh[2][0], bh[2][1], bh[3][0], bh[3][1], whB + 1280 + ks * 32);
            LDSM4(bl[0][0], bl[0][1], bl[1][0], bl[1][1], wlB + ks * 32);
            LDSM4(bl[2][0], bl[2][1], bl[3][0], bl[3][1], wlB + 1280 + ks * 32);
#pragma unroll
            for (int mt = 0; mt < 4; ++mt) {
                uint32_t a0, a1, a2, a3;
                LDSM4(a0, a1, a2, a3, aB + mt * 1280 + ks * 32);
#pragma unroll
                for (int nt = 0; nt < 4; ++nt) {
                    MMAH(acc[mt][nt], a0, a1, a2, a3, bh[nt][0], bh[nt][1]);
                    MMAH(acc[mt][nt], a0, a1, a2, a3, bl[nt][0], bl[nt][1]);
                }
            }
        }
        __syncthreads();
    }

#pragma unroll
    for (int mt = 0; mt < 4; ++mt) {
#pragma unroll
        for (int half = 0; half < 2; ++half) {
            int row = m0 + wm + mt * 16 + g + half * 8;
#pragma unroll
            for (int nt = 0; nt < 4; ++nt) {
                int col = f0 + wn + nt * 8 + tg * 2;
                float v0 = acc[mt][nt][half * 2 + 0];
                float v1 = acc[mt][nt][half * 2 + 1];
                if (bias) { v0 += bias[col]; v1 += bias[col + 1]; }
                if (GELU) { v0 = v0 * normcdff(v0); v1 = v1 * normcdff(v1); }
                if (RES)  { v0 += res[(size_t)row * F + col]; v1 += res[(size_t)row * F + col + 1]; }
                if (OUTF16) {
                    *(uint32_t*)(Ch + (size_t)row * F + col) = packh(v0, v1);
                } else {
                    float2 o; o.x = v0; o.y = v1;
                    *(float2*)(C + (size_t)row * F + col) = o;
                }
            }
        }
    }
}

// ---------------- qkv prepass ----------------
__launch_bounds__(256)
__global__ void qkv_prep(const float* __restrict__ qkv,
                         __half* __restrict__ qh,
                         __half* __restrict__ kh, __half* __restrict__ kl,
                         __half* __restrict__ vth, __half* __restrict__ vtl) {
    __shared__ float vsm[64][33];
    int nb = blockIdx.x * 64;
    int g = nb >> 10;
    int jb = nb & 1023;
    int tid = threadIdx.x;
    const float scale = 0.17677669529663687f;

#pragma unroll
    for (int it = 0; it < 32; ++it) {
        int flat = tid + it * 256;
        int row = flat >> 7, c4 = flat & 127;
        int node = nb + row;
        float4 v = *(const float4*)&qkv[(size_t)node * QKVD + c4 * 4];
        int c = c4 * 4;
        if (c < 256) {
            *(uint2*)(qh + (size_t)node * HH + c) =
                make_uint2(packh(v.x * scale, v.y * scale), packh(v.z * scale, v.w * scale));
        } else {
            uint32_t h0, l0, h1, l1;
            split2(v.x, v.y, h0, l0);
            split2(v.z, v.w, h1, l1);
            *(uint2*)(kh + (size_t)node * HH + c - 256) = make_uint2(h0, h1);
            *(uint2*)(kl + (size_t)node * HH + c - 256) = make_uint2(l0, l1);
        }
    }

    for (int h = 0; h < NHEADS; ++h) {
        __syncthreads();
#pragma unroll
        for (int it = 0; it < 2; ++it) {
            int flat = tid + it * 256;
            int row = flat >> 3, c4 = flat & 7;
            float4 v = *(const float4*)&qkv[(size_t)(nb + row) * QKVD + 512 + h * 32 + c4 * 4];
            vsm[row][c4 * 4 + 0] = v.x;
            vsm[row][c4 * 4 + 1] = v.y;
            vsm[row][c4 * 4 + 2] = v.z;
            vsm[row][c4 * 4 + 3] = v.w;
        }
        __syncthreads();
        int d = tid >> 3, j0 = (tid & 7) * 8;
        uint32_t hw[4], lw[4];
#pragma unroll
        for (int p = 0; p < 4; ++p) {
            float a = vsm[j0 + p * 2 + 0][d];
            float b = vsm[j0 + p * 2 + 1][d];
            split2(a, b, hw[p], lw[p]);
        }
        size_t off = ((size_t)(g * NHEADS + h) * HDIM + d) * MM + jb + j0;
        *(uint4*)(vth + off) = make_uint4(hw[0], hw[1], hw[2], hw[3]);
        *(uint4*)(vtl + off) = make_uint4(lw[0], lw[1], lw[2], lw[3]);
    }
}

// ---------------- flash attention (fp16 A-single / B-dual) ----------------
__launch_bounds__(256)
__global__ void attn_mma(const __half* __restrict__ qh,
                         const __half* __restrict__ kh, const __half* __restrict__ kl,
                         const __half* __restrict__ vth, const __half* __restrict__ vtl,
                         const unsigned char* __restrict__ dist, const float* __restrict__ bias_emb,
                         __half* __restrict__ oh) {
    extern __shared__ unsigned char smp[];
    const int STG = 37888;
    __shared__ float btab[8];
    int gh = blockIdx.x;
    int g = gh >> 3, h = gh & 7;
    int i0 = blockIdx.y * 128;
    int tid = threadIdx.x, lane = tid & 31, warp = tid >> 5;
    int r = lane >> 2, tg = lane & 3;
    if (tid < 7) btab[tid] = bias_emb[tid];
    uint32_t sb = (uint32_t)__cvta_generic_to_shared(smp);
    const float L2E = 1.44269504f;

    int rowA = i0 + warp * 16 + r;
    int rowB = rowA + 8;
    uint32_t qf[2][4];
#pragma unroll
    for (int kc = 0; kc < 2; ++kc) {
        size_t baseA = (size_t)(g * MM + rowA) * HH + h * HDIM + kc * 16 + tg * 2;
        size_t baseB = (size_t)(g * MM + rowB) * HH + h * HDIM + kc * 16 + tg * 2;
        qf[kc][0] = *(const uint32_t*)(qh + baseA);
        qf[kc][1] = *(const uint32_t*)(qh + baseB);
        qf[kc][2] = *(const uint32_t*)(qh + baseA + 8);
        qf[kc][3] = *(const uint32_t*)(qh + baseB + 8);
    }

    float acc_o[4][4];
#pragma unroll
    for (int a = 0; a < 4; ++a)
#pragma unroll
        for (int b = 0; b < 4; ++b) acc_o[a][b] = 0.f;
    float mA = -1e30f, mB = -1e30f, lA = 0.f, lB = 0.f;

    const unsigned char* drowA = dist + ((size_t)(g * MM + rowA)) * MM;
    const unsigned char* drowB = dist + ((size_t)(g * MM + rowB)) * MM;

    auto load_stage = [&](int s, int j0) {
        uint32_t db = sb + s * STG;
#pragma unroll
        for (int c = 0; c < 2; ++c) {
            int t = tid + c * 256;
            int row = t >> 2, ch = t & 3;
            const __half* src = kh + (size_t)(g * MM + j0 + row) * HH + h * HDIM + ch * 8;
            CP16(db + row * 80 + ch * 16, src);
            const __half* srcl = kl + (size_t)(g * MM + j0 + row) * HH + h * HDIM + ch * 8;
            CP16(db + 10240 + row * 80 + ch * 16, srcl);
        }
#pragma unroll
        for (int c = 0; c < 2; ++c) {
            int t = tid + c * 256;
            int row = t >> 4, ch = t & 15;
            size_t off = ((size_t)(gh) * HDIM + row) * MM + j0 + ch * 8;
            CP16(db + 20480 + row * 272 + ch * 16, vth + off);
            CP16(db + 29184 + row * 272 + ch * 16, vtl + off);
        }
        asm volatile("cp.async.commit_group;\n" ::);
    };

    load_stage(0, 0);
    for (int ch = 0; ch < 8; ++ch) {
        int j0 = ch * 128;
        if (ch < 7) {
            load_stage((ch + 1) & 1, j0 + 128);
            asm volatile("cp.async.wait_group 1;\n" ::);
        } else {
            asm volatile("cp.async.wait_group 0;\n" ::);
        }
        __syncthreads();

        const uint32_t* KH = (const uint32_t*)(smp + (ch & 1) * STG);
        const uint32_t* KL = KH + 2560;
        const uint32_t* VH = KH + 5120;
        const uint32_t* VL = VH + 2176;

        float acc_s[16][4];
#pragma unroll
        for (int nt = 0; nt < 16; ++nt)
#pragma unroll
            for (int c = 0; c < 4; ++c) acc_s[nt][c] = 0.f;
#pragma unroll
        for (int kc = 0; kc < 2; ++kc) {
#pragma unroll
            for (int nt = 0; nt < 16; ++nt) {
                int idx = (nt * 8 + r) * 20 + kc * 8 + tg;
                uint32_t b0h = KH[idx], b1h = KH[idx + 4];
                uint32_t b0l = KL[idx], b1l = KL[idx + 4];
                MMAH(acc_s[nt], qf[kc][0], qf[kc][1], qf[kc][2], qf[kc][3], b0h, b1h);
                MMAH(acc_s[nt], qf[kc][0], qf[kc][1], qf[kc][2], qf[kc][3], b0l, b1l);
            }
        }

        float cmA = -1e30f, cmB = -1e30f;
#pragma unroll
        for (int nt = 0; nt < 16; ++nt) {
            uchar2 dA = *(const uchar2*)(drowA + j0 + nt * 8 + tg * 2);
            uchar2 dB = *(const uchar2*)(drowB + j0 + nt * 8 + tg * 2);
            acc_s[nt][0] += btab[dA.x];
            acc_s[nt][1] += btab[dA.y];
            acc_s[nt][2] += btab[dB.x];
            acc_s[nt][3] += btab[dB.y];
            cmA = fmaxf(cmA, fmaxf(acc_s[nt][0], acc_s[nt][1]));
            cmB = fmaxf(cmB, fmaxf(acc_s[nt][2], acc_s[nt][3]));
        }
        cmA = fmaxf(cmA, __shfl_xor_sync(0xFFFFFFFFu, cmA, 1));
        cmA = fmaxf(cmA, __shfl_xor_sync(0xFFFFFFFFu, cmA, 2));
        cmB = fmaxf(cmB, __shfl_xor_sync(0xFFFFFFFFu, cmB, 1));
        cmB = fmaxf(cmB, __shfl_xor_sync(0xFFFFFFFFu, cmB, 2));

        float mAn = fmaxf(mA, cmA), mBn = fmaxf(mB, cmB);
        float corrA = ex2f((mA - mAn) * L2E);
        float corrB = ex2f((mB - mBn) * L2E);
        mA = mAn; mB = mBn;

        uint32_t ph0[16], ph1[16];
        float lsA = 0.f, lsB = 0.f;
#pragma unroll
        for (int nt = 0; nt < 16; ++nt) {
            float p0 = ex2f((acc_s[nt][0] - mA) * L2E);
            float p1 = ex2f((acc_s[nt][1] - mA) * L2E);
            float p2 = ex2f((acc_s[nt][2] - mB) * L2E);
            float p3 = ex2f((acc_s[nt][3] - mB) * L2E);
            lsA += p0 + p1; lsB += p2 + p3;
            ph0[nt] = packh(p0, p1);
            ph1[nt] = packh(p2, p3);
        }
        lsA += __shfl_xor_sync(0xFFFFFFFFu, lsA, 1);
        lsA += __shfl_xor_sync(0xFFFFFFFFu, lsA, 2);
        lsB += __shfl_xor_sync(0xFFFFFFFFu, lsB, 1);
        lsB += __shfl_xor_sync(0xFFFFFFFFu, lsB, 2);
        lA = lA * corrA + lsA;
        lB = lB * corrB + lsB;

#pragma unroll
        for (int nto = 0; nto < 4; ++nto) {
            acc_o[nto][0] *= corrA; acc_o[nto][1] *= corrA;
            acc_o[nto][2] *= corrB; acc_o[nto][3] *= corrB;
        }

#pragma unroll
        for (int kc = 0; kc < 8; ++kc) {
            uint32_t a0 = ph0[2 * kc], a1 = ph1[2 * kc], a2 = ph0[2 * kc + 1], a3 = ph1[2 * kc + 1];
#pragma unroll
            for (int nto = 0; nto < 4; ++nto) {
                int idx = (nto * 8 + r) * 68 + kc * 8 + tg;
                uint32_t b0h = VH[idx], b1h = VH[idx + 4];
                uint32_t b0l = VL[idx], b1l = VL[idx + 4];
                MMAH(acc_o[nto], a0, a1, a2, a3, b0h, b1h);
                MMAH(acc_o[nto], a0, a1, a2, a3, b0l, b1l);
            }
        }
        __syncthreads();
    }

    float invA = 1.f / lA, invB = 1.f / lB;
#pragma unroll
    for (int nto = 0; nto < 4; ++nto) {
        int col = h * HDIM + nto * 8 + tg * 2;
        *(uint32_t*)(oh + (size_t)(g * MM + rowA) * HH + col) =
            packh(acc_o[nto][0] * invA, acc_o[nto][1] * invA);
        *(uint32_t*)(oh + (size_t)(g * MM + rowB) * HH + col) =
            packh(acc_o[nto][2] * invB, acc_o[nto][3] * invB);
    }
}

// ---------------- LayerNorm ----------------
__launch_bounds__(256)
__global__ void ln_kernel(const float* __restrict__ a, const float* __restrict__ b,
                          const float* __restrict__ c, const float* __restrict__ gam,
                          const float* __restrict__ bet, float* __restrict__ out,
                          __half* __restrict__ oh) {
    int row = blockIdx.x, t = threadIdx.x;
    size_t idx = (size_t)row * HH + t;
    float v = a[idx];
    if (b) v += b[idx];
    if (c) v += c[idx];
    float s = v, s2 = v * v;
#pragma unroll
    for (int o = 16; o; o >>= 1) {
        s  += __shfl_xor_sync(0xFFFFFFFFu, s, o);
        s2 += __shfl_xor_sync(0xFFFFFFFFu, s2, o);
    }
    __shared__ float sh1[8], sh2[8];
    int w = t >> 5, ln = t & 31;
    if (ln == 0) { sh1[w] = s; sh2[w] = s2; }
    __syncthreads();
    if (w == 0) {
        s  = (ln < 8) ? sh1[ln] : 0.f;
        s2 = (ln < 8) ? sh2[ln] : 0.f;
#pragma unroll
        for (int o = 4; o; o >>= 1) {
            s  += __shfl_xor_sync(0xFFFFFFFFu, s, o);
            s2 += __shfl_xor_sync(0xFFFFFFFFu, s2, o);
        }
        if (ln == 0) { sh1[0] = s; sh2[0] = s2; }
    }
    __syncthreads();
    float mean = sh1[0] * (1.f / HH);
    float var  = sh2[0] * (1.f / HH) - mean * mean;
    float rr = (v - mean) * rsqrtf(var + 1e-5f) * gam[t] + bet[t];
    out[idx] = rr;
    if (oh) oh[idx] = __float2half(rr);
}

// ---------------- host ----------------
static void* sym(const void* s) { void* p = nullptr; cudaGetSymbolAddress(&p, s); return p; }

extern "C" void kernel_launch(void* const* d_in, const int* in_sizes, int n_in,
                              void* d_out, int out_size) {
    const float* x      = (const float*)d_in[0];
    const float* gcn_w  = (const float*)d_in[1];
    const float* gcn_b  = (const float*)d_in[2];
    const float* qkv_w  = (const float*)d_in[3];
    const float* qkv_b  = (const float*)d_in[4];
    const float* proj_w = (const float*)d_in[5];
    const float* proj_b = (const float*)d_in[6];
    const float* ln1_g  = (const float*)d_in[7];
    const float* ln1_b  = (const float*)d_in[8];
    const float* ln2_g  = (const float*)d_in[9];
    const float* ln2_b  = (const float*)d_in[10];
    const float* ffn1_w = (const float*)d_in[11];
    const float* ffn1_b = (const float*)d_in[12];
    const float* ffn2_w = (const float*)d_in[13];
    const float* ffn2_b = (const float*)d_in[14];
    const float* bias_e = (const float*)d_in[15];
    const float* oln1_g = (const float*)d_in[16];
    const float* oln1_b = (const float*)d_in[17];
    const float* oln2_g = (const float*)d_in[18];
    const float* oln2_b = (const float*)d_in[19];
    const float* offn1_w= (const float*)d_in[20];
    const float* offn1_b= (const float*)d_in[21];
    const float* offn2_w= (const float*)d_in[22];
    const float* offn2_b= (const float*)d_in[23];
    const int*   ei     = (const int*)d_in[24];
    int E = in_sizes[24] / 2;

    float*    p_dinv = (float*)sym(g_dinv);
    float*    p_xw   = (float*)sym(g_xw);
    float*    p_xl   = (float*)sym(g_xl);
    uint32_t* p_adj  = (uint32_t*)sym(g_adj);
    uint32_t* p_R2   = (uint32_t*)sym(g_R2);
    uint32_t* p_R3   = (uint32_t*)sym(g_R3);
    uint32_t* p_R4   = (uint32_t*)sym(g_R4);
    uint32_t* p_R5   = (uint32_t*)sym(g_R5);
    unsigned char* p_dist = (unsigned char*)sym(g_dist);
    float*    p_qkv  = (float*)sym(g_qkv);
    float*    p_tmp  = (float*)sym(g_tmp);
    float*    p_h1   = (float*)sym(g_h1);
    float*    p_h2   = (float*)sym(g_h2);
    float*    p_y    = (float*)sym(g_y);
    int*      p_cnt  = (int*)sym(g_cnt);
    int*      p_base = (int*)sym(g_base);
    int*      p_fill = (int*)sym(g_fillp);
    int*      p_esrc = (int*)sym(g_esrc);
    __half* x_h   = (__half*)sym(g_x_h);
    __half* at_h  = (__half*)sym(g_at_h);
    __half* h1_h  = (__half*)sym(g_h1_h);
    __half* y_h   = (__half*)sym(g_y_h);
    __half* mid_h = (__half*)sym(g_mid_h);
    __half* q_h   = (__half*)sym(g_q_h);
    __half* k_h   = (__half*)sym(g_k_h);
    __half* k_l   = (__half*)sym(g_k_l);
    __half* vt_h  = (__half*)sym(g_vt_h);
    __half* vt_l  = (__half*)sym(g_vt_l);
    __half* whi   = (__half*)sym(g_whi);
    __half* wlo   = (__half*)sym(g_wlo);
    float* out = (float*)d_out;

    const int SMEM  = 61440;
    const int ASMEM = 75776;
    cudaFuncSetAttribute(gemm_f16<0,0,0>, cudaFuncAttributeMaxDynamicSharedMemorySize, SMEM);
    cudaFuncSetAttribute(gemm_f16<0,1,0>, cudaFuncAttributeMaxDynamicSharedMemorySize, SMEM);
    cudaFuncSetAttribute(gemm_f16<1,0,1>, cudaFuncAttributeMaxDynamicSharedMemorySize, SMEM);
    cudaFuncSetAttribute(attn_mma, cudaFuncAttributeMaxDynamicSharedMemorySize, ASMEM);

    // --- graph prep + SPD via boolean matrix powers ---
    zero_prep<<<(GG * MM * 32 + 255) / 256, 256>>>(p_cnt, p_adj);
    splitw<<<(344064 + 255) / 256, 256>>>((const float4*)gcn_w, (const float4*)qkv_w,
        (const float4*)proj_w, (const float4*)ffn1_w, (const float4*)ffn2_w,
        (const float4*)offn1_w, (const float4*)offn2_w, whi, wlo);
    edge_prep<<<(E + 255) / 256, 256>>>(ei, E, p_cnt, p_adj);
    spd_round<<<NN * 32 / 256, 256>>>(p_adj, p_adj, p_R2);
    spd_round<<<NN * 32 / 256, 256>>>(p_adj, p_R2, p_R3);
    spd_round<<<NN * 32 / 256, 256>>>(p_adj, p_R3, p_R4);
    spd_round<<<NN * 32 / 256, 256>>>(p_adj, p_R4, p_R5);
    spd_final<<<NN * 32 / 256, 256>>>(p_adj, p_R2, p_R3, p_R4, p_R5, p_dist);

    // --- remaining prep ---
    splitx<<<(NN * HH / 4 + 255) / 256, 256>>>((const float4*)x, x_h, NN * HH / 4);
    scan_kernel<<<1, 1024>>>(p_cnt, p_base, p_fill, p_dinv);
    fill_edges<<<(E + 255) / 256, 256>>>(ei, E, p_fill, p_esrc);

    // --- GCN branch ---
    gemm_f16<0,0,0><<<dim3(NN/128, HH/128), 256, SMEM>>>(x_h, whi + OFF_GCN, wlo + OFF_GCN,
        nullptr, nullptr, p_xw, nullptr, HH, HH);
    gcn_gather<<<NN / 4, 256>>>(p_xw, p_dinv, p_base, p_cnt, p_esrc, gcn_b, p_xl);

    // --- Graphormer layer ---
    gemm_f16<0,0,0><<<dim3(NN/128, QKVD/128), 256, SMEM>>>(x_h, whi + OFF_QKV, wlo + OFF_QKV,
        qkv_b, nullptr, p_qkv, nullptr, HH, QKVD);
    qkv_prep<<<NN / 64, 256>>>(p_qkv, q_h, k_h, k_l, vt_h, vt_l);
    attn_mma<<<dim3(GG * NHEADS, MM / 128), 256, ASMEM>>>(q_h, k_h, k_l, vt_h, vt_l,
        p_dist, bias_e, at_h);
    gemm_f16<0,1,0><<<dim3(NN/128, HH/128), 256, SMEM>>>(at_h, whi + OFF_PROJ, wlo + OFF_PROJ,
        proj_b, x, p_tmp, nullptr, HH, HH);
    ln_kernel<<<NN, 256>>>(p_tmp, nullptr, nullptr, ln1_g, ln1_b, p_h1, h1_h);
    gemm_f16<1,0,1><<<dim3(NN/128, FFND/128), 256, SMEM>>>(h1_h, whi + OFF_FFN1, wlo + OFF_FFN1,
        ffn1_b, nullptr, nullptr, mid_h, HH, FFND);
    gemm_f16<0,1,0><<<dim3(NN/128, HH/128), 256, SMEM>>>(mid_h, whi + OFF_FFN2, wlo + OFF_FFN2,
        ffn2_b, p_h1, p_tmp, nullptr, FFND, HH);
    ln_kernel<<<NN, 256>>>(p_tmp, nullptr, nullptr, ln2_g, ln2_b, p_h2, nullptr);

    // --- GPS combine + outer FFN ---
    ln_kernel<<<NN, 256>>>(x, p_xl, p_h2, oln1_g, oln1_b, p_y, y_h);
    gemm_f16<1,0,1><<<dim3(NN/128, FFND/128), 256, SMEM>>>(y_h, whi + OFF_OFFN1, wlo + OFF_OFFN1,
        offn1_b, nullptr, nullptr, mid_h, HH, FFND);
    gemm_f16<0,1,0><<<dim3(NN/128, HH/128), 256, SMEM>>>(mid_h, whi + OFF_OFFN2, wlo + OFF_OFFN2,
        offn2_b, p_y, p_tmp, nullptr, FFND, HH);
    ln_kernel<<<NN, 256>>>(p_tmp, nullptr, nullptr, oln2_g, oln2_b, out, nullptr);
}

// round 11
// speedup vs baseline: 1.9335x; 1.1198x over previous
#include <cuda_runtime.h>
#include <cuda_fp16.h>
#include <cstdint>
#include <math.h>

#define GG 8
#define MM 1024
#define NN 8192
#define HH 256
#define NHEADS 8
#define HDIM 32
#define FFND 1024
#define QKVD 768

// ---------------- scratch ----------------
__device__ float    g_dinv[NN];
__device__ float    g_xw  [NN * HH];
__device__ float    g_xl  [NN * HH];
__device__ uint32_t g_adj [GG * MM * 32];
__device__ uint32_t g_R2  [GG * MM * 32];
__device__ uint32_t g_R3  [GG * MM * 32];
__device__ uint32_t g_R4  [GG * MM * 32];
__device__ uint32_t g_R5  [GG * MM * 32];
__device__ unsigned char g_dist[(size_t)GG * MM * MM];
__device__ float    g_qkv [(size_t)NN * QKVD];
__device__ float    g_tmp [NN * HH];
__device__ float    g_h1  [NN * HH];
__device__ float    g_h2  [NN * HH];
__device__ float    g_y   [NN * HH];
__device__ int      g_cnt [NN];
__device__ int      g_base[NN];
__device__ int      g_fillp[NN];
__device__ int      g_esrc[262144];

#define AL16 __align__(16)
__device__ AL16 __half g_x_h [NN * HH];
__device__ AL16 __half g_at_h[NN * HH];
__device__ AL16 __half g_h1_h[NN * HH];
__device__ AL16 __half g_y_h [NN * HH];
__device__ AL16 __half g_mid_h[(size_t)NN * FFND];
__device__ AL16 __half g_q_h [NN * HH];
__device__ AL16 __half g_k_h [NN * HH];
__device__ AL16 __half g_vt_h[GG * NHEADS * HDIM * MM];
__device__ AL16 __half g_whi[1376256], g_wlo[1376256];
#define OFF_GCN   0
#define OFF_QKV   65536
#define OFF_PROJ  262144
#define OFF_FFN1  327680
#define OFF_FFN2  589824
#define OFF_OFFN1 851968
#define OFF_OFFN2 1114112

// ---------------- helpers ----------------
__device__ __forceinline__ uint32_t packh(float a, float b) {
    uint32_t r;
    asm("cvt.rn.f16x2.f32 %0, %1, %2;" : "=r"(r) : "f"(b), "f"(a));
    return r;
}
__device__ __forceinline__ float ex2f(float x) {
    float y; asm("ex2.approx.f32 %0, %1;" : "=f"(y) : "f"(x)); return y;
}
__device__ __forceinline__ void split2(float a, float b, uint32_t& hi, uint32_t& lo) {
    uint32_t h = packh(a, b);
    __half2 h2 = *reinterpret_cast<__half2*>(&h);
    float2 f2 = __half22float2(h2);
    hi = h;
    lo = packh(a - f2.x, b - f2.y);
}
#define CP16(dst, src) asm volatile("cp.async.cg.shared.global [%0], [%1], 16;\n" :: "r"(dst), "l"(src))
#define MMAH(d, a0, a1, a2, a3, b0, b1) \
    asm volatile("mma.sync.aligned.m16n8k16.row.col.f32.f16.f16.f32 " \
                 "{%0,%1,%2,%3}, {%4,%5,%6,%7}, {%8,%9}, {%0,%1,%2,%3};" \
                 : "+f"(d[0]), "+f"(d[1]), "+f"(d[2]), "+f"(d[3]) \
                 : "r"(a0), "r"(a1), "r"(a2), "r"(a3), "r"(b0), "r"(b1))
#define LDSM4(r0, r1, r2, r3, addr) \
    asm volatile("ldmatrix.sync.aligned.m8n8.x4.shared.b16 {%0,%1,%2,%3}, [%4];" \
                 : "=r"(r0), "=r"(r1), "=r"(r2), "=r"(r3) : "r"(addr))

// ---------------- splits ----------------
__global__ void splitx(const float4* __restrict__ in, __half* __restrict__ hi, int n4) {
    int i = blockIdx.x * blockDim.x + threadIdx.x;
    if (i >= n4) return;
    float4 v = in[i];
    *(uint2*)(hi + i * 4) = make_uint2(packh(v.x, v.y), packh(v.z, v.w));
}
__global__ void splitw(const float4* w0, const float4* w1, const float4* w2, const float4* w3,
                       const float4* w4, const float4* w5, const float4* w6,
                       __half* __restrict__ hi, __half* __restrict__ lo) {
    int i = blockIdx.x * blockDim.x + threadIdx.x;
    if (i >= 344064) return;
    const float4* src; int base;
    if      (i < 16384)  { src = w0; base = 0; }
    else if (i < 65536)  { src = w1; base = 16384; }
    else if (i < 81920)  { src = w2; base = 65536; }
    else if (i < 147456) { src = w3; base = 81920; }
    else if (i < 212992) { src = w4; base = 147456; }
    else if (i < 278528) { src = w5; base = 212992; }
    else                 { src = w6; base = 278528; }
    float4 v = src[i - base];
    uint32_t h0, l0, h1, l1;
    split2(v.x, v.y, h0, l0);
    split2(v.z, v.w, h1, l1);
    *(uint2*)(hi + (size_t)i * 4) = make_uint2(h0, h1);
    *(uint2*)(lo + (size_t)i * 4) = make_uint2(l0, l1);
}

// ---------------- graph prep ----------------
__global__ void zero_prep(int* __restrict__ cnt, uint32_t* __restrict__ adj) {
    int i = blockIdx.x * blockDim.x + threadIdx.x;
    if (i < GG * MM * 32) adj[i] = 0u;
    if (i < NN) cnt[i] = 0;
}
__global__ void edge_prep(const int* __restrict__ ei, int E, int* __restrict__ cnt,
                          uint32_t* __restrict__ adj) {
    int e = blockIdx.x * blockDim.x + threadIdx.x;
    if (e >= E) return;
    int s = ei[e], d = ei[E + e];
    atomicAdd(&cnt[d], 1);
    if (s == d || (s >> 10) != (d >> 10)) return;
    int g = s >> 10, ls = s & 1023, ld = d & 1023;
    atomicOr(&adj[((size_t)g * MM + ls) * 32 + (ld >> 5)], 1u << (ld & 31));
    atomicOr(&adj[((size_t)g * MM + ld) * 32 + (ls >> 5)], 1u << (ls & 31));
}
__global__ void scan_kernel(const int* __restrict__ cnt, int* __restrict__ base,
                            int* __restrict__ fillp, float* __restrict__ dinv) {
    __shared__ int wsum[32];
    int t = threadIdx.x;
    int v[8]; int s = 0;
#pragma unroll
    for (int k = 0; k < 8; ++k) { v[k] = s; s += cnt[t * 8 + k]; }
    int lane = t & 31, w = t >> 5;
    int tot = s, sc = s;
#pragma unroll
    for (int o = 1; o < 32; o <<= 1) {
        int n = __shfl_up_sync(0xFFFFFFFFu, sc, o);
        if (lane >= o) sc += n;
    }
    if (lane == 31) wsum[w] = sc;
    __syncthreads();
    if (w == 0) {
        int x = wsum[lane];
#pragma unroll
        for (int o = 1; o < 32; o <<= 1) {
            int n = __shfl_up_sync(0xFFFFFFFFu, x, o);
            if (lane >= o) x += n;
        }
        wsum[lane] = x;
    }
    __syncthreads();
    int excl = sc - tot + (w > 0 ? wsum[w - 1] : 0);
#pragma unroll
    for (int k = 0; k < 8; ++k) {
        int idx = t * 8 + k;
        int b = excl + v[k];
        base[idx] = b;
        fillp[idx] = b;
        dinv[idx] = rsqrtf((float)cnt[idx] + 1.0f);
    }
}
__global__ void fill_edges(const int* __restrict__ ei, int E, int* __restrict__ fillp,
                           int* __restrict__ esrc) {
    int e = blockIdx.x * blockDim.x + threadIdx.x;
    if (e >= E) return;
    int s = ei[e], d = ei[E + e];
    int pos = atomicAdd(&fillp[d], 1);
    esrc[pos] = s;
}
__launch_bounds__(256)
__global__ void gcn_gather(const float* __restrict__ xw, const float* __restrict__ dinv,
                           const int* __restrict__ base, const int* __restrict__ cnt,
                           const int* __restrict__ esrc, const float* __restrict__ gcn_b,
                           float* __restrict__ xl) {
    int node = blockIdx.x * 4 + (threadIdx.x >> 6);
    int c4 = (threadIdx.x & 63) * 4;
    float dd = dinv[node];
    float4 v0 = *(const float4*)&xw[(size_t)node * HH + c4];
    float ax = dd * v0.x, ay = dd * v0.y, az = dd * v0.z, aw = dd * v0.w;
    int b0 = __ldg(&base[node]);
    int n  = __ldg(&cnt[node]);
    int k = 0;
    for (; k + 4 <= n; k += 4) {
        int s0 = __ldg(&esrc[b0 + k]);
        int s1 = __ldg(&esrc[b0 + k + 1]);
        int s2 = __ldg(&esrc[b0 + k + 2]);
        int s3 = __ldg(&esrc[b0 + k + 3]);
        float w0 = __ldg(&dinv[s0]), w1 = __ldg(&dinv[s1]);
        float w2 = __ldg(&dinv[s2]), w3 = __ldg(&dinv[s3]);
        float4 a = *(const float4*)&xw[(size_t)s0 * HH + c4];
        float4 b = *(const float4*)&xw[(size_t)s1 * HH + c4];
        float4 c = *(const float4*)&xw[(size_t)s2 * HH + c4];
        float4 d = *(const float4*)&xw[(size_t)s3 * HH + c4];
        ax += w0 * a.x + w1 * b.x + w2 * c.x + w3 * d.x;
        ay += w0 * a.y + w1 * b.y + w2 * c.y + w3 * d.y;
        az += w0 * a.z + w1 * b.z + w2 * c.z + w3 * d.z;
        aw += w0 * a.w + w1 * b.w + w2 * c.w + w3 * d.w;
    }
    for (; k < n; ++k) {
        int s = __ldg(&esrc[b0 + k]);
        float ws = __ldg(&dinv[s]);
        float4 v = *(const float4*)&xw[(size_t)s * HH + c4];
        ax += ws * v.x; ay += ws * v.y; az += ws * v.z; aw += ws * v.w;
    }
    float4 bia = *(const float4*)&gcn_b[c4];
    float4 o;
    o.x = dd * ax + bia.x; o.y = dd * ay + bia.y;
    o.z = dd * az + bia.z; o.w = dd * aw + bia.w;
    *(float4*)&xl[(size_t)node * HH + c4] = o;
}

// ---------------- SPD: boolean matrix powers, warp-per-row ----------------
__launch_bounds__(256)
__global__ void spd_round(const uint32_t* __restrict__ adj, const uint32_t* __restrict__ Rp,
                          uint32_t* __restrict__ Rn) {
    int gw = (blockIdx.x * 256 + threadIdx.x) >> 5;
    int lane = threadIdx.x & 31;
    int g = gw >> 10, i = gw & 1023;
    const uint32_t* Rg = Rp + (size_t)g * MM * 32;
    uint32_t a = adj[((size_t)g * MM + i) * 32 + lane];
    uint32_t nw = Rg[i * 32 + lane];
    for (int w = 0; w < 32; ++w) {
        uint32_t f = __shfl_sync(0xFFFFFFFFu, a, w);
        while (f) {
            int b = __ffs((int)f) - 1;
            f &= f - 1;
            nw |= Rg[(w * 32 + b) * 32 + lane];
        }
    }
    Rn[((size_t)g * MM + i) * 32 + lane] = nw;
}
__device__ __forceinline__ uint32_t nibspread(uint32_t r, int q) {
    return (((r >> (q * 4)) & 0xFu) * 0x00204081u) & 0x01010101u;
}
__launch_bounds__(256)
__global__ void spd_final(const uint32_t* __restrict__ R1, const uint32_t* __restrict__ R2,
                          const uint32_t* __restrict__ R3, const uint32_t* __restrict__ R4,
                          const uint32_t* __restrict__ R5, unsigned char* __restrict__ dist) {
    int idx = blockIdx.x * 256 + threadIdx.x;
    int row = idx >> 5, w = idx & 31;
    uint32_t r1 = R1[idx], r2 = R2[idx], r3 = R3[idx], r4 = R4[idx], r5 = R5[idx];
    unsigned char* drow = dist + (size_t)row * MM;
    uint4* dp = (uint4*)(drow + w * 32);
    uint32_t o[8];
#pragma unroll
    for (int q = 0; q < 8; ++q) {
        uint32_t s = nibspread(r1, q) + nibspread(r2, q) + nibspread(r3, q)
                   + nibspread(r4, q) + nibspread(r5, q);
        o[q] = 0x06060606u - s;
    }
    dp[0] = make_uint4(o[0], o[1], o[2], o[3]);
    dp[1] = make_uint4(o[4], o[5], o[6], o[7]);
    int i = row & 1023;
    if ((i >> 5) == w) drow[i] = 0;
}

// ---------------- fp16 GEMM 128x128 (ldmatrix) ----------------
template <int GELU, int RES, int OUTF16>
__launch_bounds__(256, 2)
__global__ void gemm_f16(const __half* __restrict__ Ag, const __half* __restrict__ Whg,
                         const __half* __restrict__ Wlg,
                         const float* __restrict__ bias, const float* __restrict__ res,
                         float* __restrict__ C, __half* __restrict__ Ch, int K, int F) {
    extern __shared__ unsigned char smp[];
    const int STG = 30720;
    int m0 = blockIdx.x * 128, f0 = blockIdx.y * 128;
    int tid = threadIdx.x, lane = tid & 31, warp = tid >> 5;
    int g = lane >> 2, tg = lane & 3;
    int wm = (warp >> 2) * 64, wn = (warp & 3) * 32;
    uint32_t smem_base = (uint32_t)__cvta_generic_to_shared(smp);

    uint32_t aOff = (uint32_t)(wm + (lane & 15)) * 80 + (uint32_t)(lane >> 4) * 16;
    uint32_t bOff = (uint32_t)(wn + ((lane >> 4) << 3) + (lane & 7)) * 80
                  + (uint32_t)((lane >> 3) & 1) * 16;

    float acc[4][4][4];
#pragma unroll
    for (int a = 0; a < 4; ++a)
#pragma unroll
        for (int b = 0; b < 4; ++b)
#pragma unroll
            for (int c = 0; c < 4; ++c) acc[a][b][c] = 0.f;

    auto load_stage = [&](int s, int k0) {
        uint32_t db = smem_base + s * STG;
        const __half* srcs[3] = {
            Ag + (size_t)m0 * K + k0, Whg + (size_t)f0 * K + k0, Wlg + (size_t)f0 * K + k0 };
#pragma unroll
        for (int arr = 0; arr < 3; ++arr) {
            const __half* bp = srcs[arr];
            uint32_t ab = db + arr * 10240;
#pragma unroll
            for (int c = 0; c < 2; ++c) {
                int t = tid + c * 256;
                int row = t >> 2, ch = t & 3;
                CP16(ab + row * 80 + ch * 16, bp + (size_t)row * K + ch * 8);
            }
        }
        asm volatile("cp.async.commit_group;\n" ::);
    };

    int nk = K >> 5;
    load_stage(0, 0);
    for (int kc = 0; kc < nk; ++kc) {
        if (kc + 1 < nk) {
            load_stage((kc + 1) & 1, (kc + 1) << 5);
            asm volatile("cp.async.wait_group 1;\n" ::);
        } else {
            asm volatile("cp.async.wait_group 0;\n" ::);
        }
        __syncthreads();

        uint32_t stg = smem_base + (kc & 1) * STG;
        uint32_t aB  = stg + aOff;
        uint32_t whB = stg + 10240 + bOff;
        uint32_t wlB = stg + 20480 + bOff;
#pragma unroll
        for (int ks = 0; ks < 2; ++ks) {
            uint32_t bh[4][2], bl[4][2];
            LDSM4(bh[0][0], bh[0][1], bh[1][0], bh[1][1], whB + ks * 32);
            LDSM4(bh[2][0], bh[2][1], bh[3][0], bh[3][1], whB + 1280 + ks * 32);
            LDSM4(bl[0][0], bl[0][1], bl[1][0], bl[1][1], wlB + ks * 32);
            LDSM4(bl[2][0], bl[2][1], bl[3][0], bl[3][1], wlB + 1280 + ks * 32);
#pragma unroll
            for (int mt = 0; mt < 4; ++mt) {
                uint32_t a0, a1, a2, a3;
                LDSM4(a0, a1, a2, a3, aB + mt * 1280 + ks * 32);
#pragma unroll
                for (int nt = 0; nt < 4; ++nt) {
                    MMAH(acc[mt][nt], a0, a1, a2, a3, bh[nt][0], bh[nt][1]);
                    MMAH(acc[mt][nt], a0, a1, a2, a3, bl[nt][0], bl[nt][1]);
                }
            }
        }
        __syncthreads();
    }

#pragma unroll
    for (int mt = 0; mt < 4; ++mt) {
#pragma unroll
        for (int half = 0; half < 2; ++half) {
            int row = m0 + wm + mt * 16 + g + half * 8;
#pragma unroll
            for (int nt = 0; nt < 4; ++nt) {
                int col = f0 + wn + nt * 8 + tg * 2;
                float v0 = acc[mt][nt][half * 2 + 0];
                float v1 = acc[mt][nt][half * 2 + 1];
                if (bias) { v0 += bias[col]; v1 += bias[col + 1]; }
                if (GELU) { v0 = v0 * normcdff(v0); v1 = v1 * normcdff(v1); }
                if (RES)  { v0 += res[(size_t)row * F + col]; v1 += res[(size_t)row * F + col + 1]; }
                if (OUTF16) {
                    *(uint32_t*)(Ch + (size_t)row * F + col) = packh(v0, v1);
                } else {
                    float2 o; o.x = v0; o.y = v1;
                    *(float2*)(C + (size_t)row * F + col) = o;
                }
            }
        }
    }
}

// ---------------- qkv prepass (q prescaled, k single, v transposed single) ----------------
__launch_bounds__(256)
__global__ void qkv_prep(const float* __restrict__ qkv,
                         __half* __restrict__ qh, __half* __restrict__ kh,
                         __half* __restrict__ vth) {
    __shared__ float vsm[64][33];
    int nb = blockIdx.x * 64;
    int g = nb >> 10;
    int jb = nb & 1023;
    int tid = threadIdx.x;
    const float scale = 0.17677669529663687f;

#pragma unroll
    for (int it = 0; it < 32; ++it) {
        int flat = tid + it * 256;
        int row = flat >> 7, c4 = flat & 127;
        int node = nb + row;
        float4 v = *(const float4*)&qkv[(size_t)node * QKVD + c4 * 4];
        int c = c4 * 4;
        if (c < 256) {
            *(uint2*)(qh + (size_t)node * HH + c) =
                make_uint2(packh(v.x * scale, v.y * scale), packh(v.z * scale, v.w * scale));
        } else {
            *(uint2*)(kh + (size_t)node * HH + c - 256) =
                make_uint2(packh(v.x, v.y), packh(v.z, v.w));
        }
    }

    for (int h = 0; h < NHEADS; ++h) {
        __syncthreads();
#pragma unroll
        for (int it = 0; it < 2; ++it) {
            int flat = tid + it * 256;
            int row = flat >> 3, c4 = flat & 7;
            float4 v = *(const float4*)&qkv[(size_t)(nb + row) * QKVD + 512 + h * 32 + c4 * 4];
            vsm[row][c4 * 4 + 0] = v.x;
            vsm[row][c4 * 4 + 1] = v.y;
            vsm[row][c4 * 4 + 2] = v.z;
            vsm[row][c4 * 4 + 3] = v.w;
        }
        __syncthreads();
        int d = tid >> 3, j0 = (tid & 7) * 8;
        uint32_t hw[4];
#pragma unroll
        for (int p = 0; p < 4; ++p)
            hw[p] = packh(vsm[j0 + p * 2 + 0][d], vsm[j0 + p * 2 + 1][d]);
        size_t off = ((size_t)(g * NHEADS + h) * HDIM + d) * MM + jb + j0;
        *(uint4*)(vth + off) = make_uint4(hw[0], hw[1], hw[2], hw[3]);
    }
}

// ---------------- flash attention (fp16 single K/V) ----------------
__launch_bounds__(256)
__global__ void attn_mma(const __half* __restrict__ qh, const __half* __restrict__ kh,
                         const __half* __restrict__ vth,
                         const unsigned char* __restrict__ dist, const float* __restrict__ bias_emb,
                         __half* __restrict__ oh) {
    extern __shared__ unsigned char smp[];
    const int STG = 18944;   // K 10240 + VT 8704
    __shared__ float btab[8];
    int gh = blockIdx.x;
    int g = gh >> 3, h = gh & 7;
    int i0 = blockIdx.y * 128;
    int tid = threadIdx.x, lane = tid & 31, warp = tid >> 5;
    int r = lane >> 2, tg = lane & 3;
    if (tid < 7) btab[tid] = bias_emb[tid];
    uint32_t sb = (uint32_t)__cvta_generic_to_shared(smp);
    const float L2E = 1.44269504f;

    int rowA = i0 + warp * 16 + r;
    int rowB = rowA + 8;
    uint32_t qf[2][4];
#pragma unroll
    for (int kc = 0; kc < 2; ++kc) {
        size_t baseA = (size_t)(g * MM + rowA) * HH + h * HDIM + kc * 16 + tg * 2;
        size_t baseB = (size_t)(g * MM + rowB) * HH + h * HDIM + kc * 16 + tg * 2;
        qf[kc][0] = *(const uint32_t*)(qh + baseA);
        qf[kc][1] = *(const uint32_t*)(qh + baseB);
        qf[kc][2] = *(const uint32_t*)(qh + baseA + 8);
        qf[kc][3] = *(const uint32_t*)(qh + baseB + 8);
    }

    float acc_o[4][4];
#pragma unroll
    for (int a = 0; a < 4; ++a)
#pragma unroll
        for (int b = 0; b < 4; ++b) acc_o[a][b] = 0.f;
    float mA = -1e30f, mB = -1e30f, lA = 0.f, lB = 0.f;

    const unsigned char* drowA = dist + ((size_t)(g * MM + rowA)) * MM;
    const unsigned char* drowB = dist + ((size_t)(g * MM + rowB)) * MM;

    auto load_stage = [&](int s, int j0) {
        uint32_t db = sb + s * STG;
#pragma unroll
        for (int c = 0; c < 2; ++c) {
            int t = tid + c * 256;
            int row = t >> 2, ch = t & 3;
            const __half* src = kh + (size_t)(g * MM + j0 + row) * HH + h * HDIM + ch * 8;
            CP16(db + row * 80 + ch * 16, src);
        }
#pragma unroll
        for (int c = 0; c < 2; ++c) {
            int t = tid + c * 256;
            int row = t >> 4, ch = t & 15;
            size_t off = ((size_t)(gh) * HDIM + row) * MM + j0 + ch * 8;
            CP16(db + 10240 + row * 272 + ch * 16, vth + off);
        }
        asm volatile("cp.async.commit_group;\n" ::);
    };

    load_stage(0, 0);
    for (int ch = 0; ch < 8; ++ch) {
        int j0 = ch * 128;
        if (ch < 7) {
            load_stage((ch + 1) & 1, j0 + 128);
            asm volatile("cp.async.wait_group 1;\n" ::);
        } else {
            asm volatile("cp.async.wait_group 0;\n" ::);
        }
        __syncthreads();

        const uint32_t* KH = (const uint32_t*)(smp + (ch & 1) * STG);
        const uint32_t* VH = KH + 2560;

        float acc_s[16][4];
#pragma unroll
        for (int nt = 0; nt < 16; ++nt)
#pragma unroll
            for (int c = 0; c < 4; ++c) acc_s[nt][c] = 0.f;
#pragma unroll
        for (int kc = 0; kc < 2; ++kc) {
#pragma unroll
            for (int nt = 0; nt < 16; ++nt) {
                int idx = (nt * 8 + r) * 20 + kc * 8 + tg;
                MMAH(acc_s[nt], qf[kc][0], qf[kc][1], qf[kc][2], qf[kc][3],
                     KH[idx], KH[idx + 4]);
            }
        }

        float cmA = -1e30f, cmB = -1e30f;
#pragma unroll
        for (int nt = 0; nt < 16; ++nt) {
            uchar2 dA = *(const uchar2*)(drowA + j0 + nt * 8 + tg * 2);
            uchar2 dB = *(const uchar2*)(drowB + j0 + nt * 8 + tg * 2);
            acc_s[nt][0] += btab[dA.x];
            acc_s[nt][1] += btab[dA.y];
            acc_s[nt][2] += btab[dB.x];
            acc_s[nt][3] += btab[dB.y];
            cmA = fmaxf(cmA, fmaxf(acc_s[nt][0], acc_s[nt][1]));
            cmB = fmaxf(cmB, fmaxf(acc_s[nt][2], acc_s[nt][3]));
        }
        cmA = fmaxf(cmA, __shfl_xor_sync(0xFFFFFFFFu, cmA, 1));
        cmA = fmaxf(cmA, __shfl_xor_sync(0xFFFFFFFFu, cmA, 2));
        cmB = fmaxf(cmB, __shfl_xor_sync(0xFFFFFFFFu, cmB, 1));
        cmB = fmaxf(cmB, __shfl_xor_sync(0xFFFFFFFFu, cmB, 2));

        float mAn = fmaxf(mA, cmA), mBn = fmaxf(mB, cmB);
        float corrA = ex2f((mA - mAn) * L2E);
        float corrB = ex2f((mB - mBn) * L2E);
        mA = mAn; mB = mBn;

        uint32_t ph0[16], ph1[16];
        float lsA = 0.f, lsB = 0.f;
#pragma unroll
        for (int nt = 0; nt < 16; ++nt) {
            float p0 = ex2f((acc_s[nt][0] - mA) * L2E);
            float p1 = ex2f((acc_s[nt][1] - mA) * L2E);
            float p2 = ex2f((acc_s[nt][2] - mB) * L2E);
            float p3 = ex2f((acc_s[nt][3] - mB) * L2E);
            lsA += p0 + p1; lsB += p2 + p3;
            ph0[nt] = packh(p0, p1);
            ph1[nt] = packh(p2, p3);
        }
        lsA += __shfl_xor_sync(0xFFFFFFFFu, lsA, 1);
        lsA += __shfl_xor_sync(0xFFFFFFFFu, lsA, 2);
        lsB += __shfl_xor_sync(0xFFFFFFFFu, lsB, 1);
        lsB += __shfl_xor_sync(0xFFFFFFFFu, lsB, 2);
        lA = lA * corrA + lsA;
        lB = lB * corrB + lsB;

#pragma unroll
        for (int nto = 0; nto < 4; ++nto) {
            acc_o[nto][0] *= corrA; acc_o[nto][1] *= corrA;
            acc_o[nto][2] *= corrB; acc_o[nto][3] *= corrB;
        }

#pragma unroll
        for (int kc = 0; kc < 8; ++kc) {
            uint32_t a0 = ph0[2 * kc], a1 = ph1[2 * kc], a2 = ph0[2 * kc + 1], a3 = ph1[2 * kc + 1];
#pragma unroll
            for (int nto = 0; nto < 4; ++nto) {
                int idx = (nto * 8 + r) * 68 + kc * 8 + tg;
                MMAH(acc_o[nto], a0, a1, a2, a3, VH[idx], VH[idx + 4]);
            }
        }
        __syncthreads();
    }

    float invA = 1.f / lA, invB = 1.f / lB;
#pragma unroll
    for (int nto = 0; nto < 4; ++nto) {
        int col = h * HDIM + nto * 8 + tg * 2;
        *(uint32_t*)(oh + (size_t)(g * MM + rowA) * HH + col) =
            packh(acc_o[nto][0] * invA, acc_o[nto][1] * invA);
        *(uint32_t*)(oh + (size_t)(g * MM + rowB) * HH + col) =
            packh(acc_o[nto][2] * invB, acc_o[nto][3] * invB);
    }
}

// ---------------- LayerNorm ----------------
__launch_bounds__(256)
__global__ void ln_kernel(const float* __restrict__ a, const float* __restrict__ b,
                          const float* __restrict__ c, const float* __restrict__ gam,
                          const float* __restrict__ bet, float* __restrict__ out,
                          __half* __restrict__ oh) {
    int row = blockIdx.x, t = threadIdx.x;
    size_t idx = (size_t)row * HH + t;
    float v = a[idx];
    if (b) v += b[idx];
    if (c) v += c[idx];
    float s = v, s2 = v * v;
#pragma unroll
    for (int o = 16; o; o >>= 1) {
        s  += __shfl_xor_sync(0xFFFFFFFFu, s, o);
        s2 += __shfl_xor_sync(0xFFFFFFFFu, s2, o);
    }
    __shared__ float sh1[8], sh2[8];
    int w = t >> 5, ln = t & 31;
    if (ln == 0) { sh1[w] = s; sh2[w] = s2; }
    __syncthreads();
    if (w == 0) {
        s  = (ln < 8) ? sh1[ln] : 0.f;
        s2 = (ln < 8) ? sh2[ln] : 0.f;
#pragma unroll
        for (int o = 4; o; o >>= 1) {
            s  += __shfl_xor_sync(0xFFFFFFFFu, s, o);
            s2 += __shfl_xor_sync(0xFFFFFFFFu, s2, o);
        }
        if (ln == 0) { sh1[0] = s; sh2[0] = s2; }
    }
    __syncthreads();
    float mean = sh1[0] * (1.f / HH);
    float var  = sh2[0] * (1.f / HH) - mean * mean;
    float rr = (v - mean) * rsqrtf(var + 1e-5f) * gam[t] + bet[t];
    out[idx] = rr;
    if (oh) oh[idx] = __float2half(rr);
}

// ---------------- host ----------------
static void* sym(const void* s) { void* p = nullptr; cudaGetSymbolAddress(&p, s); return p; }

extern "C" void kernel_launch(void* const* d_in, const int* in_sizes, int n_in,
                              void* d_out, int out_size) {
    const float* x      = (const float*)d_in[0];
    const float* gcn_w  = (const float*)d_in[1];
    const float* gcn_b  = (const float*)d_in[2];
    const float* qkv_w  = (const float*)d_in[3];
    const float* qkv_b  = (const float*)d_in[4];
    const float* proj_w = (const float*)d_in[5];
    const float* proj_b = (const float*)d_in[6];
    const float* ln1_g  = (const float*)d_in[7];
    const float* ln1_b  = (const float*)d_in[8];
    const float* ln2_g  = (const float*)d_in[9];
    const float* ln2_b  = (const float*)d_in[10];
    const float* ffn1_w = (const float*)d_in[11];
    const float* ffn1_b = (const float*)d_in[12];
    const float* ffn2_w = (const float*)d_in[13];
    const float* ffn2_b = (const float*)d_in[14];
    const float* bias_e = (const float*)d_in[15];
    const float* oln1_g = (const float*)d_in[16];
    const float* oln1_b = (const float*)d_in[17];
    const float* oln2_g = (const float*)d_in[18];
    const float* oln2_b = (const float*)d_in[19];
    const float* offn1_w= (const float*)d_in[20];
    const float* offn1_b= (const float*)d_in[21];
    const float* offn2_w= (const float*)d_in[22];
    const float* offn2_b= (const float*)d_in[23];
    const int*   ei     = (const int*)d_in[24];
    int E = in_sizes[24] / 2;

    float*    p_dinv = (float*)sym(g_dinv);
    float*    p_xw   = (float*)sym(g_xw);
    float*    p_xl   = (float*)sym(g_xl);
    uint32_t* p_adj  = (uint32_t*)sym(g_adj);
    uint32_t* p_R2   = (uint32_t*)sym(g_R2);
    uint32_t* p_R3   = (uint32_t*)sym(g_R3);
    uint32_t* p_R4   = (uint32_t*)sym(g_R4);
    uint32_t* p_R5   = (uint32_t*)sym(g_R5);
    unsigned char* p_dist = (unsigned char*)sym(g_dist);
    float*    p_qkv  = (float*)sym(g_qkv);
    float*    p_tmp  = (float*)sym(g_tmp);
    float*    p_h1   = (float*)sym(g_h1);
    float*    p_h2   = (float*)sym(g_h2);
    float*    p_y    = (float*)sym(g_y);
    int*      p_cnt  = (int*)sym(g_cnt);
    int*      p_base = (int*)sym(g_base);
    int*      p_fill = (int*)sym(g_fillp);
    int*      p_esrc = (int*)sym(g_esrc);
    __half* x_h   = (__half*)sym(g_x_h);
    __half* at_h  = (__half*)sym(g_at_h);
    __half* h1_h  = (__half*)sym(g_h1_h);
    __half* y_h   = (__half*)sym(g_y_h);
    __half* mid_h = (__half*)sym(g_mid_h);
    __half* q_h   = (__half*)sym(g_q_h);
    __half* k_h   = (__half*)sym(g_k_h);
    __half* vt_h  = (__half*)sym(g_vt_h);
    __half* whi   = (__half*)sym(g_whi);
    __half* wlo   = (__half*)sym(g_wlo);
    float* out = (float*)d_out;

    const int SMEM  = 61440;
    const int ASMEM = 37888;
    cudaFuncSetAttribute(gemm_f16<0,0,0>, cudaFuncAttributeMaxDynamicSharedMemorySize, SMEM);
    cudaFuncSetAttribute(gemm_f16<0,1,0>, cudaFuncAttributeMaxDynamicSharedMemorySize, SMEM);
    cudaFuncSetAttribute(gemm_f16<1,0,1>, cudaFuncAttributeMaxDynamicSharedMemorySize, SMEM);
    cudaFuncSetAttribute(attn_mma, cudaFuncAttributeMaxDynamicSharedMemorySize, ASMEM);

    // --- graph prep + SPD via boolean matrix powers ---
    zero_prep<<<(GG * MM * 32 + 255) / 256, 256>>>(p_cnt, p_adj);
    splitw<<<(344064 + 255) / 256, 256>>>((const float4*)gcn_w, (const float4*)qkv_w,
        (const float4*)proj_w, (const float4*)ffn1_w, (const float4*)ffn2_w,
        (const float4*)offn1_w, (const float4*)offn2_w, whi, wlo);
    edge_prep<<<(E + 255) / 256, 256>>>(ei, E, p_cnt, p_adj);
    spd_round<<<NN * 32 / 256, 256>>>(p_adj, p_adj, p_R2);
    spd_round<<<NN * 32 / 256, 256>>>(p_adj, p_R2, p_R3);
    spd_round<<<NN * 32 / 256, 256>>>(p_adj, p_R3, p_R4);
    spd_round<<<NN * 32 / 256, 256>>>(p_adj, p_R4, p_R5);
    spd_final<<<NN * 32 / 256, 256>>>(p_adj, p_R2, p_R3, p_R4, p_R5, p_dist);

    // --- remaining prep ---
    splitx<<<(NN * HH / 4 + 255) / 256, 256>>>((const float4*)x, x_h, NN * HH / 4);
    scan_kernel<<<1, 1024>>>(p_cnt, p_base, p_fill, p_dinv);
    fill_edges<<<(E + 255) / 256, 256>>>(ei, E, p_fill, p_esrc);

    // --- GCN branch ---
    gemm_f16<0,0,0><<<dim3(NN/128, HH/128), 256, SMEM>>>(x_h, whi + OFF_GCN, wlo + OFF_GCN,
        nullptr, nullptr, p_xw, nullptr, HH, HH);
    gcn_gather<<<NN / 4, 256>>>(p_xw, p_dinv, p_base, p_cnt, p_esrc, gcn_b, p_xl);

    // --- Graphormer layer ---
    gemm_f16<0,0,0><<<dim3(NN/128, QKVD/128), 256, SMEM>>>(x_h, whi + OFF_QKV, wlo + OFF_QKV,
        qkv_b, nullptr, p_qkv, nullptr, HH, QKVD);
    qkv_prep<<<NN / 64, 256>>>(p_qkv, q_h, k_h, vt_h);
    attn_mma<<<dim3(GG * NHEADS, MM / 128), 256, ASMEM>>>(q_h, k_h, vt_h, p_dist, bias_e, at_h);
    gemm_f16<0,1,0><<<dim3(NN/128, HH/128), 256, SMEM>>>(at_h, whi + OFF_PROJ, wlo + OFF_PROJ,
        proj_b, x, p_tmp, nullptr, HH, HH);
    ln_kernel<<<NN, 256>>>(p_tmp, nullptr, nullptr, ln1_g, ln1_b, p_h1, h1_h);
    gemm_f16<1,0,1><<<dim3(NN/128, FFND/128), 256, SMEM>>>(h1_h, whi + OFF_FFN1, wlo + OFF_FFN1,
        ffn1_b, nullptr, nullptr, mid_h, HH, FFND);
    gemm_f16<0,1,0><<<dim3(NN/128, HH/128), 256, SMEM>>>(mid_h, whi + OFF_FFN2, wlo + OFF_FFN2,
        ffn2_b, p_h1, p_tmp, nullptr, FFND, HH);
    ln_kernel<<<NN, 256>>>(p_tmp, nullptr, nullptr, ln2_g, ln2_b, p_h2, nullptr);

    // --- GPS combine + outer FFN ---
    ln_kernel<<<NN, 256>>>(x, p_xl, p_h2, oln1_g, oln1_b, p_y, y_h);
    gemm_f16<1,0,1><<<dim3(NN/128, FFND/128), 256, SMEM>>>(y_h, whi + OFF_OFFN1, wlo + OFF_OFFN1,
        offn1_b, nullptr, nullptr, mid_h, HH, FFND);
    gemm_f16<0,1,0><<<dim3(NN/128, HH/128), 256, SMEM>>>(mid_h, whi + OFF_OFFN2, wlo + OFF_OFFN2,
        offn2_b, p_y, p_tmp, nullptr, FFND, HH);
    ln_kernel<<<NN, 256>>>(p_tmp, nullptr, nullptr, oln2_g, oln2_b, out, nullptr);
}

// round 12
// speedup vs baseline: 2.1933x; 1.1343x over previous
#include <cuda_runtime.h>
#include <cuda_fp16.h>
#include <cstdint>
#include <math.h>

#define GG 8
#define MM 1024
#define NN 8192
#define HH 256
#define NHEADS 8
#define HDIM 32
#define FFND 1024
#define QKVD 768

// ---------------- scratch ----------------
__device__ float    g_dinv[NN];
__device__ float    g_xw  [NN * HH];
__device__ float    g_xl  [NN * HH];
__device__ uint32_t g_adj [GG * MM * 32];
__device__ uint32_t g_R2  [GG * MM * 32];
__device__ uint32_t g_R3  [GG * MM * 32];
__device__ uint32_t g_R4  [GG * MM * 32];
__device__ uint32_t g_R5  [GG * MM * 32];
__device__ unsigned char g_dist[(size_t)GG * MM * MM];
__device__ float    g_qkv [(size_t)NN * QKVD];
__device__ float    g_tmp [NN * HH];
__device__ float    g_h1  [NN * HH];
__device__ float    g_h2  [NN * HH];
__device__ float    g_y   [NN * HH];
__device__ int      g_cnt [NN];
__device__ int      g_base[NN];
__device__ int      g_fillp[NN];
__device__ int      g_esrc[262144];

#define AL16 __align__(16)
__device__ AL16 __half g_x_h [NN * HH];
__device__ AL16 __half g_at_h[NN * HH];
__device__ AL16 __half g_h1_h[NN * HH];
__device__ AL16 __half g_y_h [NN * HH];
__device__ AL16 __half g_mid_h[(size_t)NN * FFND];
__device__ AL16 __half g_q_h [NN * HH];
__device__ AL16 __half g_k_h [NN * HH];
__device__ AL16 __half g_vt_h[GG * NHEADS * HDIM * MM];
__device__ AL16 __half g_whi[1376256];
#define OFF_GCN   0
#define OFF_QKV   65536
#define OFF_PROJ  262144
#define OFF_FFN1  327680
#define OFF_FFN2  589824
#define OFF_OFFN1 851968
#define OFF_OFFN2 1114112

// ---------------- helpers ----------------
__device__ __forceinline__ uint32_t packh(float a, float b) {
    uint32_t r;
    asm("cvt.rn.f16x2.f32 %0, %1, %2;" : "=r"(r) : "f"(b), "f"(a));
    return r;
}
__device__ __forceinline__ float ex2f(float x) {
    float y; asm("ex2.approx.f32 %0, %1;" : "=f"(y) : "f"(x)); return y;
}
#define CP16(dst, src) asm volatile("cp.async.cg.shared.global [%0], [%1], 16;\n" :: "r"(dst), "l"(src))
#define MMAH(d, a0, a1, a2, a3, b0, b1) \
    asm volatile("mma.sync.aligned.m16n8k16.row.col.f32.f16.f16.f32 " \
                 "{%0,%1,%2,%3}, {%4,%5,%6,%7}, {%8,%9}, {%0,%1,%2,%3};" \
                 : "+f"(d[0]), "+f"(d[1]), "+f"(d[2]), "+f"(d[3]) \
                 : "r"(a0), "r"(a1), "r"(a2), "r"(a3), "r"(b0), "r"(b1))
#define LDSM4(r0, r1, r2, r3, addr) \
    asm volatile("ldmatrix.sync.aligned.m8n8.x4.shared.b16 {%0,%1,%2,%3}, [%4];" \
                 : "=r"(r0), "=r"(r1), "=r"(r2), "=r"(r3) : "r"(addr))

// ---------------- splits (plain fp16 cast) ----------------
__global__ void splitx(const float4* __restrict__ in, __half* __restrict__ hi, int n4) {
    int i = blockIdx.x * blockDim.x + threadIdx.x;
    if (i >= n4) return;
    float4 v = in[i];
    *(uint2*)(hi + i * 4) = make_uint2(packh(v.x, v.y), packh(v.z, v.w));
}
__global__ void splitw(const float4* w0, const float4* w1, const float4* w2, const float4* w3,
                       const float4* w4, const float4* w5, const float4* w6,
                       __half* __restrict__ hi) {
    int i = blockIdx.x * blockDim.x + threadIdx.x;
    if (i >= 344064) return;
    const float4* src; int base;
    if      (i < 16384)  { src = w0; base = 0; }
    else if (i < 65536)  { src = w1; base = 16384; }
    else if (i < 81920)  { src = w2; base = 65536; }
    else if (i < 147456) { src = w3; base = 81920; }
    else if (i < 212992) { src = w4; base = 147456; }
    else if (i < 278528) { src = w5; base = 212992; }
    else                 { src = w6; base = 278528; }
    float4 v = src[i - base];
    *(uint2*)(hi + (size_t)i * 4) = make_uint2(packh(v.x, v.y), packh(v.z, v.w));
}

// ---------------- graph prep ----------------
__global__ void zero_prep(int* __restrict__ cnt, uint32_t* __restrict__ adj) {
    int i = blockIdx.x * blockDim.x + threadIdx.x;
    if (i < GG * MM * 32) adj[i] = 0u;
    if (i < NN) cnt[i] = 0;
}
__global__ void edge_prep(const int* __restrict__ ei, int E, int* __restrict__ cnt,
                          uint32_t* __restrict__ adj) {
    int e = blockIdx.x * blockDim.x + threadIdx.x;
    if (e >= E) return;
    int s = ei[e], d = ei[E + e];
    atomicAdd(&cnt[d], 1);
    if (s == d || (s >> 10) != (d >> 10)) return;
    int g = s >> 10, ls = s & 1023, ld = d & 1023;
    atomicOr(&adj[((size_t)g * MM + ls) * 32 + (ld >> 5)], 1u << (ld & 31));
    atomicOr(&adj[((size_t)g * MM + ld) * 32 + (ls >> 5)], 1u << (ls & 31));
}
__global__ void scan_kernel(const int* __restrict__ cnt, int* __restrict__ base,
                            int* __restrict__ fillp, float* __restrict__ dinv) {
    __shared__ int wsum[32];
    int t = threadIdx.x;
    int v[8]; int s = 0;
#pragma unroll
    for (int k = 0; k < 8; ++k) { v[k] = s; s += cnt[t * 8 + k]; }
    int lane = t & 31, w = t >> 5;
    int tot = s, sc = s;
#pragma unroll
    for (int o = 1; o < 32; o <<= 1) {
        int n = __shfl_up_sync(0xFFFFFFFFu, sc, o);
        if (lane >= o) sc += n;
    }
    if (lane == 31) wsum[w] = sc;
    __syncthreads();
    if (w == 0) {
        int x = wsum[lane];
#pragma unroll
        for (int o = 1; o < 32; o <<= 1) {
            int n = __shfl_up_sync(0xFFFFFFFFu, x, o);
            if (lane >= o) x += n;
        }
        wsum[lane] = x;
    }
    __syncthreads();
    int excl = sc - tot + (w > 0 ? wsum[w - 1] : 0);
#pragma unroll
    for (int k = 0; k < 8; ++k) {
        int idx = t * 8 + k;
        int b = excl + v[k];
        base[idx] = b;
        fillp[idx] = b;
        dinv[idx] = rsqrtf((float)cnt[idx] + 1.0f);
    }
}
__global__ void fill_edges(const int* __restrict__ ei, int E, int* __restrict__ fillp,
                           int* __restrict__ esrc) {
    int e = blockIdx.x * blockDim.x + threadIdx.x;
    if (e >= E) return;
    int s = ei[e], d = ei[E + e];
    int pos = atomicAdd(&fillp[d], 1);
    esrc[pos] = s;
}
__launch_bounds__(256)
__global__ void gcn_gather(const float* __restrict__ xw, const float* __restrict__ dinv,
                           const int* __restrict__ base, const int* __restrict__ cnt,
                           const int* __restrict__ esrc, const float* __restrict__ gcn_b,
                           float* __restrict__ xl) {
    int node = blockIdx.x * 4 + (threadIdx.x >> 6);
    int c4 = (threadIdx.x & 63) * 4;
    float dd = dinv[node];
    float4 v0 = *(const float4*)&xw[(size_t)node * HH + c4];
    float ax = dd * v0.x, ay = dd * v0.y, az = dd * v0.z, aw = dd * v0.w;
    int b0 = __ldg(&base[node]);
    int n  = __ldg(&cnt[node]);
    int k = 0;
    for (; k + 4 <= n; k += 4) {
        int s0 = __ldg(&esrc[b0 + k]);
        int s1 = __ldg(&esrc[b0 + k + 1]);
        int s2 = __ldg(&esrc[b0 + k + 2]);
        int s3 = __ldg(&esrc[b0 + k + 3]);
        float w0 = __ldg(&dinv[s0]), w1 = __ldg(&dinv[s1]);
        float w2 = __ldg(&dinv[s2]), w3 = __ldg(&dinv[s3]);
        float4 a = *(const float4*)&xw[(size_t)s0 * HH + c4];
        float4 b = *(const float4*)&xw[(size_t)s1 * HH + c4];
        float4 c = *(const float4*)&xw[(size_t)s2 * HH + c4];
        float4 d = *(const float4*)&xw[(size_t)s3 * HH + c4];
        ax += w0 * a.x + w1 * b.x + w2 * c.x + w3 * d.x;
        ay += w0 * a.y + w1 * b.y + w2 * c.y + w3 * d.y;
        az += w0 * a.z + w1 * b.z + w2 * c.z + w3 * d.z;
        aw += w0 * a.w + w1 * b.w + w2 * c.w + w3 * d.w;
    }
    for (; k < n; ++k) {
        int s = __ldg(&esrc[b0 + k]);
        float ws = __ldg(&dinv[s]);
        float4 v = *(const float4*)&xw[(size_t)s * HH + c4];
        ax += ws * v.x; ay += ws * v.y; az += ws * v.z; aw += ws * v.w;
    }
    float4 bia = *(const float4*)&gcn_b[c4];
    float4 o;
    o.x = dd * ax + bia.x; o.y = dd * ay + bia.y;
    o.z = dd * az + bia.z; o.w = dd * aw + bia.w;
    *(float4*)&xl[(size_t)node * HH + c4] = o;
}

// ---------------- SPD: boolean matrix powers, warp-per-row ----------------
__launch_bounds__(256)
__global__ void spd_round(const uint32_t* __restrict__ adj, const uint32_t* __restrict__ Rp,
                          uint32_t* __restrict__ Rn) {
    int gw = (blockIdx.x * 256 + threadIdx.x) >> 5;
    int lane = threadIdx.x & 31;
    int g = gw >> 10, i = gw & 1023;
    const uint32_t* Rg = Rp + (size_t)g * MM * 32;
    uint32_t a = adj[((size_t)g * MM + i) * 32 + lane];
    uint32_t nw = Rg[i * 32 + lane];
    for (int w = 0; w < 32; ++w) {
        uint32_t f = __shfl_sync(0xFFFFFFFFu, a, w);
        while (f) {
            int b = __ffs((int)f) - 1;
            f &= f - 1;
            nw |= Rg[(w * 32 + b) * 32 + lane];
        }
    }
    Rn[((size_t)g * MM + i) * 32 + lane] = nw;
}
__device__ __forceinline__ uint32_t nibspread(uint32_t r, int q) {
    return (((r >> (q * 4)) & 0xFu) * 0x00204081u) & 0x01010101u;
}
__launch_bounds__(256)
__global__ void spd_final(const uint32_t* __restrict__ R1, const uint32_t* __restrict__ R2,
                          const uint32_t* __restrict__ R3, const uint32_t* __restrict__ R4,
                          const uint32_t* __restrict__ R5, unsigned char* __restrict__ dist) {
    int idx = blockIdx.x * 256 + threadIdx.x;
    int row = idx >> 5, w = idx & 31;
    uint32_t r1 = R1[idx], r2 = R2[idx], r3 = R3[idx], r4 = R4[idx], r5 = R5[idx];
    unsigned char* drow = dist + (size_t)row * MM;
    uint4* dp = (uint4*)(drow + w * 32);
    uint32_t o[8];
#pragma unroll
    for (int q = 0; q < 8; ++q) {
        uint32_t s = nibspread(r1, q) + nibspread(r2, q) + nibspread(r3, q)
                   + nibspread(r4, q) + nibspread(r5, q);
        o[q] = 0x06060606u - s;
    }
    dp[0] = make_uint4(o[0], o[1], o[2], o[3]);
    dp[1] = make_uint4(o[4], o[5], o[6], o[7]);
    int i = row & 1023;
    if ((i >> 5) == w) drow[i] = 0;
}

// ---------------- fp16 GEMM 128x128 (ldmatrix, single-fp16 W) ----------------
template <int GELU, int RES, int OUTF16>
__launch_bounds__(256, 2)
__global__ void gemm_f16(const __half* __restrict__ Ag, const __half* __restrict__ Whg,
                         const float* __restrict__ bias, const float* __restrict__ res,
                         float* __restrict__ C, __half* __restrict__ Ch, int K, int F) {
    extern __shared__ unsigned char smp[];
    const int STG = 20480;       // 2 arrays x 128 rows x 80B
    int m0 = blockIdx.x * 128, f0 = blockIdx.y * 128;
    int tid = threadIdx.x, lane = tid & 31, warp = tid >> 5;
    int g = lane >> 2, tg = lane & 3;
    int wm = (warp >> 2) * 64, wn = (warp & 3) * 32;
    uint32_t smem_base = (uint32_t)__cvta_generic_to_shared(smp);

    uint32_t aOff = (uint32_t)(wm + (lane & 15)) * 80 + (uint32_t)(lane >> 4) * 16;
    uint32_t bOff = (uint32_t)(wn + ((lane >> 4) << 3) + (lane & 7)) * 80
                  + (uint32_t)((lane >> 3) & 1) * 16;

    float acc[4][4][4];
#pragma unroll
    for (int a = 0; a < 4; ++a)
#pragma unroll
        for (int b = 0; b < 4; ++b)
#pragma unroll
            for (int c = 0; c < 4; ++c) acc[a][b][c] = 0.f;

    auto load_stage = [&](int s, int k0) {
        uint32_t db = smem_base + s * STG;
        const __half* srcs[2] = { Ag + (size_t)m0 * K + k0, Whg + (size_t)f0 * K + k0 };
#pragma unroll
        for (int arr = 0; arr < 2; ++arr) {
            const __half* bp = srcs[arr];
            uint32_t ab = db + arr * 10240;
#pragma unroll
            for (int c = 0; c < 2; ++c) {
                int t = tid + c * 256;
                int row = t >> 2, ch = t & 3;
                CP16(ab + row * 80 + ch * 16, bp + (size_t)row * K + ch * 8);
            }
        }
        asm volatile("cp.async.commit_group;\n" ::);
    };

    int nk = K >> 5;
    load_stage(0, 0);
    for (int kc = 0; kc < nk; ++kc) {
        if (kc + 1 < nk) {
            load_stage((kc + 1) & 1, (kc + 1) << 5);
            asm volatile("cp.async.wait_group 1;\n" ::);
        } else {
            asm volatile("cp.async.wait_group 0;\n" ::);
        }
        __syncthreads();

        uint32_t stg = smem_base + (kc & 1) * STG;
        uint32_t aB  = stg + aOff;
        uint32_t whB = stg + 10240 + bOff;
#pragma unroll
        for (int ks = 0; ks < 2; ++ks) {
            uint32_t bh[4][2];
            LDSM4(bh[0][0], bh[0][1], bh[1][0], bh[1][1], whB + ks * 32);
            LDSM4(bh[2][0], bh[2][1], bh[3][0], bh[3][1], whB + 1280 + ks * 32);
#pragma unroll
            for (int mt = 0; mt < 4; ++mt) {
                uint32_t a0, a1, a2, a3;
                LDSM4(a0, a1, a2, a3, aB + mt * 1280 + ks * 32);
#pragma unroll
                for (int nt = 0; nt < 4; ++nt)
                    MMAH(acc[mt][nt], a0, a1, a2, a3, bh[nt][0], bh[nt][1]);
            }
        }
        __syncthreads();
    }

#pragma unroll
    for (int mt = 0; mt < 4; ++mt) {
#pragma unroll
        for (int half = 0; half < 2; ++half) {
            int row = m0 + wm + mt * 16 + g + half * 8;
#pragma unroll
            for (int nt = 0; nt < 4; ++nt) {
                int col = f0 + wn + nt * 8 + tg * 2;
                float v0 = acc[mt][nt][half * 2 + 0];
                float v1 = acc[mt][nt][half * 2 + 1];
                if (bias) { v0 += bias[col]; v1 += bias[col + 1]; }
                if (GELU) { v0 = v0 * normcdff(v0); v1 = v1 * normcdff(v1); }
                if (RES)  { v0 += res[(size_t)row * F + col]; v1 += res[(size_t)row * F + col + 1]; }
                if (OUTF16) {
                    *(uint32_t*)(Ch + (size_t)row * F + col) = packh(v0, v1);
                } else {
                    float2 o; o.x = v0; o.y = v1;
                    *(float2*)(C + (size_t)row * F + col) = o;
                }
            }
        }
    }
}

// ---------------- qkv prepass ----------------
__launch_bounds__(256)
__global__ void qkv_prep(const float* __restrict__ qkv,
                         __half* __restrict__ qh, __half* __restrict__ kh,
                         __half* __restrict__ vth) {
    __shared__ float vsm[64][33];
    int nb = blockIdx.x * 64;
    int g = nb >> 10;
    int jb = nb & 1023;
    int tid = threadIdx.x;
    const float scale = 0.17677669529663687f;

#pragma unroll
    for (int it = 0; it < 32; ++it) {
        int flat = tid + it * 256;
        int row = flat >> 7, c4 = flat & 127;
        int node = nb + row;
        float4 v = *(const float4*)&qkv[(size_t)node * QKVD + c4 * 4];
        int c = c4 * 4;
        if (c < 256) {
            *(uint2*)(qh + (size_t)node * HH + c) =
                make_uint2(packh(v.x * scale, v.y * scale), packh(v.z * scale, v.w * scale));
        } else {
            *(uint2*)(kh + (size_t)node * HH + c - 256) =
                make_uint2(packh(v.x, v.y), packh(v.z, v.w));
        }
    }

    for (int h = 0; h < NHEADS; ++h) {
        __syncthreads();
#pragma unroll
        for (int it = 0; it < 2; ++it) {
            int flat = tid + it * 256;
            int row = flat >> 3, c4 = flat & 7;
            float4 v = *(const float4*)&qkv[(size_t)(nb + row) * QKVD + 512 + h * 32 + c4 * 4];
            vsm[row][c4 * 4 + 0] = v.x;
            vsm[row][c4 * 4 + 1] = v.y;
            vsm[row][c4 * 4 + 2] = v.z;
            vsm[row][c4 * 4 + 3] = v.w;
        }
        __syncthreads();
        int d = tid >> 3, j0 = (tid & 7) * 8;
        uint32_t hw[4];
#pragma unroll
        for (int p = 0; p < 4; ++p)
            hw[p] = packh(vsm[j0 + p * 2 + 0][d], vsm[j0 + p * 2 + 1][d]);
        size_t off = ((size_t)(g * NHEADS + h) * HDIM + d) * MM + jb + j0;
        *(uint4*)(vth + off) = make_uint4(hw[0], hw[1], hw[2], hw[3]);
    }
}

// ---------------- flash attention (fp16 single K/V) ----------------
__launch_bounds__(256)
__global__ void attn_mma(const __half* __restrict__ qh, const __half* __restrict__ kh,
                         const __half* __restrict__ vth,
                         const unsigned char* __restrict__ dist, const float* __restrict__ bias_emb,
                         __half* __restrict__ oh) {
    extern __shared__ unsigned char smp[];
    const int STG = 18944;   // K 10240 + VT 8704
    __shared__ float btab[8];
    int gh = blockIdx.x;
    int g = gh >> 3, h = gh & 7;
    int i0 = blockIdx.y * 128;
    int tid = threadIdx.x, lane = tid & 31, warp = tid >> 5;
    int r = lane >> 2, tg = lane & 3;
    if (tid < 7) btab[tid] = bias_emb[tid];
    uint32_t sb = (uint32_t)__cvta_generic_to_shared(smp);
    const float L2E = 1.44269504f;

    int rowA = i0 + warp * 16 + r;
    int rowB = rowA + 8;
    uint32_t qf[2][4];
#pragma unroll
    for (int kc = 0; kc < 2; ++kc) {
        size_t baseA = (size_t)(g * MM + rowA) * HH + h * HDIM + kc * 16 + tg * 2;
        size_t baseB = (size_t)(g * MM + rowB) * HH + h * HDIM + kc * 16 + tg * 2;
        qf[kc][0] = *(const uint32_t*)(qh + baseA);
        qf[kc][1] = *(const uint32_t*)(qh + baseB);
        qf[kc][2] = *(const uint32_t*)(qh + baseA + 8);
        qf[kc][3] = *(const uint32_t*)(qh + baseB + 8);
    }

    float acc_o[4][4];
#pragma unroll
    for (int a = 0; a < 4; ++a)
#pragma unroll
        for (int b = 0; b < 4; ++b) acc_o[a][b] = 0.f;
    float mA = -1e30f, mB = -1e30f, lA = 0.f, lB = 0.f;

    const unsigned char* drowA = dist + ((size_t)(g * MM + rowA)) * MM;
    const unsigned char* drowB = dist + ((size_t)(g * MM + rowB)) * MM;

    auto load_stage = [&](int s, int j0) {
        uint32_t db = sb + s * STG;
#pragma unroll
        for (int c = 0; c < 2; ++c) {
            int t = tid + c * 256;
            int row = t >> 2, ch = t & 3;
            const __half* src = kh + (size_t)(g * MM + j0 + row) * HH + h * HDIM + ch * 8;
            CP16(db + row * 80 + ch * 16, src);
        }
#pragma unroll
        for (int c = 0; c < 2; ++c) {
            int t = tid + c * 256;
            int row = t >> 4, ch = t & 15;
            size_t off = ((size_t)(gh) * HDIM + row) * MM + j0 + ch * 8;
            CP16(db + 10240 + row * 272 + ch * 16, vth + off);
        }
        asm volatile("cp.async.commit_group;\n" ::);
    };

    load_stage(0, 0);
    for (int ch = 0; ch < 8; ++ch) {
        int j0 = ch * 128;
        if (ch < 7) {
            load_stage((ch + 1) & 1, j0 + 128);
            asm volatile("cp.async.wait_group 1;\n" ::);
        } else {
            asm volatile("cp.async.wait_group 0;\n" ::);
        }
        __syncthreads();

        const uint32_t* KH = (const uint32_t*)(smp + (ch & 1) * STG);
        const uint32_t* VH = KH + 2560;

        float acc_s[16][4];
#pragma unroll
        for (int nt = 0; nt < 16; ++nt)
#pragma unroll
            for (int c = 0; c < 4; ++c) acc_s[nt][c] = 0.f;
#pragma unroll
        for (int kc = 0; kc < 2; ++kc) {
#pragma unroll
            for (int nt = 0; nt < 16; ++nt) {
                int idx = (nt * 8 + r) * 20 + kc * 8 + tg;
                MMAH(acc_s[nt], qf[kc][0], qf[kc][1], qf[kc][2], qf[kc][3],
                     KH[idx], KH[idx + 4]);
            }
        }

        float cmA = -1e30f, cmB = -1e30f;
#pragma unroll
        for (int nt = 0; nt < 16; ++nt) {
            uchar2 dA = *(const uchar2*)(drowA + j0 + nt * 8 + tg * 2);
            uchar2 dB = *(const uchar2*)(drowB + j0 + nt * 8 + tg * 2);
            acc_s[nt][0] += btab[dA.x];
            acc_s[nt][1] += btab[dA.y];
            acc_s[nt][2] += btab[dB.x];
            acc_s[nt][3] += btab[dB.y];
            cmA = fmaxf(cmA, fmaxf(acc_s[nt][0], acc_s[nt][1]));
            cmB = fmaxf(cmB, fmaxf(acc_s[nt][2], acc_s[nt][3]));
        }
        cmA = fmaxf(cmA, __shfl_xor_sync(0xFFFFFFFFu, cmA, 1));
        cmA = fmaxf(cmA, __shfl_xor_sync(0xFFFFFFFFu, cmA, 2));
        cmB = fmaxf(cmB, __shfl_xor_sync(0xFFFFFFFFu, cmB, 1));
        cmB = fmaxf(cmB, __shfl_xor_sync(0xFFFFFFFFu, cmB, 2));

        float mAn = fmaxf(mA, cmA), mBn = fmaxf(mB, cmB);
        float corrA = ex2f((mA - mAn) * L2E);
        float corrB = ex2f((mB - mBn) * L2E);
        mA = mAn; mB = mBn;

        uint32_t ph0[16], ph1[16];
        float lsA = 0.f, lsB = 0.f;
#pragma unroll
        for (int nt = 0; nt < 16; ++nt) {
            float p0 = ex2f((acc_s[nt][0] - mA) * L2E);
            float p1 = ex2f((acc_s[nt][1] - mA) * L2E);
            float p2 = ex2f((acc_s[nt][2] - mB) * L2E);
            float p3 = ex2f((acc_s[nt][3] - mB) * L2E);
            lsA += p0 + p1; lsB += p2 + p3;
            ph0[nt] = packh(p0, p1);
            ph1[nt] = packh(p2, p3);
        }
        lsA += __shfl_xor_sync(0xFFFFFFFFu, lsA, 1);
        lsA += __shfl_xor_sync(0xFFFFFFFFu, lsA, 2);
        lsB += __shfl_xor_sync(0xFFFFFFFFu, lsB, 1);
        lsB += __shfl_xor_sync(0xFFFFFFFFu, lsB, 2);
        lA = lA * corrA + lsA;
        lB = lB * corrB + lsB;

#pragma unroll
        for (int nto = 0; nto < 4; ++nto) {
            acc_o[nto][0] *= corrA; acc_o[nto][1] *= corrA;
            acc_o[nto][2] *= corrB; acc_o[nto][3] *= corrB;
        }

#pragma unroll
        for (int kc = 0; kc < 8; ++kc) {
            uint32_t a0 = ph0[2 * kc], a1 = ph1[2 * kc], a2 = ph0[2 * kc + 1], a3 = ph1[2 * kc + 1];
#pragma unroll
            for (int nto = 0; nto < 4; ++nto) {
                int idx = (nto * 8 + r) * 68 + kc * 8 + tg;
                MMAH(acc_o[nto], a0, a1, a2, a3, VH[idx], VH[idx + 4]);
            }
        }
        __syncthreads();
    }

    float invA = 1.f / lA, invB = 1.f / lB;
#pragma unroll
    for (int nto = 0; nto < 4; ++nto) {
        int col = h * HDIM + nto * 8 + tg * 2;
        *(uint32_t*)(oh + (size_t)(g * MM + rowA) * HH + col) =
            packh(acc_o[nto][0] * invA, acc_o[nto][1] * invA);
        *(uint32_t*)(oh + (size_t)(g * MM + rowB) * HH + col) =
            packh(acc_o[nto][2] * invB, acc_o[nto][3] * invB);
    }
}

// ---------------- LayerNorm ----------------
__launch_bounds__(256)
__global__ void ln_kernel(const float* __restrict__ a, const float* __restrict__ b,
                          const float* __restrict__ c, const float* __restrict__ gam,
                          const float* __restrict__ bet, float* __restrict__ out,
                          __half* __restrict__ oh) {
    int row = blockIdx.x, t = threadIdx.x;
    size_t idx = (size_t)row * HH + t;
    float v = a[idx];
    if (b) v += b[idx];
    if (c) v += c[idx];
    float s = v, s2 = v * v;
#pragma unroll
    for (int o = 16; o; o >>= 1) {
        s  += __shfl_xor_sync(0xFFFFFFFFu, s, o);
        s2 += __shfl_xor_sync(0xFFFFFFFFu, s2, o);
    }
    __shared__ float sh1[8], sh2[8];
    int w = t >> 5, ln = t & 31;
    if (ln == 0) { sh1[w] = s; sh2[w] = s2; }
    __syncthreads();
    if (w == 0) {
        s  = (ln < 8) ? sh1[ln] : 0.f;
        s2 = (ln < 8) ? sh2[ln] : 0.f;
#pragma unroll
        for (int o = 4; o; o >>= 1) {
            s  += __shfl_xor_sync(0xFFFFFFFFu, s, o);
            s2 += __shfl_xor_sync(0xFFFFFFFFu, s2, o);
        }
        if (ln == 0) { sh1[0] = s; sh2[0] = s2; }
    }
    __syncthreads();
    float mean = sh1[0] * (1.f / HH);
    float var  = sh2[0] * (1.f / HH) - mean * mean;
    float rr = (v - mean) * rsqrtf(var + 1e-5f) * gam[t] + bet[t];
    out[idx] = rr;
    if (oh) oh[idx] = __float2half(rr);
}

// ---------------- host ----------------
static void* sym(const void* s) { void* p = nullptr; cudaGetSymbolAddress(&p, s); return p; }

extern "C" void kernel_launch(void* const* d_in, const int* in_sizes, int n_in,
                              void* d_out, int out_size) {
    const float* x      = (const float*)d_in[0];
    const float* gcn_w  = (const float*)d_in[1];
    const float* gcn_b  = (const float*)d_in[2];
    const float* qkv_w  = (const float*)d_in[3];
    const float* qkv_b  = (const float*)d_in[4];
    const float* proj_w = (const float*)d_in[5];
    const float* proj_b = (const float*)d_in[6];
    const float* ln1_g  = (const float*)d_in[7];
    const float* ln1_b  = (const float*)d_in[8];
    const float* ln2_g  = (const float*)d_in[9];
    const float* ln2_b  = (const float*)d_in[10];
    const float* ffn1_w = (const float*)d_in[11];
    const float* ffn1_b = (const float*)d_in[12];
    const float* ffn2_w = (const float*)d_in[13];
    const float* ffn2_b = (const float*)d_in[14];
    const float* bias_e = (const float*)d_in[15];
    const float* oln1_g = (const float*)d_in[16];
    const float* oln1_b = (const float*)d_in[17];
    const float* oln2_g = (const float*)d_in[18];
    const float* oln2_b = (const float*)d_in[19];
    const float* offn1_w= (const float*)d_in[20];
    const float* offn1_b= (const float*)d_in[21];
    const float* offn2_w= (const float*)d_in[22];
    const float* offn2_b= (const float*)d_in[23];
    const int*   ei     = (const int*)d_in[24];
    int E = in_sizes[24] / 2;

    float*    p_dinv = (float*)sym(g_dinv);
    float*    p_xw   = (float*)sym(g_xw);
    float*    p_xl   = (float*)sym(g_xl);
    uint32_t* p_adj  = (uint32_t*)sym(g_adj);
    uint32_t* p_R2   = (uint32_t*)sym(g_R2);
    uint32_t* p_R3   = (uint32_t*)sym(g_R3);
    uint32_t* p_R4   = (uint32_t*)sym(g_R4);
    uint32_t* p_R5   = (uint32_t*)sym(g_R5);
    unsigned char* p_dist = (unsigned char*)sym(g_dist);
    float*    p_qkv  = (float*)sym(g_qkv);
    float*    p_tmp  = (float*)sym(g_tmp);
    float*    p_h1   = (float*)sym(g_h1);
    float*    p_h2   = (float*)sym(g_h2);
    float*    p_y    = (float*)sym(g_y);
    int*      p_cnt  = (int*)sym(g_cnt);
    int*      p_base = (int*)sym(g_base);
    int*      p_fill = (int*)sym(g_fillp);
    int*      p_esrc = (int*)sym(g_esrc);
    __half* x_h   = (__half*)sym(g_x_h);
    __half* at_h  = (__half*)sym(g_at_h);
    __half* h1_h  = (__half*)sym(g_h1_h);
    __half* y_h   = (__half*)sym(g_y_h);
    __half* mid_h = (__half*)sym(g_mid_h);
    __half* q_h   = (__half*)sym(g_q_h);
    __half* k_h   = (__half*)sym(g_k_h);
    __half* vt_h  = (__half*)sym(g_vt_h);
    __half* whi   = (__half*)sym(g_whi);
    float* out = (float*)d_out;

    const int SMEM  = 40960;
    const int ASMEM = 37888;
    cudaFuncSetAttribute(gemm_f16<0,0,0>, cudaFuncAttributeMaxDynamicSharedMemorySize, SMEM);
    cudaFuncSetAttribute(gemm_f16<0,1,0>, cudaFuncAttributeMaxDynamicSharedMemorySize, SMEM);
    cudaFuncSetAttribute(gemm_f16<1,0,1>, cudaFuncAttributeMaxDynamicSharedMemorySize, SMEM);
    cudaFuncSetAttribute(attn_mma, cudaFuncAttributeMaxDynamicSharedMemorySize, ASMEM);

    // --- graph prep + SPD via boolean matrix powers ---
    zero_prep<<<(GG * MM * 32 + 255) / 256, 256>>>(p_cnt, p_adj);
    splitw<<<(344064 + 255) / 256, 256>>>((const float4*)gcn_w, (const float4*)qkv_w,
        (const float4*)proj_w, (const float4*)ffn1_w, (const float4*)ffn2_w,
        (const float4*)offn1_w, (const float4*)offn2_w, whi);
    edge_prep<<<(E + 255) / 256, 256>>>(ei, E, p_cnt, p_adj);
    spd_round<<<NN * 32 / 256, 256>>>(p_adj, p_adj, p_R2);
    spd_round<<<NN * 32 / 256, 256>>>(p_adj, p_R2, p_R3);
    spd_round<<<NN * 32 / 256, 256>>>(p_adj, p_R3, p_R4);
    spd_round<<<NN * 32 / 256, 256>>>(p_adj, p_R4, p_R5);
    spd_final<<<NN * 32 / 256, 256>>>(p_adj, p_R2, p_R3, p_R4, p_R5, p_dist);

    // --- remaining prep ---
    splitx<<<(NN * HH / 4 + 255) / 256, 256>>>((const float4*)x, x_h, NN * HH / 4);
    scan_kernel<<<1, 1024>>>(p_cnt, p_base, p_fill, p_dinv);
    fill_edges<<<(E + 255) / 256, 256>>>(ei, E, p_fill, p_esrc);

    // --- GCN branch ---
    gemm_f16<0,0,0><<<dim3(NN/128, HH/128), 256, SMEM>>>(x_h, whi + OFF_GCN,
        nullptr, nullptr, p_xw, nullptr, HH, HH);
    gcn_gather<<<NN / 4, 256>>>(p_xw, p_dinv, p_base, p_cnt, p_esrc, gcn_b, p_xl);

    // --- Graphormer layer ---
    gemm_f16<0,0,0><<<dim3(NN/128, QKVD/128), 256, SMEM>>>(x_h, whi + OFF_QKV,
        qkv_b, nullptr, p_qkv, nullptr, HH, QKVD);
    qkv_prep<<<NN / 64, 256>>>(p_qkv, q_h, k_h, vt_h);
    attn_mma<<<dim3(GG * NHEADS, MM / 128), 256, ASMEM>>>(q_h, k_h, vt_h, p_dist, bias_e, at_h);
    gemm_f16<0,1,0><<<dim3(NN/128, HH/128), 256, SMEM>>>(at_h, whi + OFF_PROJ,
        proj_b, x, p_tmp, nullptr, HH, HH);
    ln_kernel<<<NN, 256>>>(p_tmp, nullptr, nullptr, ln1_g, ln1_b, p_h1, h1_h);
    gemm_f16<1,0,1><<<dim3(NN/128, FFND/128), 256, SMEM>>>(h1_h, whi + OFF_FFN1,
        ffn1_b, nullptr, nullptr, mid_h, HH, FFND);
    gemm_f16<0,1,0><<<dim3(NN/128, HH/128), 256, SMEM>>>(mid_h, whi + OFF_FFN2,
        ffn2_b, p_h1, p_tmp, nullptr, FFND, HH);
    ln_kernel<<<NN, 256>>>(p_tmp, nullptr, nullptr, ln2_g, ln2_b, p_h2, nullptr);

    // --- GPS combine + outer FFN ---
    ln_kernel<<<NN, 256>>>(x, p_xl, p_h2, oln1_g, oln1_b, p_y, y_h);
    gemm_f16<1,0,1><<<dim3(NN/128, FFND/128), 256, SMEM>>>(y_h, whi + OFF_OFFN1,
        offn1_b, nullptr, nullptr, mid_h, HH, FFND);
    gemm_f16<0,1,0><<<dim3(NN/128, HH/128), 256, SMEM>>>(mid_h, whi + OFF_OFFN2,
        offn2_b, p_y, p_tmp, nullptr, FFND, HH);
    ln_kernel<<<NN, 256>>>(p_tmp, nullptr, nullptr, oln2_g, oln2_b, out, nullptr);
}

// round 13
// speedup vs baseline: 2.5741x; 1.1736x over previous
#include <cuda_runtime.h>
#include <cuda_fp16.h>
#include <cstdint>
#include <math.h>

#define GG 8
#define MM 1024
#define NN 8192
#define HH 256
#define NHEADS 8
#define HDIM 32
#define FFND 1024
#define QKVD 768

// ---------------- scratch ----------------
__device__ float    g_dinv[NN];
__device__ float    g_xw  [NN * HH];
__device__ float    g_xl  [NN * HH];
__device__ uint32_t g_adj [GG * MM * 32];
__device__ uint32_t g_R2  [GG * MM * 32];
__device__ uint32_t g_R3  [GG * MM * 32];
__device__ uint32_t g_R4  [GG * MM * 32];
__device__ uint32_t g_R5  [GG * MM * 32];
__device__ unsigned char g_dist[(size_t)GG * MM * MM];
__device__ float    g_qkv [(size_t)NN * QKVD];
__device__ float    g_tmp [NN * HH];
__device__ float    g_h1  [NN * HH];
__device__ float    g_h2  [NN * HH];
__device__ float    g_y   [NN * HH];
__device__ int      g_cnt [NN];
__device__ int      g_base[NN];
__device__ int      g_fillp[NN];
__device__ int      g_esrc[262144];

#define AL16 __align__(16)
__device__ AL16 __half g_x_h [NN * HH];
__device__ AL16 __half g_at_h[NN * HH];
__device__ AL16 __half g_h1_h[NN * HH];
__device__ AL16 __half g_y_h [NN * HH];
__device__ AL16 __half g_mid_h[(size_t)NN * FFND];
__device__ AL16 __half g_q_h [NN * HH];
__device__ AL16 __half g_k_h [NN * HH];
__device__ AL16 __half g_vt_h[GG * NHEADS * HDIM * MM];
__device__ AL16 __half g_whi[1376256];
#define OFF_GCN   0
#define OFF_QKV   65536
#define OFF_PROJ  262144
#define OFF_FFN1  327680
#define OFF_FFN2  589824
#define OFF_OFFN1 851968
#define OFF_OFFN2 1114112

// ---------------- helpers ----------------
__device__ __forceinline__ uint32_t packh(float a, float b) {
    uint32_t r;
    asm("cvt.rn.f16x2.f32 %0, %1, %2;" : "=r"(r) : "f"(b), "f"(a));
    return r;
}
__device__ __forceinline__ float ex2f(float x) {
    float y; asm("ex2.approx.f32 %0, %1;" : "=f"(y) : "f"(x)); return y;
}
#define CP16(dst, src) asm volatile("cp.async.cg.shared.global [%0], [%1], 16;\n" :: "r"(dst), "l"(src))
#define MMAH(d, a0, a1, a2, a3, b0, b1) \
    asm volatile("mma.sync.aligned.m16n8k16.row.col.f32.f16.f16.f32 " \
                 "{%0,%1,%2,%3}, {%4,%5,%6,%7}, {%8,%9}, {%0,%1,%2,%3};" \
                 : "+f"(d[0]), "+f"(d[1]), "+f"(d[2]), "+f"(d[3]) \
                 : "r"(a0), "r"(a1), "r"(a2), "r"(a3), "r"(b0), "r"(b1))
#define LDSM4(r0, r1, r2, r3, addr) \
    asm volatile("ldmatrix.sync.aligned.m8n8.x4.shared.b16 {%0,%1,%2,%3}, [%4];" \
                 : "=r"(r0), "=r"(r1), "=r"(r2), "=r"(r3) : "r"(addr))

// ---------------- splits (plain fp16 cast) ----------------
__global__ void splitx(const float4* __restrict__ in, __half* __restrict__ hi, int n4) {
    int i = blockIdx.x * blockDim.x + threadIdx.x;
    if (i >= n4) return;
    float4 v = in[i];
    *(uint2*)(hi + i * 4) = make_uint2(packh(v.x, v.y), packh(v.z, v.w));
}
__global__ void splitw(const float4* w0, const float4* w1, const float4* w2, const float4* w3,
                       const float4* w4, const float4* w5, const float4* w6,
                       __half* __restrict__ hi) {
    int i = blockIdx.x * blockDim.x + threadIdx.x;
    if (i >= 344064) return;
    const float4* src; int base;
    if      (i < 16384)  { src = w0; base = 0; }
    else if (i < 65536)  { src = w1; base = 16384; }
    else if (i < 81920)  { src = w2; base = 65536; }
    else if (i < 147456) { src = w3; base = 81920; }
    else if (i < 212992) { src = w4; base = 147456; }
    else if (i < 278528) { src = w5; base = 212992; }
    else                 { src = w6; base = 278528; }
    float4 v = src[i - base];
    *(uint2*)(hi + (size_t)i * 4) = make_uint2(packh(v.x, v.y), packh(v.z, v.w));
}

// ---------------- graph prep ----------------
__global__ void zero_prep(int* __restrict__ cnt, uint32_t* __restrict__ adj) {
    int i = blockIdx.x * blockDim.x + threadIdx.x;
    if (i < GG * MM * 32) adj[i] = 0u;
    if (i < NN) cnt[i] = 0;
}
__global__ void edge_prep(const int* __restrict__ ei, int E, int* __restrict__ cnt,
                          uint32_t* __restrict__ adj) {
    int e = blockIdx.x * blockDim.x + threadIdx.x;
    if (e >= E) return;
    int s = ei[e], d = ei[E + e];
    atomicAdd(&cnt[d], 1);
    if (s == d || (s >> 10) != (d >> 10)) return;
    int g = s >> 10, ls = s & 1023, ld = d & 1023;
    atomicOr(&adj[((size_t)g * MM + ls) * 32 + (ld >> 5)], 1u << (ld & 31));
    atomicOr(&adj[((size_t)g * MM + ld) * 32 + (ls >> 5)], 1u << (ls & 31));
}
__global__ void scan_kernel(const int* __restrict__ cnt, int* __restrict__ base,
                            int* __restrict__ fillp, float* __restrict__ dinv) {
    __shared__ int wsum[32];
    int t = threadIdx.x;
    int v[8]; int s = 0;
#pragma unroll
    for (int k = 0; k < 8; ++k) { v[k] = s; s += cnt[t * 8 + k]; }
    int lane = t & 31, w = t >> 5;
    int tot = s, sc = s;
#pragma unroll
    for (int o = 1; o < 32; o <<= 1) {
        int n = __shfl_up_sync(0xFFFFFFFFu, sc, o);
        if (lane >= o) sc += n;
    }
    if (lane == 31) wsum[w] = sc;
    __syncthreads();
    if (w == 0) {
        int x = wsum[lane];
#pragma unroll
        for (int o = 1; o < 32; o <<= 1) {
            int n = __shfl_up_sync(0xFFFFFFFFu, x, o);
            if (lane >= o) x += n;
        }
        wsum[lane] = x;
    }
    __syncthreads();
    int excl = sc - tot + (w > 0 ? wsum[w - 1] : 0);
#pragma unroll
    for (int k = 0; k < 8; ++k) {
        int idx = t * 8 + k;
        int b = excl + v[k];
        base[idx] = b;
        fillp[idx] = b;
        dinv[idx] = rsqrtf((float)cnt[idx] + 1.0f);
    }
}
__global__ void fill_edges(const int* __restrict__ ei, int E, int* __restrict__ fillp,
                           int* __restrict__ esrc) {
    int e = blockIdx.x * blockDim.x + threadIdx.x;
    if (e >= E) return;
    int s = ei[e], d = ei[E + e];
    int pos = atomicAdd(&fillp[d], 1);
    esrc[pos] = s;
}
__launch_bounds__(256)
__global__ void gcn_gather(const float* __restrict__ xw, const float* __restrict__ dinv,
                           const int* __restrict__ base, const int* __restrict__ cnt,
                           const int* __restrict__ esrc, const float* __restrict__ gcn_b,
                           float* __restrict__ xl) {
    int node = blockIdx.x * 4 + (threadIdx.x >> 6);
    int c4 = (threadIdx.x & 63) * 4;
    float dd = dinv[node];
    float4 v0 = *(const float4*)&xw[(size_t)node * HH + c4];
    float ax = dd * v0.x, ay = dd * v0.y, az = dd * v0.z, aw = dd * v0.w;
    int b0 = __ldg(&base[node]);
    int n  = __ldg(&cnt[node]);
    int k = 0;
    for (; k + 4 <= n; k += 4) {
        int s0 = __ldg(&esrc[b0 + k]);
        int s1 = __ldg(&esrc[b0 + k + 1]);
        int s2 = __ldg(&esrc[b0 + k + 2]);
        int s3 = __ldg(&esrc[b0 + k + 3]);
        float w0 = __ldg(&dinv[s0]), w1 = __ldg(&dinv[s1]);
        float w2 = __ldg(&dinv[s2]), w3 = __ldg(&dinv[s3]);
        float4 a = *(const float4*)&xw[(size_t)s0 * HH + c4];
        float4 b = *(const float4*)&xw[(size_t)s1 * HH + c4];
        float4 c = *(const float4*)&xw[(size_t)s2 * HH + c4];
        float4 d = *(const float4*)&xw[(size_t)s3 * HH + c4];
        ax += w0 * a.x + w1 * b.x + w2 * c.x + w3 * d.x;
        ay += w0 * a.y + w1 * b.y + w2 * c.y + w3 * d.y;
        az += w0 * a.z + w1 * b.z + w2 * c.z + w3 * d.z;
        aw += w0 * a.w + w1 * b.w + w2 * c.w + w3 * d.w;
    }
    for (; k < n; ++k) {
        int s = __ldg(&esrc[b0 + k]);
        float ws = __ldg(&dinv[s]);
        float4 v = *(const float4*)&xw[(size_t)s * HH + c4];
        ax += ws * v.x; ay += ws * v.y; az += ws * v.z; aw += ws * v.w;
    }
    float4 bia = *(const float4*)&gcn_b[c4];
    float4 o;
    o.x = dd * ax + bia.x; o.y = dd * ay + bia.y;
    o.z = dd * az + bia.z; o.w = dd * aw + bia.w;
    *(float4*)&xl[(size_t)node * HH + c4] = o;
}

// ---------------- SPD: boolean matrix powers, warp-per-row ----------------
__launch_bounds__(256)
__global__ void spd_round(const uint32_t* __restrict__ adj, const uint32_t* __restrict__ Rp,
                          uint32_t* __restrict__ Rn) {
    int gw = (blockIdx.x * 256 + threadIdx.x) >> 5;
    int lane = threadIdx.x & 31;
    int g = gw >> 10, i = gw & 1023;
    const uint32_t* Rg = Rp + (size_t)g * MM * 32;
    uint32_t a = adj[((size_t)g * MM + i) * 32 + lane];
    uint32_t nw = Rg[i * 32 + lane];
    for (int w = 0; w < 32; ++w) {
        uint32_t f = __shfl_sync(0xFFFFFFFFu, a, w);
        while (f) {
            int b = __ffs((int)f) - 1;
            f &= f - 1;
            nw |= Rg[(w * 32 + b) * 32 + lane];
        }
    }
    Rn[((size_t)g * MM + i) * 32 + lane] = nw;
}
__device__ __forceinline__ uint32_t nibspread(uint32_t r, int q) {
    return (((r >> (q * 4)) & 0xFu) * 0x00204081u) & 0x01010101u;
}
__launch_bounds__(256)
__global__ void spd_final(const uint32_t* __restrict__ R1, const uint32_t* __restrict__ R2,
                          const uint32_t* __restrict__ R3, const uint32_t* __restrict__ R4,
                          const uint32_t* __restrict__ R5, unsigned char* __restrict__ dist) {
    int idx = blockIdx.x * 256 + threadIdx.x;
    int row = idx >> 5, w = idx & 31;
    uint32_t r1 = R1[idx], r2 = R2[idx], r3 = R3[idx], r4 = R4[idx], r5 = R5[idx];
    unsigned char* drow = dist + (size_t)row * MM;
    uint4* dp = (uint4*)(drow + w * 32);
    uint32_t o[8];
#pragma unroll
    for (int q = 0; q < 8; ++q) {
        uint32_t s = nibspread(r1, q) + nibspread(r2, q) + nibspread(r3, q)
                   + nibspread(r4, q) + nibspread(r5, q);
        o[q] = 0x06060606u - s;
    }
    dp[0] = make_uint4(o[0], o[1], o[2], o[3]);
    dp[1] = make_uint4(o[4], o[5], o[6], o[7]);
    int i = row & 1023;
    if ((i >> 5) == w) drow[i] = 0;
}

// ---------------- fp16 GEMM 128x128 (ldmatrix, single-fp16 W) ----------------
template <int GELU, int RES, int OUTF16>
__launch_bounds__(256, 2)
__global__ void gemm_f16(const __half* __restrict__ Ag, const __half* __restrict__ Whg,
                         const float* __restrict__ bias, const float* __restrict__ res,
                         float* __restrict__ C, __half* __restrict__ Ch, int K, int F) {
    extern __shared__ unsigned char smp[];
    const int STG = 20480;
    int m0 = blockIdx.x * 128, f0 = blockIdx.y * 128;
    int tid = threadIdx.x, lane = tid & 31, warp = tid >> 5;
    int g = lane >> 2, tg = lane & 3;
    int wm = (warp >> 2) * 64, wn = (warp & 3) * 32;
    uint32_t smem_base = (uint32_t)__cvta_generic_to_shared(smp);

    uint32_t aOff = (uint32_t)(wm + (lane & 15)) * 80 + (uint32_t)(lane >> 4) * 16;
    uint32_t bOff = (uint32_t)(wn + ((lane >> 4) << 3) + (lane & 7)) * 80
                  + (uint32_t)((lane >> 3) & 1) * 16;

    float acc[4][4][4];
#pragma unroll
    for (int a = 0; a < 4; ++a)
#pragma unroll
        for (int b = 0; b < 4; ++b)
#pragma unroll
            for (int c = 0; c < 4; ++c) acc[a][b][c] = 0.f;

    auto load_stage = [&](int s, int k0) {
        uint32_t db = smem_base + s * STG;
        const __half* srcs[2] = { Ag + (size_t)m0 * K + k0, Whg + (size_t)f0 * K + k0 };
#pragma unroll
        for (int arr = 0; arr < 2; ++arr) {
            const __half* bp = srcs[arr];
            uint32_t ab = db + arr * 10240;
#pragma unroll
            for (int c = 0; c < 2; ++c) {
                int t = tid + c * 256;
                int row = t >> 2, ch = t & 3;
                CP16(ab + row * 80 + ch * 16, bp + (size_t)row * K + ch * 8);
            }
        }
        asm volatile("cp.async.commit_group;\n" ::);
    };

    int nk = K >> 5;
    load_stage(0, 0);
    for (int kc = 0; kc < nk; ++kc) {
        if (kc + 1 < nk) {
            load_stage((kc + 1) & 1, (kc + 1) << 5);
            asm volatile("cp.async.wait_group 1;\n" ::);
        } else {
            asm volatile("cp.async.wait_group 0;\n" ::);
        }
        __syncthreads();

        uint32_t stg = smem_base + (kc & 1) * STG;
        uint32_t aB  = stg + aOff;
        uint32_t whB = stg + 10240 + bOff;
#pragma unroll
        for (int ks = 0; ks < 2; ++ks) {
            uint32_t bh[4][2];
            LDSM4(bh[0][0], bh[0][1], bh[1][0], bh[1][1], whB + ks * 32);
            LDSM4(bh[2][0], bh[2][1], bh[3][0], bh[3][1], whB + 1280 + ks * 32);
#pragma unroll
            for (int mt = 0; mt < 4; ++mt) {
                uint32_t a0, a1, a2, a3;
                LDSM4(a0, a1, a2, a3, aB + mt * 1280 + ks * 32);
#pragma unroll
                for (int nt = 0; nt < 4; ++nt)
                    MMAH(acc[mt][nt], a0, a1, a2, a3, bh[nt][0], bh[nt][1]);
            }
        }
        __syncthreads();
    }

#pragma unroll
    for (int mt = 0; mt < 4; ++mt) {
#pragma unroll
        for (int half = 0; half < 2; ++half) {
            int row = m0 + wm + mt * 16 + g + half * 8;
#pragma unroll
            for (int nt = 0; nt < 4; ++nt) {
                int col = f0 + wn + nt * 8 + tg * 2;
                float v0 = acc[mt][nt][half * 2 + 0];
                float v1 = acc[mt][nt][half * 2 + 1];
                if (bias) { v0 += bias[col]; v1 += bias[col + 1]; }
                if (GELU) { v0 = v0 * normcdff(v0); v1 = v1 * normcdff(v1); }
                if (RES)  { v0 += res[(size_t)row * F + col]; v1 += res[(size_t)row * F + col + 1]; }
                if (OUTF16) {
                    *(uint32_t*)(Ch + (size_t)row * F + col) = packh(v0, v1);
                } else {
                    float2 o; o.x = v0; o.y = v1;
                    *(float2*)(C + (size_t)row * F + col) = o;
                }
            }
        }
    }
}

// ---------------- qkv prepass ----------------
__launch_bounds__(256)
__global__ void qkv_prep(const float* __restrict__ qkv,
                         __half* __restrict__ qh, __half* __restrict__ kh,
                         __half* __restrict__ vth) {
    __shared__ float vsm[64][33];
    int nb = blockIdx.x * 64;
    int g = nb >> 10;
    int jb = nb & 1023;
    int tid = threadIdx.x;
    const float scale = 0.17677669529663687f;

#pragma unroll
    for (int it = 0; it < 32; ++it) {
        int flat = tid + it * 256;
        int row = flat >> 7, c4 = flat & 127;
        int node = nb + row;
        float4 v = *(const float4*)&qkv[(size_t)node * QKVD + c4 * 4];
        int c = c4 * 4;
        if (c < 256) {
            *(uint2*)(qh + (size_t)node * HH + c) =
                make_uint2(packh(v.x * scale, v.y * scale), packh(v.z * scale, v.w * scale));
        } else {
            *(uint2*)(kh + (size_t)node * HH + c - 256) =
                make_uint2(packh(v.x, v.y), packh(v.z, v.w));
        }
    }

    for (int h = 0; h < NHEADS; ++h) {
        __syncthreads();
#pragma unroll
        for (int it = 0; it < 2; ++it) {
            int flat = tid + it * 256;
            int row = flat >> 3, c4 = flat & 7;
            float4 v = *(const float4*)&qkv[(size_t)(nb + row) * QKVD + 512 + h * 32 + c4 * 4];
            vsm[row][c4 * 4 + 0] = v.x;
            vsm[row][c4 * 4 + 1] = v.y;
            vsm[row][c4 * 4 + 2] = v.z;
            vsm[row][c4 * 4 + 3] = v.w;
        }
        __syncthreads();
        int d = tid >> 3, j0 = (tid & 7) * 8;
        uint32_t hw[4];
#pragma unroll
        for (int p = 0; p < 4; ++p)
            hw[p] = packh(vsm[j0 + p * 2 + 0][d], vsm[j0 + p * 2 + 1][d]);
        size_t off = ((size_t)(g * NHEADS + h) * HDIM + d) * MM + jb + j0;
        *(uint4*)(vth + off) = make_uint4(hw[0], hw[1], hw[2], hw[3]);
    }
}

// ---------------- flash attention (fp16 single K/V) ----------------
__launch_bounds__(256)
__global__ void attn_mma(const __half* __restrict__ qh, const __half* __restrict__ kh,
                         const __half* __restrict__ vth,
                         const unsigned char* __restrict__ dist, const float* __restrict__ bias_emb,
                         __half* __restrict__ oh) {
    extern __shared__ unsigned char smp[];
    const int STG = 18944;
    __shared__ float btab[8];
    int gh = blockIdx.x;
    int g = gh >> 3, h = gh & 7;
    int i0 = blockIdx.y * 128;
    int tid = threadIdx.x, lane = tid & 31, warp = tid >> 5;
    int r = lane >> 2, tg = lane & 3;
    if (tid < 7) btab[tid] = bias_emb[tid];
    uint32_t sb = (uint32_t)__cvta_generic_to_shared(smp);
    const float L2E = 1.44269504f;

    int rowA = i0 + warp * 16 + r;
    int rowB = rowA + 8;
    uint32_t qf[2][4];
#pragma unroll
    for (int kc = 0; kc < 2; ++kc) {
        size_t baseA = (size_t)(g * MM + rowA) * HH + h * HDIM + kc * 16 + tg * 2;
        size_t baseB = (size_t)(g * MM + rowB) * HH + h * HDIM + kc * 16 + tg * 2;
        qf[kc][0] = *(const uint32_t*)(qh + baseA);
        qf[kc][1] = *(const uint32_t*)(qh + baseB);
        qf[kc][2] = *(const uint32_t*)(qh + baseA + 8);
        qf[kc][3] = *(const uint32_t*)(qh + baseB + 8);
    }

    float acc_o[4][4];
#pragma unroll
    for (int a = 0; a < 4; ++a)
#pragma unroll
        for (int b = 0; b < 4; ++b) acc_o[a][b] = 0.f;
    float mA = -1e30f, mB = -1e30f, lA = 0.f, lB = 0.f;

    const unsigned char* drowA = dist + ((size_t)(g * MM + rowA)) * MM;
    const unsigned char* drowB = dist + ((size_t)(g * MM + rowB)) * MM;

    auto load_stage = [&](int s, int j0) {
        uint32_t db = sb + s * STG;
#pragma unroll
        for (int c = 0; c < 2; ++c) {
            int t = tid + c * 256;
            int row = t >> 2, ch = t & 3;
            const __half* src = kh + (size_t)(g * MM + j0 + row) * HH + h * HDIM + ch * 8;
            CP16(db + row * 80 + ch * 16, src);
        }
#pragma unroll
        for (int c = 0; c < 2; ++c) {
            int t = tid + c * 256;
            int row = t >> 4, ch = t & 15;
            size_t off = ((size_t)(gh) * HDIM + row) * MM + j0 + ch * 8;
            CP16(db + 10240 + row * 272 + ch * 16, vth + off);
        }
        asm volatile("cp.async.commit_group;\n" ::);
    };

    load_stage(0, 0);
    for (int ch = 0; ch < 8; ++ch) {
        int j0 = ch * 128;
        if (ch < 7) {
            load_stage((ch + 1) & 1, j0 + 128);
            asm volatile("cp.async.wait_group 1;\n" ::);
        } else {
            asm volatile("cp.async.wait_group 0;\n" ::);
        }
        __syncthreads();

        const uint32_t* KH = (const uint32_t*)(smp + (ch & 1) * STG);
        const uint32_t* VH = KH + 2560;

        float acc_s[16][4];
#pragma unroll
        for (int nt = 0; nt < 16; ++nt)
#pragma unroll
            for (int c = 0; c < 4; ++c) acc_s[nt][c] = 0.f;
#pragma unroll
        for (int kc = 0; kc < 2; ++kc) {
#pragma unroll
            for (int nt = 0; nt < 16; ++nt) {
                int idx = (nt * 8 + r) * 20 + kc * 8 + tg;
                MMAH(acc_s[nt], qf[kc][0], qf[kc][1], qf[kc][2], qf[kc][3],
                     KH[idx], KH[idx + 4]);
            }
        }

        float cmA = -1e30f, cmB = -1e30f;
#pragma unroll
        for (int nt = 0; nt < 16; ++nt) {
            uchar2 dA = *(const uchar2*)(drowA + j0 + nt * 8 + tg * 2);
            uchar2 dB = *(const uchar2*)(drowB + j0 + nt * 8 + tg * 2);
            acc_s[nt][0] += btab[dA.x];
            acc_s[nt][1] += btab[dA.y];
            acc_s[nt][2] += btab[dB.x];
            acc_s[nt][3] += btab[dB.y];
            cmA = fmaxf(cmA, fmaxf(acc_s[nt][0], acc_s[nt][1]));
            cmB = fmaxf(cmB, fmaxf(acc_s[nt][2], acc_s[nt][3]));
        }
        cmA = fmaxf(cmA, __shfl_xor_sync(0xFFFFFFFFu, cmA, 1));
        cmA = fmaxf(cmA, __shfl_xor_sync(0xFFFFFFFFu, cmA, 2));
        cmB = fmaxf(cmB, __shfl_xor_sync(0xFFFFFFFFu, cmB, 1));
        cmB = fmaxf(cmB, __shfl_xor_sync(0xFFFFFFFFu, cmB, 2));

        float mAn = fmaxf(mA, cmA), mBn = fmaxf(mB, cmB);
        float corrA = ex2f((mA - mAn) * L2E);
        float corrB = ex2f((mB - mBn) * L2E);
        mA = mAn; mB = mBn;

        uint32_t ph0[16], ph1[16];
        float lsA = 0.f, lsB = 0.f;
#pragma unroll
        for (int nt = 0; nt < 16; ++nt) {
            float p0 = ex2f((acc_s[nt][0] - mA) * L2E);
            float p1 = ex2f((acc_s[nt][1] - mA) * L2E);
            float p2 = ex2f((acc_s[nt][2] - mB) * L2E);
            float p3 = ex2f((acc_s[nt][3] - mB) * L2E);
            lsA += p0 + p1; lsB += p2 + p3;
            ph0[nt] = packh(p0, p1);
            ph1[nt] = packh(p2, p3);
        }
        lsA += __shfl_xor_sync(0xFFFFFFFFu, lsA, 1);
        lsA += __shfl_xor_sync(0xFFFFFFFFu, lsA, 2);
        lsB += __shfl_xor_sync(0xFFFFFFFFu, lsB, 1);
        lsB += __shfl_xor_sync(0xFFFFFFFFu, lsB, 2);
        lA = lA * corrA + lsA;
        lB = lB * corrB + lsB;

#pragma unroll
        for (int nto = 0; nto < 4; ++nto) {
            acc_o[nto][0] *= corrA; acc_o[nto][1] *= corrA;
            acc_o[nto][2] *= corrB; acc_o[nto][3] *= corrB;
        }

#pragma unroll
        for (int kc = 0; kc < 8; ++kc) {
            uint32_t a0 = ph0[2 * kc], a1 = ph1[2 * kc], a2 = ph0[2 * kc + 1], a3 = ph1[2 * kc + 1];
#pragma unroll
            for (int nto = 0; nto < 4; ++nto) {
                int idx = (nto * 8 + r) * 68 + kc * 8 + tg;
                MMAH(acc_o[nto], a0, a1, a2, a3, VH[idx], VH[idx + 4]);
            }
        }
        __syncthreads();
    }

    float invA = 1.f / lA, invB = 1.f / lB;
#pragma unroll
    for (int nto = 0; nto < 4; ++nto) {
        int col = h * HDIM + nto * 8 + tg * 2;
        *(uint32_t*)(oh + (size_t)(g * MM + rowA) * HH + col) =
            packh(acc_o[nto][0] * invA, acc_o[nto][1] * invA);
        *(uint32_t*)(oh + (size_t)(g * MM + rowB) * HH + col) =
            packh(acc_o[nto][2] * invB, acc_o[nto][3] * invB);
    }
}

// ---------------- LayerNorm: warp-per-row, 8 rows per CTA ----------------
__launch_bounds__(256)
__global__ void ln_kernel(const float* __restrict__ a, const float* __restrict__ b,
                          const float* __restrict__ c, const float* __restrict__ gam,
                          const float* __restrict__ bet, float* __restrict__ out,
                          __half* __restrict__ oh) {
    int row = blockIdx.x * 8 + (threadIdx.x >> 5);
    int lane = threadIdx.x & 31;
    size_t idx = (size_t)row * HH + lane * 8;
    float v[8];
    float4 u0 = *(const float4*)&a[idx];
    float4 u1 = *(const float4*)&a[idx + 4];
    v[0] = u0.x; v[1] = u0.y; v[2] = u0.z; v[3] = u0.w;
    v[4] = u1.x; v[5] = u1.y; v[6] = u1.z; v[7] = u1.w;
    if (b) {
        float4 b0 = *(const float4*)&b[idx];
        float4 b1 = *(const float4*)&b[idx + 4];
        v[0] += b0.x; v[1] += b0.y; v[2] += b0.z; v[3] += b0.w;
        v[4] += b1.x; v[5] += b1.y; v[6] += b1.z; v[7] += b1.w;
    }
    if (c) {
        float4 c0 = *(const float4*)&c[idx];
        float4 c1 = *(const float4*)&c[idx + 4];
        v[0] += c0.x; v[1] += c0.y; v[2] += c0.z; v[3] += c0.w;
        v[4] += c1.x; v[5] += c1.y; v[6] += c1.z; v[7] += c1.w;
    }
    float s = 0.f, s2 = 0.f;
#pragma unroll
    for (int j = 0; j < 8; ++j) { s += v[j]; s2 += v[j] * v[j]; }
#pragma unroll
    for (int o = 16; o; o >>= 1) {
        s  += __shfl_xor_sync(0xFFFFFFFFu, s, o);
        s2 += __shfl_xor_sync(0xFFFFFFFFu, s2, o);
    }
    float mean = s * (1.f / HH);
    float var  = s2 * (1.f / HH) - mean * mean;
    float rstd = rsqrtf(var + 1e-5f);
    int gcol = lane * 8;
    float4 g0 = *(const float4*)&gam[gcol];
    float4 g1 = *(const float4*)&gam[gcol + 4];
    float4 e0 = *(const float4*)&bet[gcol];
    float4 e1 = *(const float4*)&bet[gcol + 4];
    float r[8];
    r[0] = (v[0] - mean) * rstd * g0.x + e0.x;
    r[1] = (v[1] - mean) * rstd * g0.y + e0.y;
    r[2] = (v[2] - mean) * rstd * g0.z + e0.z;
    r[3] = (v[3] - mean) * rstd * g0.w + e0.w;
    r[4] = (v[4] - mean) * rstd * g1.x + e1.x;
    r[5] = (v[5] - mean) * rstd * g1.y + e1.y;
    r[6] = (v[6] - mean) * rstd * g1.z + e1.z;
    r[7] = (v[7] - mean) * rstd * g1.w + e1.w;
    float4 o0, o1;
    o0.x = r[0]; o0.y = r[1]; o0.z = r[2]; o0.w = r[3];
    o1.x = r[4]; o1.y = r[5]; o1.z = r[6]; o1.w = r[7];
    *(float4*)&out[idx] = o0;
    *(float4*)&out[idx + 4] = o1;
    if (oh) {
        *(uint4*)(oh + idx) = make_uint4(packh(r[0], r[1]), packh(r[2], r[3]),
                                         packh(r[4], r[5]), packh(r[6], r[7]));
    }
}

// ---------------- host ----------------
static void* sym(const void* s) { void* p = nullptr; cudaGetSymbolAddress(&p, s); return p; }

// streams + events created once at process init (no device memory APIs used)
static cudaStream_t s_s1, s_s2;
static cudaEvent_t  s_evA, s_evXW, s_evSPD, s_evGA;
static struct StreamInit {
    StreamInit() {
        cudaStreamCreateWithFlags(&s_s1, cudaStreamNonBlocking);
        cudaStreamCreateWithFlags(&s_s2, cudaStreamNonBlocking);
        cudaEventCreateWithFlags(&s_evA,   cudaEventDisableTiming);
        cudaEventCreateWithFlags(&s_evXW,  cudaEventDisableTiming);
        cudaEventCreateWithFlags(&s_evSPD, cudaEventDisableTiming);
        cudaEventCreateWithFlags(&s_evGA,  cudaEventDisableTiming);
    }
} s_streamInit;

extern "C" void kernel_launch(void* const* d_in, const int* in_sizes, int n_in,
                              void* d_out, int out_size) {
    const float* x      = (const float*)d_in[0];
    const float* gcn_w  = (const float*)d_in[1];
    const float* gcn_b  = (const float*)d_in[2];
    const float* qkv_w  = (const float*)d_in[3];
    const float* qkv_b  = (const float*)d_in[4];
    const float* proj_w = (const float*)d_in[5];
    const float* proj_b = (const float*)d_in[6];
    const float* ln1_g  = (const float*)d_in[7];
    const float* ln1_b  = (const float*)d_in[8];
    const float* ln2_g  = (const float*)d_in[9];
    const float* ln2_b  = (const float*)d_in[10];
    const float* ffn1_w = (const float*)d_in[11];
    const float* ffn1_b = (const float*)d_in[12];
    const float* ffn2_w = (const float*)d_in[13];
    const float* ffn2_b = (const float*)d_in[14];
    const float* bias_e = (const float*)d_in[15];
    const float* oln1_g = (const float*)d_in[16];
    const float* oln1_b = (const float*)d_in[17];
    const float* oln2_g = (const float*)d_in[18];
    const float* oln2_b = (const float*)d_in[19];
    const float* offn1_w= (const float*)d_in[20];
    const float* offn1_b= (const float*)d_in[21];
    const float* offn2_w= (const float*)d_in[22];
    const float* offn2_b= (const float*)d_in[23];
    const int*   ei     = (const int*)d_in[24];
    int E = in_sizes[24] / 2;

    float*    p_dinv = (float*)sym(g_dinv);
    float*    p_xw   = (float*)sym(g_xw);
    float*    p_xl   = (float*)sym(g_xl);
    uint32_t* p_adj  = (uint32_t*)sym(g_adj);
    uint32_t* p_R2   = (uint32_t*)sym(g_R2);
    uint32_t* p_R3   = (uint32_t*)sym(g_R3);
    uint32_t* p_R4   = (uint32_t*)sym(g_R4);
    uint32_t* p_R5   = (uint32_t*)sym(g_R5);
    unsigned char* p_dist = (unsigned char*)sym(g_dist);
    float*    p_qkv  = (float*)sym(g_qkv);
    float*    p_tmp  = (float*)sym(g_tmp);
    float*    p_h1   = (float*)sym(g_h1);
    float*    p_h2   = (float*)sym(g_h2);
    float*    p_y    = (float*)sym(g_y);
    int*      p_cnt  = (int*)sym(g_cnt);
    int*      p_base = (int*)sym(g_base);
    int*      p_fill = (int*)sym(g_fillp);
    int*      p_esrc = (int*)sym(g_esrc);
    __half* x_h   = (__half*)sym(g_x_h);
    __half* at_h  = (__half*)sym(g_at_h);
    __half* h1_h  = (__half*)sym(g_h1_h);
    __half* y_h   = (__half*)sym(g_y_h);
    __half* mid_h = (__half*)sym(g_mid_h);
    __half* q_h   = (__half*)sym(g_q_h);
    __half* k_h   = (__half*)sym(g_k_h);
    __half* vt_h  = (__half*)sym(g_vt_h);
    __half* whi   = (__half*)sym(g_whi);
    float* out = (float*)d_out;

    const int SMEM  = 40960;
    const int ASMEM = 37888;
    cudaFuncSetAttribute(gemm_f16<0,0,0>, cudaFuncAttributeMaxDynamicSharedMemorySize, SMEM);
    cudaFuncSetAttribute(gemm_f16<0,1,0>, cudaFuncAttributeMaxDynamicSharedMemorySize, SMEM);
    cudaFuncSetAttribute(gemm_f16<1,0,1>, cudaFuncAttributeMaxDynamicSharedMemorySize, SMEM);
    cudaFuncSetAttribute(attn_mma, cudaFuncAttributeMaxDynamicSharedMemorySize, ASMEM);

    // --- default stream: counts + adjacency, then fork ---
    zero_prep<<<(GG * MM * 32 + 255) / 256, 256>>>(p_cnt, p_adj);
    edge_prep<<<(E + 255) / 256, 256>>>(ei, E, p_cnt, p_adj);
    cudaEventRecord(s_evA, 0);

    // --- s1: SPD chain (independent of GEMMs) ---
    cudaStreamWaitEvent(s_s1, s_evA, 0);
    spd_round<<<NN * 32 / 256, 256, 0, s_s1>>>(p_adj, p_adj, p_R2);
    spd_round<<<NN * 32 / 256, 256, 0, s_s1>>>(p_adj, p_R2, p_R3);
    spd_round<<<NN * 32 / 256, 256, 0, s_s1>>>(p_adj, p_R3, p_R4);
    spd_round<<<NN * 32 / 256, 256, 0, s_s1>>>(p_adj, p_R4, p_R5);
    spd_final<<<NN * 32 / 256, 256, 0, s_s1>>>(p_adj, p_R2, p_R3, p_R4, p_R5, p_dist);
    cudaEventRecord(s_evSPD, s_s1);

    // --- s2: edge CSR + (later) GCN gather ---
    cudaStreamWaitEvent(s_s2, s_evA, 0);
    scan_kernel<<<1, 1024, 0, s_s2>>>(p_cnt, p_base, p_fill, p_dinv);
    fill_edges<<<(E + 255) / 256, 256, 0, s_s2>>>(ei, E, p_fill, p_esrc);

    // --- default stream: splits + GEMM chain ---
    splitw<<<(344064 + 255) / 256, 256>>>((const float4*)gcn_w, (const float4*)qkv_w,
        (const float4*)proj_w, (const float4*)ffn1_w, (const float4*)ffn2_w,
        (const float4*)offn1_w, (const float4*)offn2_w, whi);
    splitx<<<(NN * HH / 4 + 255) / 256, 256>>>((const float4*)x, x_h, NN * HH / 4);
    gemm_f16<0,0,0><<<dim3(NN/128, HH/128), 256, SMEM>>>(x_h, whi + OFF_GCN,
        nullptr, nullptr, p_xw, nullptr, HH, HH);
    cudaEventRecord(s_evXW, 0);
    cudaStreamWaitEvent(s_s2, s_evXW, 0);
    gcn_gather<<<NN / 4, 256, 0, s_s2>>>(p_xw, p_dinv, p_base, p_cnt, p_esrc, gcn_b, p_xl);
    cudaEventRecord(s_evGA, s_s2);

    gemm_f16<0,0,0><<<dim3(NN/128, QKVD/128), 256, SMEM>>>(x_h, whi + OFF_QKV,
        qkv_b, nullptr, p_qkv, nullptr, HH, QKVD);
    qkv_prep<<<NN / 64, 256>>>(p_qkv, q_h, k_h, vt_h);

    cudaStreamWaitEvent(0, s_evSPD, 0);
    attn_mma<<<dim3(GG * NHEADS, MM / 128), 256, ASMEM>>>(q_h, k_h, vt_h, p_dist, bias_e, at_h);
    gemm_f16<0,1,0><<<dim3(NN/128, HH/128), 256, SMEM>>>(at_h, whi + OFF_PROJ,
        proj_b, x, p_tmp, nullptr, HH, HH);
    ln_kernel<<<NN / 8, 256>>>(p_tmp, nullptr, nullptr, ln1_g, ln1_b, p_h1, h1_h);
    gemm_f16<1,0,1><<<dim3(NN/128, FFND/128), 256, SMEM>>>(h1_h, whi + OFF_FFN1,
        ffn1_b, nullptr, nullptr, mid_h, HH, FFND);
    gemm_f16<0,1,0><<<dim3(NN/128, HH/128), 256, SMEM>>>(mid_h, whi + OFF_FFN2,
        ffn2_b, p_h1, p_tmp, nullptr, FFND, HH);
    ln_kernel<<<NN / 8, 256>>>(p_tmp, nullptr, nullptr, ln2_g, ln2_b, p_h2, nullptr);

    // --- GPS combine + outer FFN (needs xl from s2) ---
    cudaStreamWaitEvent(0, s_evGA, 0);
    ln_kernel<<<NN / 8, 256>>>(x, p_xl, p_h2, oln1_g, oln1_b, p_y, y_h);
    gemm_f16<1,0,1><<<dim3(NN/128, FFND/128), 256, SMEM>>>(y_h, whi + OFF_OFFN1,
        offn1_b, nullptr, nullptr, mid_h, HH, FFND);
    gemm_f16<0,1,0><<<dim3(NN/128, HH/128), 256, SMEM>>>(mid_h, whi + OFF_OFFN2,
        offn2_b, p_y, p_tmp, nullptr, FFND, HH);
    ln_kernel<<<NN / 8, 256>>>(p_tmp, nullptr, nullptr, oln2_g, oln2_b, out, nullptr);
}